// round 3
// baseline (speedup 1.0000x reference)
#include <cuda_runtime.h>
#include <cuda_bf16.h>
#include <math.h>

// Problem shapes (fixed)
#define B 2
#define NSEQ 2048
#define DIM 1024
#define HEADS 16
#define HDIM 64
#define MROWS (B * NSEQ)   // 4096
#define ATT_SCALE 0.125f   // 64^-0.5

// ---------------------------------------------------------------------------
// Scratch (device globals: allocation-free). Selected device-side via a
// compile-time pointer table so kernel_launch needs NO host API calls.
// ---------------------------------------------------------------------------
__device__ float g_q[MROWS * DIM];
__device__ float g_k[MROWS * DIM];
__device__ float g_v[MROWS * DIM];
__device__ float g_o[MROWS * DIM];
__device__ float* const g_ptrs[4] = {g_q, g_k, g_v, g_o};

// ---------------------------------------------------------------------------
// SGEMM: C[m][n] = sum_k A[m][k] * Bm[n][k]  (+ bias[n])
// A: [M,K] row-major, Bm: [N,K] row-major (i.e. C = A * Bm^T)
// 128x128 tile, BK=8, 256 threads, 8x8 micro-tile.
// inIdx/outIdx >= 0 select a scratch buffer from g_ptrs; -1 uses the pointer.
// ---------------------------------------------------------------------------
__global__ __launch_bounds__(256, 2)
void sgemm_nt(const float* __restrict__ Aext, const float* __restrict__ Bm,
              const float* __restrict__ bias, float* __restrict__ Cext,
              int inIdx, int outIdx, int M, int N, int K) {
    __shared__ float As[8][128];
    __shared__ float Bs[8][128];

    const float* A = (inIdx >= 0) ? g_ptrs[inIdx] : Aext;
    float* C = (outIdx >= 0) ? g_ptrs[outIdx] : Cext;

    const int t  = threadIdx.x;
    const int tx = t & 15;        // 0..15 -> col group
    const int ty = t >> 4;        // 0..15 -> row group
    const int bx = blockIdx.x;    // n tile
    const int by = blockIdx.y;    // m tile

    const float* Ap = A + (size_t)by * 128 * K;
    const float* Bp = Bm + (size_t)bx * 128 * K;

    const int lr = t >> 1;        // 0..127
    const int lc = (t & 1) * 4;   // 0 or 4

    float acc[8][8];
    #pragma unroll
    for (int i = 0; i < 8; i++)
        #pragma unroll
        for (int j = 0; j < 8; j++) acc[i][j] = 0.f;

    for (int k0 = 0; k0 < K; k0 += 8) {
        float4 a = *(const float4*)(Ap + (size_t)lr * K + k0 + lc);
        float4 b = *(const float4*)(Bp + (size_t)lr * K + k0 + lc);
        __syncthreads();
        As[lc + 0][lr] = a.x; As[lc + 1][lr] = a.y;
        As[lc + 2][lr] = a.z; As[lc + 3][lr] = a.w;
        Bs[lc + 0][lr] = b.x; Bs[lc + 1][lr] = b.y;
        Bs[lc + 2][lr] = b.z; Bs[lc + 3][lr] = b.w;
        __syncthreads();

        #pragma unroll
        for (int kk = 0; kk < 8; kk++) {
            float ar[8], br[8];
            float4 a0 = *(const float4*)&As[kk][ty * 8];
            float4 a1 = *(const float4*)&As[kk][ty * 8 + 4];
            float4 b0 = *(const float4*)&Bs[kk][tx * 8];
            float4 b1 = *(const float4*)&Bs[kk][tx * 8 + 4];
            ar[0]=a0.x; ar[1]=a0.y; ar[2]=a0.z; ar[3]=a0.w;
            ar[4]=a1.x; ar[5]=a1.y; ar[6]=a1.z; ar[7]=a1.w;
            br[0]=b0.x; br[1]=b0.y; br[2]=b0.z; br[3]=b0.w;
            br[4]=b1.x; br[5]=b1.y; br[6]=b1.z; br[7]=b1.w;
            #pragma unroll
            for (int i = 0; i < 8; i++)
                #pragma unroll
                for (int j = 0; j < 8; j++)
                    acc[i][j] = fmaf(ar[i], br[j], acc[i][j]);
        }
    }

    // Epilogue
    #pragma unroll
    for (int i = 0; i < 8; i++) {
        int row = by * 128 + ty * 8 + i;
        #pragma unroll
        for (int j4 = 0; j4 < 2; j4++) {
            int col = bx * 128 + tx * 8 + j4 * 4;
            float4 o;
            o.x = acc[i][j4 * 4 + 0];
            o.y = acc[i][j4 * 4 + 1];
            o.z = acc[i][j4 * 4 + 2];
            o.w = acc[i][j4 * 4 + 3];
            if (bias) {
                o.x += bias[col + 0]; o.y += bias[col + 1];
                o.z += bias[col + 2]; o.w += bias[col + 3];
            }
            *(float4*)(C + (size_t)row * N + col) = o;
        }
    }
}

// ---------------------------------------------------------------------------
// Flash attention (fp32), static shared memory (< 48 KB).
// One block: (b,h) x 64-query tile. 256 threads.
// KV tiles of 32. S micro-tile 4x2 per thread, O micro-tile 4x4.
// Reads g_q/g_k/g_v, writes g_o directly (no pointer args needed).
// ---------------------------------------------------------------------------
#define QT 64
#define KT 32
#define PADQ 65
#define PADP 33

__global__ __launch_bounds__(256, 2)
void attn_kernel() {
    __shared__ float Qs[QT][PADQ];      // 64 x 65
    __shared__ float Ks[KT][PADQ];      // 32 x 65
    __shared__ float Vs[KT][PADQ];      // 32 x 65
    __shared__ float Ps[QT][PADP];      // 64 x 33
    __shared__ float rowmax[QT];
    __shared__ float rowsum[QT];
    __shared__ float ralpha[QT];

    const int t  = threadIdx.x;
    const int tx = t & 15;
    const int ty = t >> 4;
    const int qt = blockIdx.x;            // 0..31
    const int bh = blockIdx.y;            // 0..31
    const int b  = bh >> 4;
    const int h  = bh & 15;
    const int n0 = qt * QT;

    const float* Qbase = g_q + (size_t)b * NSEQ * DIM + (size_t)h * HDIM;
    const float* Kbase = g_k + (size_t)b * NSEQ * DIM + (size_t)h * HDIM;
    const float* Vbase = g_v + (size_t)b * NSEQ * DIM + (size_t)h * HDIM;

    // Load Q tile [64][64] (float4, coalesced): 1024 float4s / 256 threads
    #pragma unroll
    for (int i = 0; i < 4; i++) {
        int idx = t + i * 256;
        int r = idx >> 4;
        int c = (idx & 15) * 4;
        float4 val = *(const float4*)(Qbase + (size_t)(n0 + r) * DIM + c);
        Qs[r][c + 0] = val.x; Qs[r][c + 1] = val.y;
        Qs[r][c + 2] = val.z; Qs[r][c + 3] = val.w;
    }
    if (t < QT) { rowmax[t] = -1e30f; rowsum[t] = 0.f; }

    float acc[4][4];
    #pragma unroll
    for (int i = 0; i < 4; i++)
        #pragma unroll
        for (int j = 0; j < 4; j++) acc[i][j] = 0.f;

    for (int kt = 0; kt < NSEQ / KT; kt++) {
        const int kv0 = kt * KT;

        // Load K tile [32][64]: 512 float4s / 256 threads = 2 iters
        __syncthreads();
        #pragma unroll
        for (int i = 0; i < 2; i++) {
            int idx = t + i * 256;
            int r = idx >> 4;
            int c = (idx & 15) * 4;
            float4 val = *(const float4*)(Kbase + (size_t)(kv0 + r) * DIM + c);
            Ks[r][c + 0] = val.x; Ks[r][c + 1] = val.y;
            Ks[r][c + 2] = val.z; Ks[r][c + 3] = val.w;
        }
        __syncthreads();

        // S = Q * K^T  (4 rows x 2 cols per thread): S is 64x32
        float s[4][2];
        #pragma unroll
        for (int i = 0; i < 4; i++) { s[i][0] = 0.f; s[i][1] = 0.f; }
        #pragma unroll 8
        for (int d = 0; d < HDIM; d++) {
            float qv[4], kv[2];
            #pragma unroll
            for (int i = 0; i < 4; i++) qv[i] = Qs[4 * ty + i][d];
            kv[0] = Ks[2 * tx + 0][d];
            kv[1] = Ks[2 * tx + 1][d];
            #pragma unroll
            for (int i = 0; i < 4; i++) {
                s[i][0] = fmaf(qv[i], kv[0], s[i][0]);
                s[i][1] = fmaf(qv[i], kv[1], s[i][1]);
            }
        }
        #pragma unroll
        for (int i = 0; i < 4; i++) {
            Ps[4 * ty + i][2 * tx + 0] = s[i][0] * ATT_SCALE;
            Ps[4 * ty + i][2 * tx + 1] = s[i][1] * ATT_SCALE;
        }
        __syncthreads();

        // Online softmax per row (threads 0..63 each own one row of 32)
        if (t < QT) {
            float tmax = -1e30f;
            #pragma unroll 8
            for (int k = 0; k < KT; k++) tmax = fmaxf(tmax, Ps[t][k]);
            float nmax = fmaxf(rowmax[t], tmax);
            float a = __expf(rowmax[t] - nmax);
            float lsum = 0.f;
            #pragma unroll 8
            for (int k = 0; k < KT; k++) {
                float p = __expf(Ps[t][k] - nmax);
                Ps[t][k] = p;
                lsum += p;
            }
            rowsum[t] = rowsum[t] * a + lsum;
            rowmax[t] = nmax;
            ralpha[t] = a;
        }

        // Load V tile [32][64] (overlap with softmax; sync after)
        #pragma unroll
        for (int i = 0; i < 2; i++) {
            int idx = t + i * 256;
            int r = idx >> 4;
            int c = (idx & 15) * 4;
            float4 val = *(const float4*)(Vbase + (size_t)(kv0 + r) * DIM + c);
            Vs[r][c + 0] = val.x; Vs[r][c + 1] = val.y;
            Vs[r][c + 2] = val.z; Vs[r][c + 3] = val.w;
        }
        __syncthreads();

        // Rescale accumulators, then O += P * V  (4x4 per thread over 64 cols)
        #pragma unroll
        for (int i = 0; i < 4; i++) {
            float a = ralpha[4 * ty + i];
            #pragma unroll
            for (int j = 0; j < 4; j++) acc[i][j] *= a;
        }
        #pragma unroll 8
        for (int kk = 0; kk < KT; kk++) {
            float pv[4], vv[4];
            #pragma unroll
            for (int i = 0; i < 4; i++) pv[i] = Ps[4 * ty + i][kk];
            #pragma unroll
            for (int j = 0; j < 4; j++) vv[j] = Vs[kk][4 * tx + j];
            #pragma unroll
            for (int i = 0; i < 4; i++)
                #pragma unroll
                for (int j = 0; j < 4; j++)
                    acc[i][j] = fmaf(pv[i], vv[j], acc[i][j]);
        }
    }
    __syncthreads();

    // Normalize and write out: g_o[b, n0+r, h*64 + c]
    #pragma unroll
    for (int i = 0; i < 4; i++) {
        int r = 4 * ty + i;
        float inv = 1.0f / rowsum[r];
        size_t base = (size_t)(b * NSEQ + n0 + r) * DIM + h * HDIM + 4 * tx;
        #pragma unroll
        for (int j = 0; j < 4; j++)
            g_o[base + j] = acc[i][j] * inv;
    }
}

// ---------------------------------------------------------------------------
// Launch: kernel launches ONLY (no host API calls — maximally capture-safe)
// ---------------------------------------------------------------------------
extern "C" void kernel_launch(void* const* d_in, const int* in_sizes, int n_in,
                              void* d_out, int out_size) {
    const float* x1 = (const float*)d_in[0];
    const float* x2 = (const float*)d_in[1];
    const float* wq = (const float*)d_in[2];
    const float* wk = (const float*)d_in[3];
    const float* wv = (const float*)d_in[4];
    const float* wo = (const float*)d_in[5];
    const float* bo = (const float*)d_in[6];
    float* out = (float*)d_out;

    dim3 gg(DIM / 128, MROWS / 128);  // (8, 32)
    // Q = x1 @ wq^T -> g_q (outIdx 0)
    sgemm_nt<<<gg, 256>>>(x1, wq, nullptr, nullptr, -1, 0, MROWS, DIM, DIM);
    // K = x2 @ wk^T -> g_k (outIdx 1)
    sgemm_nt<<<gg, 256>>>(x2, wk, nullptr, nullptr, -1, 1, MROWS, DIM, DIM);
    // V = x2 @ wv^T -> g_v (outIdx 2)
    sgemm_nt<<<gg, 256>>>(x2, wv, nullptr, nullptr, -1, 2, MROWS, DIM, DIM);

    attn_kernel<<<dim3(NSEQ / QT, B * HEADS), 256>>>();

    // out = g_o @ wo^T + bo (inIdx 3 -> g_o)
    sgemm_nt<<<gg, 256>>>(nullptr, wo, bo, out, 3, -1, MROWS, DIM, DIM);
}

// round 6
// speedup vs baseline: 1.0378x; 1.0378x over previous
#include <cuda_runtime.h>
#include <cuda_bf16.h>
#include <cstdint>
#include <math.h>

// Problem shapes (fixed)
#define B 2
#define NSEQ 2048
#define DIM 1024
#define HEADS 16
#define HDIM 64
#define MROWS (B * NSEQ)   // 4096
#define ATT_SCALE 0.125f   // 64^-0.5

#define GM_M 4096
#define GM_N 1024
#define GM_K 1024

// ===========================================================================
// Scratch (device globals). fp32 table + bf16 split table.
// ===========================================================================
__device__ float g_q[MROWS * DIM];
__device__ float g_k[MROWS * DIM];
__device__ float g_v[MROWS * DIM];
__device__ float g_o[MROWS * DIM];
__device__ float* const g_ptrs[4] = {g_q, g_k, g_v, g_o};

__device__ __nv_bfloat16 g_x1h[MROWS * DIM];
__device__ __nv_bfloat16 g_x1l[MROWS * DIM];
__device__ __nv_bfloat16 g_x2h[MROWS * DIM];
__device__ __nv_bfloat16 g_x2l[MROWS * DIM];
__device__ __nv_bfloat16 g_wqh[DIM * DIM];
__device__ __nv_bfloat16 g_wql[DIM * DIM];
__device__ __nv_bfloat16 g_wkh[DIM * DIM];
__device__ __nv_bfloat16 g_wkl[DIM * DIM];
__device__ __nv_bfloat16 g_wvh[DIM * DIM];
__device__ __nv_bfloat16 g_wvl[DIM * DIM];
__device__ __nv_bfloat16 g_woh[DIM * DIM];
__device__ __nv_bfloat16 g_wol[DIM * DIM];
__device__ __nv_bfloat16 g_goh[MROWS * DIM];
__device__ __nv_bfloat16 g_gol[MROWS * DIM];

#define BF_X1H 0
#define BF_X1L 1
#define BF_X2H 2
#define BF_X2L 3
#define BF_WQH 4
#define BF_WQL 5
#define BF_WKH 6
#define BF_WKL 7
#define BF_WVH 8
#define BF_WVL 9
#define BF_WOH 10
#define BF_WOL 11
#define BF_GOH 12
#define BF_GOL 13
__device__ __nv_bfloat16* const g_bf[14] = {
    g_x1h, g_x1l, g_x2h, g_x2l,
    g_wqh, g_wql, g_wkh, g_wkl, g_wvh, g_wvl, g_woh, g_wol,
    g_goh, g_gol
};

// ===========================================================================
// fp32 -> (bf16 hi, bf16 lo) split
// ===========================================================================
__global__ void split_kernel(const float* __restrict__ srcExt, int srcIdx,
                             int hiIdx, int loIdx, int n) {
    const float* src = (srcIdx >= 0) ? g_ptrs[srcIdx] : srcExt;
    __nv_bfloat16* hi = g_bf[hiIdx];
    __nv_bfloat16* lo = g_bf[loIdx];
    for (int i = blockIdx.x * blockDim.x + threadIdx.x; i < n;
         i += gridDim.x * blockDim.x) {
        float x = src[i];
        __nv_bfloat16 h = __float2bfloat16_rn(x);
        float r = x - __bfloat162float(h);
        hi[i] = h;
        lo[i] = __float2bfloat16_rn(r);
    }
}

// ===========================================================================
// mma.sync bf16 m16n8k16 (sm_80+ base ISA)
// ===========================================================================
__device__ __forceinline__ void mma_bf16(float* c, const uint32_t* a,
                                         const uint32_t* b) {
    asm volatile(
        "mma.sync.aligned.m16n8k16.row.col.f32.bf16.bf16.f32 "
        "{%0,%1,%2,%3}, {%4,%5,%6,%7}, {%8,%9}, {%0,%1,%2,%3};"
        : "+f"(c[0]), "+f"(c[1]), "+f"(c[2]), "+f"(c[3])
        : "r"(a[0]), "r"(a[1]), "r"(a[2]), "r"(a[3]),
          "r"(b[0]), "r"(b[1]));
}

// ===========================================================================
// Split-bf16 tensor-core GEMM: C[m][n] = sum_k A[m][k]*Bw[n][k] (+bias)
// C = Ah*Bh + Ah*Bl + Al*Bh, fp32 accum.
// CTA tile 128x128, 8 warps (2x4), warp tile 64x32 (4x4 frags of m16n8k16).
// K chunk 32. Smem: Ah/Al/Bh/Bl [128][40] bf16 (pad 8 -> conflict-free).
// ===========================================================================
#define BKC 32
#define APAD 40

__global__ __launch_bounds__(256, 1)
void gemm_mma(int ahIdx, int alIdx, int bhIdx, int blIdx,
              float* __restrict__ Cext, int outIdx,
              const float* __restrict__ bias) {
    __shared__ __nv_bfloat16 Ahs[128][APAD];
    __shared__ __nv_bfloat16 Als[128][APAD];
    __shared__ __nv_bfloat16 Bhs[128][APAD];
    __shared__ __nv_bfloat16 Bls[128][APAD];

    const int t   = threadIdx.x;
    const int wid = t >> 5;
    const int lid = t & 31;
    const int wm  = wid >> 2;          // 0..1
    const int wn  = wid & 3;           // 0..3
    const int n0  = blockIdx.x * 128;
    const int m0  = blockIdx.y * 128;
    const int qr  = lid >> 2;          // 0..7
    const int qc  = (lid & 3) * 2;     // 0,2,4,6

    float* C = (outIdx >= 0) ? g_ptrs[outIdx] : Cext;

    const __nv_bfloat16* pAh = g_bf[ahIdx] + (size_t)m0 * GM_K;
    const __nv_bfloat16* pAl = g_bf[alIdx] + (size_t)m0 * GM_K;
    const __nv_bfloat16* pBh = g_bf[bhIdx] + (size_t)n0 * GM_K;
    const __nv_bfloat16* pBl = g_bf[blIdx] + (size_t)n0 * GM_K;

    float acc[4][4][4];
    #pragma unroll
    for (int i = 0; i < 4; i++)
        #pragma unroll
        for (int j = 0; j < 4; j++)
            #pragma unroll
            for (int q = 0; q < 4; q++) acc[i][j][q] = 0.f;

    for (int k0 = 0; k0 < GM_K; k0 += BKC) {
        __syncthreads();
        // Load 4 tiles of 128x32 bf16. 512 int4-units per tile / 256 thr.
        #pragma unroll
        for (int i = 0; i < 2; i++) {
            int unit = t + i * 256;        // 0..511
            int r  = unit >> 2;            // 0..127
            int c8 = (unit & 3) * 8;       // 0,8,16,24
            size_t goff = (size_t)r * GM_K + k0 + c8;
            *(int4*)&Ahs[r][c8] = *(const int4*)(pAh + goff);
            *(int4*)&Als[r][c8] = *(const int4*)(pAl + goff);
            *(int4*)&Bhs[r][c8] = *(const int4*)(pBh + goff);
            *(int4*)&Bls[r][c8] = *(const int4*)(pBl + goff);
        }
        __syncthreads();

        #pragma unroll
        for (int ks = 0; ks < 2; ks++) {
            const int kk = ks * 16;
            uint32_t ah[4][4], al[4][4];
            #pragma unroll
            for (int mf = 0; mf < 4; mf++) {
                int r = wm * 64 + mf * 16 + qr;
                ah[mf][0] = *(const uint32_t*)&Ahs[r    ][kk + qc    ];
                ah[mf][1] = *(const uint32_t*)&Ahs[r + 8][kk + qc    ];
                ah[mf][2] = *(const uint32_t*)&Ahs[r    ][kk + qc + 8];
                ah[mf][3] = *(const uint32_t*)&Ahs[r + 8][kk + qc + 8];
                al[mf][0] = *(const uint32_t*)&Als[r    ][kk + qc    ];
                al[mf][1] = *(const uint32_t*)&Als[r + 8][kk + qc    ];
                al[mf][2] = *(const uint32_t*)&Als[r    ][kk + qc + 8];
                al[mf][3] = *(const uint32_t*)&Als[r + 8][kk + qc + 8];
            }
            uint32_t bh[4][2], bl[4][2];
            #pragma unroll
            for (int nf = 0; nf < 4; nf++) {
                int c = wn * 32 + nf * 8 + qr;
                bh[nf][0] = *(const uint32_t*)&Bhs[c][kk + qc    ];
                bh[nf][1] = *(const uint32_t*)&Bhs[c][kk + qc + 8];
                bl[nf][0] = *(const uint32_t*)&Bls[c][kk + qc    ];
                bl[nf][1] = *(const uint32_t*)&Bls[c][kk + qc + 8];
            }
            #pragma unroll
            for (int mf = 0; mf < 4; mf++)
                #pragma unroll
                for (int nf = 0; nf < 4; nf++) {
                    mma_bf16(acc[mf][nf], ah[mf], bh[nf]);
                    mma_bf16(acc[mf][nf], ah[mf], bl[nf]);
                    mma_bf16(acc[mf][nf], al[mf], bh[nf]);
                }
        }
    }

    // Epilogue: acc frag (c0,c1)@(row,col), (c2,c3)@(row+8,col)
    #pragma unroll
    for (int mf = 0; mf < 4; mf++) {
        int row = m0 + wm * 64 + mf * 16 + qr;
        #pragma unroll
        for (int nf = 0; nf < 4; nf++) {
            int col = n0 + wn * 32 + nf * 8 + qc;
            float b0 = 0.f, b1 = 0.f;
            if (bias) { b0 = bias[col]; b1 = bias[col + 1]; }
            float2 v0 = make_float2(acc[mf][nf][0] + b0, acc[mf][nf][1] + b1);
            float2 v1 = make_float2(acc[mf][nf][2] + b0, acc[mf][nf][3] + b1);
            *(float2*)(C + (size_t)row * GM_N + col) = v0;
            *(float2*)(C + (size_t)(row + 8) * GM_N + col) = v1;
        }
    }
}

// ===========================================================================
// Flash attention (fp32), static shared memory. Unchanged from R3.
// ===========================================================================
#define QT 64
#define KT 32
#define PADQ 65
#define PADP 33

__global__ __launch_bounds__(256, 2)
void attn_kernel() {
    __shared__ float Qs[QT][PADQ];
    __shared__ float Ks[KT][PADQ];
    __shared__ float Vs[KT][PADQ];
    __shared__ float Ps[QT][PADP];
    __shared__ float rowmax[QT];
    __shared__ float rowsum[QT];
    __shared__ float ralpha[QT];

    const int t  = threadIdx.x;
    const int tx = t & 15;
    const int ty = t >> 4;
    const int qt = blockIdx.x;
    const int bh = blockIdx.y;
    const int b  = bh >> 4;
    const int h  = bh & 15;
    const int n0 = qt * QT;

    const float* Qbase = g_q + (size_t)b * NSEQ * DIM + (size_t)h * HDIM;
    const float* Kbase = g_k + (size_t)b * NSEQ * DIM + (size_t)h * HDIM;
    const float* Vbase = g_v + (size_t)b * NSEQ * DIM + (size_t)h * HDIM;

    #pragma unroll
    for (int i = 0; i < 4; i++) {
        int idx = t + i * 256;
        int r = idx >> 4;
        int c = (idx & 15) * 4;
        float4 val = *(const float4*)(Qbase + (size_t)(n0 + r) * DIM + c);
        Qs[r][c + 0] = val.x; Qs[r][c + 1] = val.y;
        Qs[r][c + 2] = val.z; Qs[r][c + 3] = val.w;
    }
    if (t < QT) { rowmax[t] = -1e30f; rowsum[t] = 0.f; }

    float acc[4][4];
    #pragma unroll
    for (int i = 0; i < 4; i++)
        #pragma unroll
        for (int j = 0; j < 4; j++) acc[i][j] = 0.f;

    for (int kt = 0; kt < NSEQ / KT; kt++) {
        const int kv0 = kt * KT;

        __syncthreads();
        #pragma unroll
        for (int i = 0; i < 2; i++) {
            int idx = t + i * 256;
            int r = idx >> 4;
            int c = (idx & 15) * 4;
            float4 val = *(const float4*)(Kbase + (size_t)(kv0 + r) * DIM + c);
            Ks[r][c + 0] = val.x; Ks[r][c + 1] = val.y;
            Ks[r][c + 2] = val.z; Ks[r][c + 3] = val.w;
        }
        __syncthreads();

        float s[4][2];
        #pragma unroll
        for (int i = 0; i < 4; i++) { s[i][0] = 0.f; s[i][1] = 0.f; }
        #pragma unroll 8
        for (int d = 0; d < HDIM; d++) {
            float qv[4], kv[2];
            #pragma unroll
            for (int i = 0; i < 4; i++) qv[i] = Qs[4 * ty + i][d];
            kv[0] = Ks[2 * tx + 0][d];
            kv[1] = Ks[2 * tx + 1][d];
            #pragma unroll
            for (int i = 0; i < 4; i++) {
                s[i][0] = fmaf(qv[i], kv[0], s[i][0]);
                s[i][1] = fmaf(qv[i], kv[1], s[i][1]);
            }
        }
        #pragma unroll
        for (int i = 0; i < 4; i++) {
            Ps[4 * ty + i][2 * tx + 0] = s[i][0] * ATT_SCALE;
            Ps[4 * ty + i][2 * tx + 1] = s[i][1] * ATT_SCALE;
        }
        __syncthreads();

        if (t < QT) {
            float tmax = -1e30f;
            #pragma unroll 8
            for (int k = 0; k < KT; k++) tmax = fmaxf(tmax, Ps[t][k]);
            float nmax = fmaxf(rowmax[t], tmax);
            float a = __expf(rowmax[t] - nmax);
            float lsum = 0.f;
            #pragma unroll 8
            for (int k = 0; k < KT; k++) {
                float p = __expf(Ps[t][k] - nmax);
                Ps[t][k] = p;
                lsum += p;
            }
            rowsum[t] = rowsum[t] * a + lsum;
            rowmax[t] = nmax;
            ralpha[t] = a;
        }

        #pragma unroll
        for (int i = 0; i < 2; i++) {
            int idx = t + i * 256;
            int r = idx >> 4;
            int c = (idx & 15) * 4;
            float4 val = *(const float4*)(Vbase + (size_t)(kv0 + r) * DIM + c);
            Vs[r][c + 0] = val.x; Vs[r][c + 1] = val.y;
            Vs[r][c + 2] = val.z; Vs[r][c + 3] = val.w;
        }
        __syncthreads();

        #pragma unroll
        for (int i = 0; i < 4; i++) {
            float a = ralpha[4 * ty + i];
            #pragma unroll
            for (int j = 0; j < 4; j++) acc[i][j] *= a;
        }
        #pragma unroll 8
        for (int kk = 0; kk < KT; kk++) {
            float pv[4], vv[4];
            #pragma unroll
            for (int i = 0; i < 4; i++) pv[i] = Ps[4 * ty + i][kk];
            #pragma unroll
            for (int j = 0; j < 4; j++) vv[j] = Vs[kk][4 * tx + j];
            #pragma unroll
            for (int i = 0; i < 4; i++)
                #pragma unroll
                for (int j = 0; j < 4; j++)
                    acc[i][j] = fmaf(pv[i], vv[j], acc[i][j]);
        }
    }
    __syncthreads();

    #pragma unroll
    for (int i = 0; i < 4; i++) {
        int r = 4 * ty + i;
        float inv = 1.0f / rowsum[r];
        size_t base = (size_t)(b * NSEQ + n0 + r) * DIM + h * HDIM + 4 * tx;
        #pragma unroll
        for (int j = 0; j < 4; j++)
            g_o[base + j] = acc[i][j] * inv;
    }
}

// ===========================================================================
// Launch: kernel launches ONLY
// ===========================================================================
extern "C" void kernel_launch(void* const* d_in, const int* in_sizes, int n_in,
                              void* d_out, int out_size) {
    const float* x1 = (const float*)d_in[0];
    const float* x2 = (const float*)d_in[1];
    const float* wq = (const float*)d_in[2];
    const float* wk = (const float*)d_in[3];
    const float* wv = (const float*)d_in[4];
    const float* wo = (const float*)d_in[5];
    const float* bo = (const float*)d_in[6];
    float* out = (float*)d_out;

    const int NX = MROWS * DIM;   // 4194304
    const int NW = DIM * DIM;     // 1048576

    split_kernel<<<1024, 256>>>(x1, -1, BF_X1H, BF_X1L, NX);
    split_kernel<<<1024, 256>>>(x2, -1, BF_X2H, BF_X2L, NX);
    split_kernel<<<512, 256>>>(wq, -1, BF_WQH, BF_WQL, NW);
    split_kernel<<<512, 256>>>(wk, -1, BF_WKH, BF_WKL, NW);
    split_kernel<<<512, 256>>>(wv, -1, BF_WVH, BF_WVL, NW);
    split_kernel<<<512, 256>>>(wo, -1, BF_WOH, BF_WOL, NW);

    dim3 gg(GM_N / 128, GM_M / 128);  // (8, 32)
    gemm_mma<<<gg, 256>>>(BF_X1H, BF_X1L, BF_WQH, BF_WQL, nullptr, 0, nullptr);
    gemm_mma<<<gg, 256>>>(BF_X2H, BF_X2L, BF_WKH, BF_WKL, nullptr, 1, nullptr);
    gemm_mma<<<gg, 256>>>(BF_X2H, BF_X2L, BF_WVH, BF_WVL, nullptr, 2, nullptr);

    attn_kernel<<<dim3(NSEQ / QT, B * HEADS), 256>>>();

    split_kernel<<<1024, 256>>>(nullptr, 3, BF_GOH, BF_GOL, NX);
    gemm_mma<<<gg, 256>>>(BF_GOH, BF_GOL, BF_WOH, BF_WOL, out, -1, bo);
}

// round 9
// speedup vs baseline: 1.4927x; 1.4383x over previous
#include <cuda_runtime.h>
#include <cuda_bf16.h>
#include <cstdint>
#include <math.h>

// Problem shapes (fixed)
#define B 2
#define NSEQ 2048
#define DIM 1024
#define HEADS 16
#define HDIM 64
#define MROWS (B * NSEQ)   // 4096
#define ATT_SCALE 0.125f   // 64^-0.5

#define GM_M 4096
#define GM_N 1024
#define GM_K 1024

// ===========================================================================
// Scratch: bf16 hi/lo split arrays (device globals)
// ===========================================================================
__device__ __nv_bfloat16 g_x1h[MROWS * DIM];
__device__ __nv_bfloat16 g_x1l[MROWS * DIM];
__device__ __nv_bfloat16 g_x2h[MROWS * DIM];
__device__ __nv_bfloat16 g_x2l[MROWS * DIM];
__device__ __nv_bfloat16 g_wqh[DIM * DIM];
__device__ __nv_bfloat16 g_wql[DIM * DIM];
__device__ __nv_bfloat16 g_wkh[DIM * DIM];
__device__ __nv_bfloat16 g_wkl[DIM * DIM];
__device__ __nv_bfloat16 g_wvh[DIM * DIM];
__device__ __nv_bfloat16 g_wvl[DIM * DIM];
__device__ __nv_bfloat16 g_woh[DIM * DIM];
__device__ __nv_bfloat16 g_wol[DIM * DIM];
__device__ __nv_bfloat16 g_qh[MROWS * DIM];
__device__ __nv_bfloat16 g_ql[MROWS * DIM];
__device__ __nv_bfloat16 g_kh[MROWS * DIM];
__device__ __nv_bfloat16 g_kl[MROWS * DIM];
__device__ __nv_bfloat16 g_vh[MROWS * DIM];
__device__ __nv_bfloat16 g_vl[MROWS * DIM];
__device__ __nv_bfloat16 g_goh[MROWS * DIM];
__device__ __nv_bfloat16 g_gol[MROWS * DIM];

#define BF_X1H 0
#define BF_X1L 1
#define BF_X2H 2
#define BF_X2L 3
#define BF_WQH 4
#define BF_WQL 5
#define BF_WKH 6
#define BF_WKL 7
#define BF_WVH 8
#define BF_WVL 9
#define BF_WOH 10
#define BF_WOL 11
#define BF_QH 12
#define BF_QL 13
#define BF_KH 14
#define BF_KL 15
#define BF_VH 16
#define BF_VL 17
#define BF_GOH 18
#define BF_GOL 19
__device__ __nv_bfloat16* const g_bf[20] = {
    g_x1h, g_x1l, g_x2h, g_x2l,
    g_wqh, g_wql, g_wkh, g_wkl, g_wvh, g_wvl, g_woh, g_wol,
    g_qh, g_ql, g_kh, g_kl, g_vh, g_vl, g_goh, g_gol
};

// ===========================================================================
// Helpers
// ===========================================================================
__device__ __forceinline__ uint32_t pack_bf16(float x, float y) {
    __nv_bfloat162 v = __floats2bfloat162_rn(x, y);   // .x = low = x
    return *(uint32_t*)&v;
}

__device__ __forceinline__ void mma_bf16(float* c, const uint32_t* a,
                                         const uint32_t* b) {
    asm volatile(
        "mma.sync.aligned.m16n8k16.row.col.f32.bf16.bf16.f32 "
        "{%0,%1,%2,%3}, {%4,%5,%6,%7}, {%8,%9}, {%0,%1,%2,%3};"
        : "+f"(c[0]), "+f"(c[1]), "+f"(c[2]), "+f"(c[3])
        : "r"(a[0]), "r"(a[1]), "r"(a[2]), "r"(a[3]),
          "r"(b[0]), "r"(b[1]));
}

// ===========================================================================
// fp32 -> (bf16 hi, bf16 lo) split (external inputs only)
// ===========================================================================
__global__ void split_kernel(const float* __restrict__ src,
                             int hiIdx, int loIdx, int n) {
    __nv_bfloat16* hi = g_bf[hiIdx];
    __nv_bfloat16* lo = g_bf[loIdx];
    for (int i = blockIdx.x * blockDim.x + threadIdx.x; i < n;
         i += gridDim.x * blockDim.x) {
        float x = src[i];
        __nv_bfloat16 h = __float2bfloat16_rn(x);
        float r = x - __bfloat162float(h);
        hi[i] = h;
        lo[i] = __float2bfloat16_rn(r);
    }
}

// ===========================================================================
// Split-bf16 tensor-core GEMM: C = A * Bw^T (+bias), C = Ah*Bh+Ah*Bl+Al*Bh.
// Epilogue: hiIdx>=0 -> write split bf16 (hi,lo); else fp32 + bias to Cext.
// ===========================================================================
#define BKC 32
#define APAD 40

__global__ __launch_bounds__(256, 1)
void gemm_mma(int ahIdx, int alIdx, int bhIdx, int blIdx,
              float* __restrict__ Cext, int hiIdx, int loIdx,
              const float* __restrict__ bias) {
    __shared__ __align__(16) __nv_bfloat16 Ahs[128][APAD];
    __shared__ __align__(16) __nv_bfloat16 Als[128][APAD];
    __shared__ __align__(16) __nv_bfloat16 Bhs[128][APAD];
    __shared__ __align__(16) __nv_bfloat16 Bls[128][APAD];

    const int t   = threadIdx.x;
    const int wid = t >> 5;
    const int lid = t & 31;
    const int wm  = wid >> 2;
    const int wn  = wid & 3;
    const int n0  = blockIdx.x * 128;
    const int m0  = blockIdx.y * 128;
    const int qr  = lid >> 2;
    const int qc  = (lid & 3) * 2;

    const __nv_bfloat16* pAh = g_bf[ahIdx] + (size_t)m0 * GM_K;
    const __nv_bfloat16* pAl = g_bf[alIdx] + (size_t)m0 * GM_K;
    const __nv_bfloat16* pBh = g_bf[bhIdx] + (size_t)n0 * GM_K;
    const __nv_bfloat16* pBl = g_bf[blIdx] + (size_t)n0 * GM_K;

    float acc[4][4][4];
    #pragma unroll
    for (int i = 0; i < 4; i++)
        #pragma unroll
        for (int j = 0; j < 4; j++)
            #pragma unroll
            for (int q = 0; q < 4; q++) acc[i][j][q] = 0.f;

    for (int k0 = 0; k0 < GM_K; k0 += BKC) {
        __syncthreads();
        #pragma unroll
        for (int i = 0; i < 2; i++) {
            int unit = t + i * 256;
            int r  = unit >> 2;
            int c8 = (unit & 3) * 8;
            size_t goff = (size_t)r * GM_K + k0 + c8;
            *(int4*)&Ahs[r][c8] = *(const int4*)(pAh + goff);
            *(int4*)&Als[r][c8] = *(const int4*)(pAl + goff);
            *(int4*)&Bhs[r][c8] = *(const int4*)(pBh + goff);
            *(int4*)&Bls[r][c8] = *(const int4*)(pBl + goff);
        }
        __syncthreads();

        #pragma unroll
        for (int ks = 0; ks < 2; ks++) {
            const int kk = ks * 16;
            uint32_t ah[4][4], al[4][4];
            #pragma unroll
            for (int mf = 0; mf < 4; mf++) {
                int r = wm * 64 + mf * 16 + qr;
                ah[mf][0] = *(const uint32_t*)&Ahs[r    ][kk + qc    ];
                ah[mf][1] = *(const uint32_t*)&Ahs[r + 8][kk + qc    ];
                ah[mf][2] = *(const uint32_t*)&Ahs[r    ][kk + qc + 8];
                ah[mf][3] = *(const uint32_t*)&Ahs[r + 8][kk + qc + 8];
                al[mf][0] = *(const uint32_t*)&Als[r    ][kk + qc    ];
                al[mf][1] = *(const uint32_t*)&Als[r + 8][kk + qc    ];
                al[mf][2] = *(const uint32_t*)&Als[r    ][kk + qc + 8];
                al[mf][3] = *(const uint32_t*)&Als[r + 8][kk + qc + 8];
            }
            uint32_t bh[4][2], bl[4][2];
            #pragma unroll
            for (int nf = 0; nf < 4; nf++) {
                int c = wn * 32 + nf * 8 + qr;
                bh[nf][0] = *(const uint32_t*)&Bhs[c][kk + qc    ];
                bh[nf][1] = *(const uint32_t*)&Bhs[c][kk + qc + 8];
                bl[nf][0] = *(const uint32_t*)&Bls[c][kk + qc    ];
                bl[nf][1] = *(const uint32_t*)&Bls[c][kk + qc + 8];
            }
            #pragma unroll
            for (int mf = 0; mf < 4; mf++)
                #pragma unroll
                for (int nf = 0; nf < 4; nf++) {
                    mma_bf16(acc[mf][nf], ah[mf], bh[nf]);
                    mma_bf16(acc[mf][nf], ah[mf], bl[nf]);
                    mma_bf16(acc[mf][nf], al[mf], bh[nf]);
                }
        }
    }

    if (hiIdx >= 0) {
        __nv_bfloat16* Ch = g_bf[hiIdx];
        __nv_bfloat16* Cl = g_bf[loIdx];
        #pragma unroll
        for (int mf = 0; mf < 4; mf++) {
            int row = m0 + wm * 64 + mf * 16 + qr;
            #pragma unroll
            for (int nf = 0; nf < 4; nf++) {
                int col = n0 + wn * 32 + nf * 8 + qc;
                #pragma unroll
                for (int half = 0; half < 2; half++) {
                    int r = row + half * 8;
                    float v0 = acc[mf][nf][half * 2 + 0];
                    float v1 = acc[mf][nf][half * 2 + 1];
                    float h0 = __bfloat162float(__float2bfloat16_rn(v0));
                    float h1 = __bfloat162float(__float2bfloat16_rn(v1));
                    *(uint32_t*)&Ch[(size_t)r * GM_N + col] = pack_bf16(h0, h1);
                    *(uint32_t*)&Cl[(size_t)r * GM_N + col] =
                        pack_bf16(v0 - h0, v1 - h1);
                }
            }
        }
    } else {
        #pragma unroll
        for (int mf = 0; mf < 4; mf++) {
            int row = m0 + wm * 64 + mf * 16 + qr;
            #pragma unroll
            for (int nf = 0; nf < 4; nf++) {
                int col = n0 + wn * 32 + nf * 8 + qc;
                float b0 = bias ? bias[col] : 0.f;
                float b1 = bias ? bias[col + 1] : 0.f;
                float2 v0 = make_float2(acc[mf][nf][0] + b0, acc[mf][nf][1] + b1);
                float2 v1 = make_float2(acc[mf][nf][2] + b0, acc[mf][nf][3] + b1);
                *(float2*)(Cext + (size_t)row * GM_N + col) = v0;
                *(float2*)(Cext + (size_t)(row + 8) * GM_N + col) = v1;
            }
        }
    }
}

// ===========================================================================
// Flash attention via mma.sync, split-bf16 everywhere.
// Block: 128 threads = 4 warps; warp w owns query rows [16w, 16w+16).
// KV tile 64. Q fragments in registers; K in smem [kv][d]; V transposed
// in smem [d][kv]. Online softmax in registers (quad shfl reductions).
// KPAD=72: row stride 144 B is a 16B multiple (int4 smem stores require it).
// Writes split bf16 to g_goh/g_gol.
// ===========================================================================
#define AKT 64
#define KPAD 72

__global__ __launch_bounds__(128, 2)
void attn_mma() {
    __shared__ __align__(16) __nv_bfloat16 Khs[AKT][KPAD];
    __shared__ __align__(16) __nv_bfloat16 Kls[AKT][KPAD];
    __shared__ __align__(16) __nv_bfloat16 Vths[HDIM][KPAD];
    __shared__ __align__(16) __nv_bfloat16 Vtls[HDIM][KPAD];

    const int t   = threadIdx.x;
    const int wid = t >> 5;
    const int lid = t & 31;
    const int gr  = lid >> 2;          // 0..7
    const int qc  = (lid & 3) * 2;     // 0,2,4,6
    const int qt  = blockIdx.x;        // 0..31
    const int bh  = blockIdx.y;        // 0..31
    const int b   = bh >> 4;
    const int h   = bh & 15;
    const int n0  = qt * 64;
    const int row0 = n0 + wid * 16;    // warp's first query row (within batch)

    const size_t batch_off = (size_t)b * NSEQ * DIM + (size_t)h * HDIM;
    const __nv_bfloat16* Qh = g_qh + batch_off;
    const __nv_bfloat16* Ql = g_ql + batch_off;
    const __nv_bfloat16* Kh = g_kh + batch_off;
    const __nv_bfloat16* Kl = g_kl + batch_off;
    const __nv_bfloat16* Vh = g_vh + batch_off;
    const __nv_bfloat16* Vl = g_vl + batch_off;

    // Q fragments in registers: [kf][4], hi and lo
    uint32_t qfh[4][4], qfl[4][4];
    {
        const int rA = row0 + gr;
        const int rB = rA + 8;
        #pragma unroll
        for (int kf = 0; kf < 4; kf++) {
            int c = kf * 16 + qc;
            qfh[kf][0] = *(const uint32_t*)&Qh[(size_t)rA * DIM + c];
            qfh[kf][1] = *(const uint32_t*)&Qh[(size_t)rB * DIM + c];
            qfh[kf][2] = *(const uint32_t*)&Qh[(size_t)rA * DIM + c + 8];
            qfh[kf][3] = *(const uint32_t*)&Qh[(size_t)rB * DIM + c + 8];
            qfl[kf][0] = *(const uint32_t*)&Ql[(size_t)rA * DIM + c];
            qfl[kf][1] = *(const uint32_t*)&Ql[(size_t)rB * DIM + c];
            qfl[kf][2] = *(const uint32_t*)&Ql[(size_t)rA * DIM + c + 8];
            qfl[kf][3] = *(const uint32_t*)&Ql[(size_t)rB * DIM + c + 8];
        }
    }

    float om0 = -1e30f, om1 = -1e30f;   // running max (unscaled) rows gr, gr+8
    float osum0 = 0.f, osum1 = 0.f;
    float o[8][4];
    #pragma unroll
    for (int nf = 0; nf < 8; nf++)
        #pragma unroll
        for (int q = 0; q < 4; q++) o[nf][q] = 0.f;

    for (int kt = 0; kt < NSEQ / AKT; kt++) {
        const int kv0 = kt * AKT;

        __syncthreads();
        // K tiles: 64x64 bf16, int4 loads (512 units / 128 threads)
        #pragma unroll
        for (int i = 0; i < 4; i++) {
            int unit = t + i * 128;
            int r  = unit >> 3;
            int c8 = (unit & 7) * 8;
            size_t goff = (size_t)(kv0 + r) * DIM + c8;
            *(int4*)&Khs[r][c8] = *(const int4*)(Kh + goff);
            *(int4*)&Kls[r][c8] = *(const int4*)(Kl + goff);
        }
        // V tiles, transposed into smem (scalar bf16 stores)
        #pragma unroll
        for (int i = 0; i < 4; i++) {
            int unit = t + i * 128;
            int r  = unit >> 3;
            int c8 = (unit & 7) * 8;
            size_t goff = (size_t)(kv0 + r) * DIM + c8;
            int4 rawh = *(const int4*)(Vh + goff);
            int4 rawl = *(const int4*)(Vl + goff);
            const __nv_bfloat16* eh = (const __nv_bfloat16*)&rawh;
            const __nv_bfloat16* el = (const __nv_bfloat16*)&rawl;
            #pragma unroll
            for (int j = 0; j < 8; j++) {
                Vths[c8 + j][r] = eh[j];
                Vtls[c8 + j][r] = el[j];
            }
        }
        __syncthreads();

        // S = Q K^T (split 3-product)
        float s[8][4];
        #pragma unroll
        for (int nf = 0; nf < 8; nf++)
            #pragma unroll
            for (int q = 0; q < 4; q++) s[nf][q] = 0.f;
        #pragma unroll
        for (int kf = 0; kf < 4; kf++) {
            const int kk = kf * 16;
            #pragma unroll
            for (int nf = 0; nf < 8; nf++) {
                int c = nf * 8 + gr;
                uint32_t bhf[2], blf[2];
                bhf[0] = *(const uint32_t*)&Khs[c][kk + qc    ];
                bhf[1] = *(const uint32_t*)&Khs[c][kk + qc + 8];
                blf[0] = *(const uint32_t*)&Kls[c][kk + qc    ];
                blf[1] = *(const uint32_t*)&Kls[c][kk + qc + 8];
                mma_bf16(s[nf], qfh[kf], bhf);
                mma_bf16(s[nf], qfh[kf], blf);
                mma_bf16(s[nf], qfl[kf], bhf);
            }
        }

        // Online softmax. Row gr -> c0,c1; row gr+8 -> c2,c3.
        float tmax0 = -1e30f, tmax1 = -1e30f;
        #pragma unroll
        for (int nf = 0; nf < 8; nf++) {
            tmax0 = fmaxf(tmax0, fmaxf(s[nf][0], s[nf][1]));
            tmax1 = fmaxf(tmax1, fmaxf(s[nf][2], s[nf][3]));
        }
        tmax0 = fmaxf(tmax0, __shfl_xor_sync(0xffffffff, tmax0, 1));
        tmax0 = fmaxf(tmax0, __shfl_xor_sync(0xffffffff, tmax0, 2));
        tmax1 = fmaxf(tmax1, __shfl_xor_sync(0xffffffff, tmax1, 1));
        tmax1 = fmaxf(tmax1, __shfl_xor_sync(0xffffffff, tmax1, 2));

        float mn0 = fmaxf(om0, tmax0);
        float mn1 = fmaxf(om1, tmax1);
        float alpha0 = __expf((om0 - mn0) * ATT_SCALE);
        float alpha1 = __expf((om1 - mn1) * ATT_SCALE);
        om0 = mn0; om1 = mn1;

        // exp + split P into bf16 A-fragments (registers only)
        uint32_t ph0[8], ph1[8], pl0[8], pl1[8];
        float lsum0 = 0.f, lsum1 = 0.f;
        #pragma unroll
        for (int nf = 0; nf < 8; nf++) {
            float p0 = __expf((s[nf][0] - mn0) * ATT_SCALE);
            float p1 = __expf((s[nf][1] - mn0) * ATT_SCALE);
            float p2 = __expf((s[nf][2] - mn1) * ATT_SCALE);
            float p3 = __expf((s[nf][3] - mn1) * ATT_SCALE);
            lsum0 += p0 + p1;
            lsum1 += p2 + p3;
            float h0 = __bfloat162float(__float2bfloat16_rn(p0));
            float h1 = __bfloat162float(__float2bfloat16_rn(p1));
            float h2 = __bfloat162float(__float2bfloat16_rn(p2));
            float h3 = __bfloat162float(__float2bfloat16_rn(p3));
            ph0[nf] = pack_bf16(h0, h1);
            ph1[nf] = pack_bf16(h2, h3);
            pl0[nf] = pack_bf16(p0 - h0, p1 - h1);
            pl1[nf] = pack_bf16(p2 - h2, p3 - h3);
        }
        lsum0 += __shfl_xor_sync(0xffffffff, lsum0, 1);
        lsum0 += __shfl_xor_sync(0xffffffff, lsum0, 2);
        lsum1 += __shfl_xor_sync(0xffffffff, lsum1, 1);
        lsum1 += __shfl_xor_sync(0xffffffff, lsum1, 2);
        osum0 = osum0 * alpha0 + lsum0;
        osum1 = osum1 * alpha1 + lsum1;

        // rescale O
        #pragma unroll
        for (int nf = 0; nf < 8; nf++) {
            o[nf][0] *= alpha0; o[nf][1] *= alpha0;
            o[nf][2] *= alpha1; o[nf][3] *= alpha1;
        }

        // O += P V (split 3-product). A-frag kf from S n-frags 2kf, 2kf+1.
        #pragma unroll
        for (int kf = 0; kf < 4; kf++) {
            uint32_t pah[4] = {ph0[2*kf], ph1[2*kf], ph0[2*kf+1], ph1[2*kf+1]};
            uint32_t pal[4] = {pl0[2*kf], pl1[2*kf], pl0[2*kf+1], pl1[2*kf+1]};
            const int kk = kf * 16;
            #pragma unroll
            for (int nf = 0; nf < 8; nf++) {
                int c = nf * 8 + gr;
                uint32_t bhf[2], blf[2];
                bhf[0] = *(const uint32_t*)&Vths[c][kk + qc    ];
                bhf[1] = *(const uint32_t*)&Vths[c][kk + qc + 8];
                blf[0] = *(const uint32_t*)&Vtls[c][kk + qc    ];
                blf[1] = *(const uint32_t*)&Vtls[c][kk + qc + 8];
                mma_bf16(o[nf], pah, bhf);
                mma_bf16(o[nf], pah, blf);
                mma_bf16(o[nf], pal, bhf);
            }
        }
    }

    // Epilogue: normalize, split, store to g_goh/g_gol
    const float inv0 = 1.0f / osum0;
    const float inv1 = 1.0f / osum1;
    const int rowA = b * NSEQ + row0 + gr;
    #pragma unroll
    for (int nf = 0; nf < 8; nf++) {
        int col = h * HDIM + nf * 8 + qc;
        float v0 = o[nf][0] * inv0;
        float v1 = o[nf][1] * inv0;
        float v2 = o[nf][2] * inv1;
        float v3 = o[nf][3] * inv1;
        float h0 = __bfloat162float(__float2bfloat16_rn(v0));
        float h1 = __bfloat162float(__float2bfloat16_rn(v1));
        float h2 = __bfloat162float(__float2bfloat16_rn(v2));
        float h3 = __bfloat162float(__float2bfloat16_rn(v3));
        *(uint32_t*)&g_goh[(size_t)rowA * DIM + col] = pack_bf16(h0, h1);
        *(uint32_t*)&g_gol[(size_t)rowA * DIM + col] = pack_bf16(v0 - h0, v1 - h1);
        *(uint32_t*)&g_goh[(size_t)(rowA + 8) * DIM + col] = pack_bf16(h2, h3);
        *(uint32_t*)&g_gol[(size_t)(rowA + 8) * DIM + col] = pack_bf16(v2 - h2, v3 - h3);
    }
}

// ===========================================================================
// Launch: kernel launches ONLY
// ===========================================================================
extern "C" void kernel_launch(void* const* d_in, const int* in_sizes, int n_in,
                              void* d_out, int out_size) {
    const float* x1 = (const float*)d_in[0];
    const float* x2 = (const float*)d_in[1];
    const float* wq = (const float*)d_in[2];
    const float* wk = (const float*)d_in[3];
    const float* wv = (const float*)d_in[4];
    const float* wo = (const float*)d_in[5];
    const float* bo = (const float*)d_in[6];
    float* out = (float*)d_out;

    const int NX = MROWS * DIM;
    const int NW = DIM * DIM;

    split_kernel<<<1024, 256>>>(x1, BF_X1H, BF_X1L, NX);
    split_kernel<<<1024, 256>>>(x2, BF_X2H, BF_X2L, NX);
    split_kernel<<<512, 256>>>(wq, BF_WQH, BF_WQL, NW);
    split_kernel<<<512, 256>>>(wk, BF_WKH, BF_WKL, NW);
    split_kernel<<<512, 256>>>(wv, BF_WVH, BF_WVL, NW);
    split_kernel<<<512, 256>>>(wo, BF_WOH, BF_WOL, NW);

    dim3 gg(GM_N / 128, GM_M / 128);  // (8, 32)
    gemm_mma<<<gg, 256>>>(BF_X1H, BF_X1L, BF_WQH, BF_WQL, nullptr, BF_QH, BF_QL, nullptr);
    gemm_mma<<<gg, 256>>>(BF_X2H, BF_X2L, BF_WKH, BF_WKL, nullptr, BF_KH, BF_KL, nullptr);
    gemm_mma<<<gg, 256>>>(BF_X2H, BF_X2L, BF_WVH, BF_WVL, nullptr, BF_VH, BF_VL, nullptr);

    attn_mma<<<dim3(NSEQ / 64, B * HEADS), 128>>>();

    gemm_mma<<<gg, 256>>>(BF_GOH, BF_GOL, BF_WOH, BF_WOL, out, -1, -1, bo);
}

// round 10
// speedup vs baseline: 2.3313x; 1.5618x over previous
#include <cuda_runtime.h>
#include <cuda_bf16.h>
#include <cstdint>
#include <math.h>

// Problem shapes (fixed)
#define B 2
#define NSEQ 2048
#define DIM 1024
#define HEADS 16
#define HDIM 64
#define MROWS (B * NSEQ)   // 4096
#define ATT_SCALE 0.125f   // 64^-0.5

#define GM_M 4096
#define GM_N 1024
#define GM_K 1024

// ===========================================================================
// Scratch: bf16 hi/lo split arrays (device globals)
// ===========================================================================
__device__ __nv_bfloat16 g_x1h[MROWS * DIM];
__device__ __nv_bfloat16 g_x1l[MROWS * DIM];
__device__ __nv_bfloat16 g_x2h[MROWS * DIM];
__device__ __nv_bfloat16 g_x2l[MROWS * DIM];
__device__ __nv_bfloat16 g_wqh[DIM * DIM];
__device__ __nv_bfloat16 g_wql[DIM * DIM];
__device__ __nv_bfloat16 g_wkh[DIM * DIM];
__device__ __nv_bfloat16 g_wkl[DIM * DIM];
__device__ __nv_bfloat16 g_wvh[DIM * DIM];
__device__ __nv_bfloat16 g_wvl[DIM * DIM];
__device__ __nv_bfloat16 g_woh[DIM * DIM];
__device__ __nv_bfloat16 g_wol[DIM * DIM];
__device__ __nv_bfloat16 g_qh[MROWS * DIM];
__device__ __nv_bfloat16 g_ql[MROWS * DIM];
__device__ __nv_bfloat16 g_kh[MROWS * DIM];
__device__ __nv_bfloat16 g_kl[MROWS * DIM];
__device__ __nv_bfloat16 g_vh[MROWS * DIM];
__device__ __nv_bfloat16 g_vl[MROWS * DIM];
__device__ __nv_bfloat16 g_goh[MROWS * DIM];
__device__ __nv_bfloat16 g_gol[MROWS * DIM];

#define BF_X1H 0
#define BF_X1L 1
#define BF_X2H 2
#define BF_X2L 3
#define BF_WQH 4
#define BF_WQL 5
#define BF_WKH 6
#define BF_WKL 7
#define BF_WVH 8
#define BF_WVL 9
#define BF_WOH 10
#define BF_WOL 11
#define BF_QH 12
#define BF_QL 13
#define BF_KH 14
#define BF_KL 15
#define BF_VH 16
#define BF_VL 17
#define BF_GOH 18
#define BF_GOL 19
__device__ __nv_bfloat16* const g_bf[20] = {
    g_x1h, g_x1l, g_x2h, g_x2l,
    g_wqh, g_wql, g_wkh, g_wkl, g_wvh, g_wvl, g_woh, g_wol,
    g_qh, g_ql, g_kh, g_kl, g_vh, g_vl, g_goh, g_gol
};

// ===========================================================================
// Helpers
// ===========================================================================
__device__ __forceinline__ uint32_t pack_bf16(float x, float y) {
    __nv_bfloat162 v = __floats2bfloat162_rn(x, y);   // .x = low = x
    return *(uint32_t*)&v;
}

__device__ __forceinline__ void mma_bf16(float* c, const uint32_t* a,
                                         const uint32_t* b) {
    asm volatile(
        "mma.sync.aligned.m16n8k16.row.col.f32.bf16.bf16.f32 "
        "{%0,%1,%2,%3}, {%4,%5,%6,%7}, {%8,%9}, {%0,%1,%2,%3};"
        : "+f"(c[0]), "+f"(c[1]), "+f"(c[2]), "+f"(c[3])
        : "r"(a[0]), "r"(a[1]), "r"(a[2]), "r"(a[3]),
          "r"(b[0]), "r"(b[1]));
}

__device__ __forceinline__ void cp16(void* smem_dst, const void* gsrc) {
    uint32_t d = (uint32_t)__cvta_generic_to_shared(smem_dst);
    asm volatile("cp.async.cg.shared.global [%0], [%1], 16;"
                 :: "r"(d), "l"(gsrc));
}
#define CP_COMMIT() asm volatile("cp.async.commit_group;" ::: "memory")
#define CP_WAIT(n)  asm volatile("cp.async.wait_group %0;" :: "n"(n) : "memory")

// ===========================================================================
// fp32 -> (bf16 hi, bf16 lo) split (external inputs only)
// ===========================================================================
__global__ void split_kernel(const float* __restrict__ src,
                             int hiIdx, int loIdx, int n) {
    __nv_bfloat16* hi = g_bf[hiIdx];
    __nv_bfloat16* lo = g_bf[loIdx];
    for (int i = blockIdx.x * blockDim.x + threadIdx.x; i < n;
         i += gridDim.x * blockDim.x) {
        float x = src[i];
        __nv_bfloat16 h = __float2bfloat16_rn(x);
        float r = x - __bfloat162float(h);
        hi[i] = h;
        lo[i] = __float2bfloat16_rn(r);
    }
}

// ===========================================================================
// Split-bf16 tensor-core GEMM: C = A * Bw^T (+bias), C = Ah*Bh+Ah*Bl+Al*Bh.
// Two-stage cp.async pipeline in dynamic smem (2 x 4 tiles of 128x32 bf16).
// Epilogue: hiIdx>=0 -> write split bf16 (hi,lo); else fp32 + bias to Cext.
// ===========================================================================
#define BKC 32
#define APAD 40
#define GTILE (128 * APAD)            // elems per tile
#define GSTAGE (4 * GTILE)            // elems per stage (Ah,Al,Bh,Bl)
#define GEMM_SMEM_BYTES (2 * GSTAGE * 2)  // 81920 B
#define NCHUNK (GM_K / BKC)           // 32

__global__ __launch_bounds__(256, 1)
void gemm_mma(int ahIdx, int alIdx, int bhIdx, int blIdx,
              float* __restrict__ Cext, int hiIdx, int loIdx,
              const float* __restrict__ bias) {
    extern __shared__ __align__(16) __nv_bfloat16 dyn[];

    const int t   = threadIdx.x;
    const int wid = t >> 5;
    const int lid = t & 31;
    const int wm  = wid >> 2;
    const int wn  = wid & 3;
    const int n0  = blockIdx.x * 128;
    const int m0  = blockIdx.y * 128;
    const int qr  = lid >> 2;
    const int qc  = (lid & 3) * 2;

    const __nv_bfloat16* pAh = g_bf[ahIdx] + (size_t)m0 * GM_K;
    const __nv_bfloat16* pAl = g_bf[alIdx] + (size_t)m0 * GM_K;
    const __nv_bfloat16* pBh = g_bf[bhIdx] + (size_t)n0 * GM_K;
    const __nv_bfloat16* pBl = g_bf[blIdx] + (size_t)n0 * GM_K;

    // per-thread load coords (2 int4 units per array per chunk)
    const int r0 = t >> 2;                 // unit = t
    const int c80 = (t & 3) * 8;
    const int r1 = (t + 256) >> 2;         // unit = t + 256
    const int c81 = ((t + 256) & 3) * 8;

    float acc[4][4][4];
    #pragma unroll
    for (int i = 0; i < 4; i++)
        #pragma unroll
        for (int j = 0; j < 4; j++)
            #pragma unroll
            for (int q = 0; q < 4; q++) acc[i][j][q] = 0.f;

    // stage loader: issues 8 cp.async per thread
    auto load_stage = [&](int stage, int k0) {
        __nv_bfloat16* s = dyn + stage * GSTAGE;
        size_t g0 = (size_t)r0 * GM_K + k0 + c80;
        size_t g1 = (size_t)r1 * GM_K + k0 + c81;
        cp16(&s[0 * GTILE + r0 * APAD + c80], pAh + g0);
        cp16(&s[0 * GTILE + r1 * APAD + c81], pAh + g1);
        cp16(&s[1 * GTILE + r0 * APAD + c80], pAl + g0);
        cp16(&s[1 * GTILE + r1 * APAD + c81], pAl + g1);
        cp16(&s[2 * GTILE + r0 * APAD + c80], pBh + g0);
        cp16(&s[2 * GTILE + r1 * APAD + c81], pBh + g1);
        cp16(&s[3 * GTILE + r0 * APAD + c80], pBl + g0);
        cp16(&s[3 * GTILE + r1 * APAD + c81], pBl + g1);
    };

    load_stage(0, 0);
    CP_COMMIT();

    for (int c = 0; c < NCHUNK; c++) {
        if (c + 1 < NCHUNK) {
            load_stage((c + 1) & 1, (c + 1) * BKC);
            CP_COMMIT();
            CP_WAIT(1);
        } else {
            CP_WAIT(0);
        }
        __syncthreads();

        const __nv_bfloat16* Ahs = dyn + (c & 1) * GSTAGE + 0 * GTILE;
        const __nv_bfloat16* Als = dyn + (c & 1) * GSTAGE + 1 * GTILE;
        const __nv_bfloat16* Bhs = dyn + (c & 1) * GSTAGE + 2 * GTILE;
        const __nv_bfloat16* Bls = dyn + (c & 1) * GSTAGE + 3 * GTILE;

        #pragma unroll
        for (int ks = 0; ks < 2; ks++) {
            const int kk = ks * 16;
            uint32_t ah[4][4], al[4][4];
            #pragma unroll
            for (int mf = 0; mf < 4; mf++) {
                int r = wm * 64 + mf * 16 + qr;
                ah[mf][0] = *(const uint32_t*)&Ahs[(r    ) * APAD + kk + qc    ];
                ah[mf][1] = *(const uint32_t*)&Ahs[(r + 8) * APAD + kk + qc    ];
                ah[mf][2] = *(const uint32_t*)&Ahs[(r    ) * APAD + kk + qc + 8];
                ah[mf][3] = *(const uint32_t*)&Ahs[(r + 8) * APAD + kk + qc + 8];
                al[mf][0] = *(const uint32_t*)&Als[(r    ) * APAD + kk + qc    ];
                al[mf][1] = *(const uint32_t*)&Als[(r + 8) * APAD + kk + qc    ];
                al[mf][2] = *(const uint32_t*)&Als[(r    ) * APAD + kk + qc + 8];
                al[mf][3] = *(const uint32_t*)&Als[(r + 8) * APAD + kk + qc + 8];
            }
            uint32_t bh[4][2], bl[4][2];
            #pragma unroll
            for (int nf = 0; nf < 4; nf++) {
                int cc = wn * 32 + nf * 8 + qr;
                bh[nf][0] = *(const uint32_t*)&Bhs[cc * APAD + kk + qc    ];
                bh[nf][1] = *(const uint32_t*)&Bhs[cc * APAD + kk + qc + 8];
                bl[nf][0] = *(const uint32_t*)&Bls[cc * APAD + kk + qc    ];
                bl[nf][1] = *(const uint32_t*)&Bls[cc * APAD + kk + qc + 8];
            }
            #pragma unroll
            for (int mf = 0; mf < 4; mf++)
                #pragma unroll
                for (int nf = 0; nf < 4; nf++) {
                    mma_bf16(acc[mf][nf], ah[mf], bh[nf]);
                    mma_bf16(acc[mf][nf], ah[mf], bl[nf]);
                    mma_bf16(acc[mf][nf], al[mf], bh[nf]);
                }
        }
        __syncthreads();
    }

    if (hiIdx >= 0) {
        __nv_bfloat16* Ch = g_bf[hiIdx];
        __nv_bfloat16* Cl = g_bf[loIdx];
        #pragma unroll
        for (int mf = 0; mf < 4; mf++) {
            int row = m0 + wm * 64 + mf * 16 + qr;
            #pragma unroll
            for (int nf = 0; nf < 4; nf++) {
                int col = n0 + wn * 32 + nf * 8 + qc;
                #pragma unroll
                for (int half = 0; half < 2; half++) {
                    int r = row + half * 8;
                    float v0 = acc[mf][nf][half * 2 + 0];
                    float v1 = acc[mf][nf][half * 2 + 1];
                    float h0 = __bfloat162float(__float2bfloat16_rn(v0));
                    float h1 = __bfloat162float(__float2bfloat16_rn(v1));
                    *(uint32_t*)&Ch[(size_t)r * GM_N + col] = pack_bf16(h0, h1);
                    *(uint32_t*)&Cl[(size_t)r * GM_N + col] =
                        pack_bf16(v0 - h0, v1 - h1);
                }
            }
        }
    } else {
        #pragma unroll
        for (int mf = 0; mf < 4; mf++) {
            int row = m0 + wm * 64 + mf * 16 + qr;
            #pragma unroll
            for (int nf = 0; nf < 4; nf++) {
                int col = n0 + wn * 32 + nf * 8 + qc;
                float b0 = bias ? bias[col] : 0.f;
                float b1 = bias ? bias[col + 1] : 0.f;
                float2 v0 = make_float2(acc[mf][nf][0] + b0, acc[mf][nf][1] + b1);
                float2 v1 = make_float2(acc[mf][nf][2] + b0, acc[mf][nf][3] + b1);
                *(float2*)(Cext + (size_t)row * GM_N + col) = v0;
                *(float2*)(Cext + (size_t)(row + 8) * GM_N + col) = v1;
            }
        }
    }
}

// ===========================================================================
// Flash attention via mma.sync, split-bf16 everywhere.
// Block: 256 threads = 8 warps; warp w owns query rows [16w, 16w+16) within
// a 128-row q tile (halves KV traffic + transpose work vs 64-row blocks).
// KV tile 64. K via cp.async (overlapped with V register-transpose).
// KPAD=72: row stride 144 B is a 16B multiple (int4/cp16 stores require it).
// Writes split bf16 to g_goh/g_gol.
// ===========================================================================
#define AKT 64
#define KPAD 72

__global__ __launch_bounds__(256, 1)
void attn_mma() {
    __shared__ __align__(16) __nv_bfloat16 Khs[AKT][KPAD];
    __shared__ __align__(16) __nv_bfloat16 Kls[AKT][KPAD];
    __shared__ __align__(16) __nv_bfloat16 Vths[HDIM][KPAD];
    __shared__ __align__(16) __nv_bfloat16 Vtls[HDIM][KPAD];

    const int t   = threadIdx.x;
    const int wid = t >> 5;            // 0..7
    const int lid = t & 31;
    const int gr  = lid >> 2;          // 0..7
    const int qc  = (lid & 3) * 2;     // 0,2,4,6
    const int qt  = blockIdx.x;        // 0..15
    const int bh  = blockIdx.y;        // 0..31
    const int b   = bh >> 4;
    const int h   = bh & 15;
    const int n0  = qt * 128;
    const int row0 = n0 + wid * 16;    // warp's first query row (within batch)

    const size_t batch_off = (size_t)b * NSEQ * DIM + (size_t)h * HDIM;
    const __nv_bfloat16* Qh = g_qh + batch_off;
    const __nv_bfloat16* Ql = g_ql + batch_off;
    const __nv_bfloat16* Kh = g_kh + batch_off;
    const __nv_bfloat16* Kl = g_kl + batch_off;
    const __nv_bfloat16* Vh = g_vh + batch_off;
    const __nv_bfloat16* Vl = g_vl + batch_off;

    // Q fragments in registers: [kf][4], hi and lo
    uint32_t qfh[4][4], qfl[4][4];
    {
        const int rA = row0 + gr;
        const int rB = rA + 8;
        #pragma unroll
        for (int kf = 0; kf < 4; kf++) {
            int c = kf * 16 + qc;
            qfh[kf][0] = *(const uint32_t*)&Qh[(size_t)rA * DIM + c];
            qfh[kf][1] = *(const uint32_t*)&Qh[(size_t)rB * DIM + c];
            qfh[kf][2] = *(const uint32_t*)&Qh[(size_t)rA * DIM + c + 8];
            qfh[kf][3] = *(const uint32_t*)&Qh[(size_t)rB * DIM + c + 8];
            qfl[kf][0] = *(const uint32_t*)&Ql[(size_t)rA * DIM + c];
            qfl[kf][1] = *(const uint32_t*)&Ql[(size_t)rB * DIM + c];
            qfl[kf][2] = *(const uint32_t*)&Ql[(size_t)rA * DIM + c + 8];
            qfl[kf][3] = *(const uint32_t*)&Ql[(size_t)rB * DIM + c + 8];
        }
    }

    float om0 = -1e30f, om1 = -1e30f;   // running max (unscaled) rows gr, gr+8
    float osum0 = 0.f, osum1 = 0.f;
    float o[8][4];
    #pragma unroll
    for (int nf = 0; nf < 8; nf++)
        #pragma unroll
        for (int q = 0; q < 4; q++) o[nf][q] = 0.f;

    for (int kt = 0; kt < NSEQ / AKT; kt++) {
        const int kv0 = kt * AKT;

        __syncthreads();
        // K tiles via cp.async: 512 int4 units / 256 threads = 2 each
        #pragma unroll
        for (int i = 0; i < 2; i++) {
            int unit = t + i * 256;
            int r  = unit >> 3;
            int c8 = (unit & 7) * 8;
            size_t goff = (size_t)(kv0 + r) * DIM + c8;
            cp16(&Khs[r][c8], Kh + goff);
            cp16(&Kls[r][c8], Kl + goff);
        }
        CP_COMMIT();
        // V tiles, transposed into smem (scalar bf16 stores) — overlaps
        // with the K cp.async in flight.
        #pragma unroll
        for (int i = 0; i < 2; i++) {
            int unit = t + i * 256;
            int r  = unit >> 3;
            int c8 = (unit & 7) * 8;
            size_t goff = (size_t)(kv0 + r) * DIM + c8;
            int4 rawh = *(const int4*)(Vh + goff);
            int4 rawl = *(const int4*)(Vl + goff);
            const __nv_bfloat16* eh = (const __nv_bfloat16*)&rawh;
            const __nv_bfloat16* el = (const __nv_bfloat16*)&rawl;
            #pragma unroll
            for (int j = 0; j < 8; j++) {
                Vths[c8 + j][r] = eh[j];
                Vtls[c8 + j][r] = el[j];
            }
        }
        CP_WAIT(0);
        __syncthreads();

        // S = Q K^T (split 3-product)
        float s[8][4];
        #pragma unroll
        for (int nf = 0; nf < 8; nf++)
            #pragma unroll
            for (int q = 0; q < 4; q++) s[nf][q] = 0.f;
        #pragma unroll
        for (int kf = 0; kf < 4; kf++) {
            const int kk = kf * 16;
            #pragma unroll
            for (int nf = 0; nf < 8; nf++) {
                int c = nf * 8 + gr;
                uint32_t bhf[2], blf[2];
                bhf[0] = *(const uint32_t*)&Khs[c][kk + qc    ];
                bhf[1] = *(const uint32_t*)&Khs[c][kk + qc + 8];
                blf[0] = *(const uint32_t*)&Kls[c][kk + qc    ];
                blf[1] = *(const uint32_t*)&Kls[c][kk + qc + 8];
                mma_bf16(s[nf], qfh[kf], bhf);
                mma_bf16(s[nf], qfh[kf], blf);
                mma_bf16(s[nf], qfl[kf], bhf);
            }
        }

        // Online softmax. Row gr -> c0,c1; row gr+8 -> c2,c3.
        float tmax0 = -1e30f, tmax1 = -1e30f;
        #pragma unroll
        for (int nf = 0; nf < 8; nf++) {
            tmax0 = fmaxf(tmax0, fmaxf(s[nf][0], s[nf][1]));
            tmax1 = fmaxf(tmax1, fmaxf(s[nf][2], s[nf][3]));
        }
        tmax0 = fmaxf(tmax0, __shfl_xor_sync(0xffffffff, tmax0, 1));
        tmax0 = fmaxf(tmax0, __shfl_xor_sync(0xffffffff, tmax0, 2));
        tmax1 = fmaxf(tmax1, __shfl_xor_sync(0xffffffff, tmax1, 1));
        tmax1 = fmaxf(tmax1, __shfl_xor_sync(0xffffffff, tmax1, 2));

        float mn0 = fmaxf(om0, tmax0);
        float mn1 = fmaxf(om1, tmax1);
        float alpha0 = __expf((om0 - mn0) * ATT_SCALE);
        float alpha1 = __expf((om1 - mn1) * ATT_SCALE);
        om0 = mn0; om1 = mn1;

        // exp + split P into bf16 A-fragments (registers only)
        uint32_t ph0[8], ph1[8], pl0[8], pl1[8];
        float lsum0 = 0.f, lsum1 = 0.f;
        #pragma unroll
        for (int nf = 0; nf < 8; nf++) {
            float p0 = __expf((s[nf][0] - mn0) * ATT_SCALE);
            float p1 = __expf((s[nf][1] - mn0) * ATT_SCALE);
            float p2 = __expf((s[nf][2] - mn1) * ATT_SCALE);
            float p3 = __expf((s[nf][3] - mn1) * ATT_SCALE);
            lsum0 += p0 + p1;
            lsum1 += p2 + p3;
            float h0 = __bfloat162float(__float2bfloat16_rn(p0));
            float h1 = __bfloat162float(__float2bfloat16_rn(p1));
            float h2 = __bfloat162float(__float2bfloat16_rn(p2));
            float h3 = __bfloat162float(__float2bfloat16_rn(p3));
            ph0[nf] = pack_bf16(h0, h1);
            ph1[nf] = pack_bf16(h2, h3);
            pl0[nf] = pack_bf16(p0 - h0, p1 - h1);
            pl1[nf] = pack_bf16(p2 - h2, p3 - h3);
        }
        lsum0 += __shfl_xor_sync(0xffffffff, lsum0, 1);
        lsum0 += __shfl_xor_sync(0xffffffff, lsum0, 2);
        lsum1 += __shfl_xor_sync(0xffffffff, lsum1, 1);
        lsum1 += __shfl_xor_sync(0xffffffff, lsum1, 2);
        osum0 = osum0 * alpha0 + lsum0;
        osum1 = osum1 * alpha1 + lsum1;

        // rescale O
        #pragma unroll
        for (int nf = 0; nf < 8; nf++) {
            o[nf][0] *= alpha0; o[nf][1] *= alpha0;
            o[nf][2] *= alpha1; o[nf][3] *= alpha1;
        }

        // O += P V (split 3-product). A-frag kf from S n-frags 2kf, 2kf+1.
        #pragma unroll
        for (int kf = 0; kf < 4; kf++) {
            uint32_t pah[4] = {ph0[2*kf], ph1[2*kf], ph0[2*kf+1], ph1[2*kf+1]};
            uint32_t pal[4] = {pl0[2*kf], pl1[2*kf], pl0[2*kf+1], pl1[2*kf+1]};
            const int kk = kf * 16;
            #pragma unroll
            for (int nf = 0; nf < 8; nf++) {
                int c = nf * 8 + gr;
                uint32_t bhf[2], blf[2];
                bhf[0] = *(const uint32_t*)&Vths[c][kk + qc    ];
                bhf[1] = *(const uint32_t*)&Vths[c][kk + qc + 8];
                blf[0] = *(const uint32_t*)&Vtls[c][kk + qc    ];
                blf[1] = *(const uint32_t*)&Vtls[c][kk + qc + 8];
                mma_bf16(o[nf], pah, bhf);
                mma_bf16(o[nf], pah, blf);
                mma_bf16(o[nf], pal, bhf);
            }
        }
    }

    // Epilogue: normalize, split, store to g_goh/g_gol
    const float inv0 = 1.0f / osum0;
    const float inv1 = 1.0f / osum1;
    const int rowA = b * NSEQ + row0 + gr;
    #pragma unroll
    for (int nf = 0; nf < 8; nf++) {
        int col = h * HDIM + nf * 8 + qc;
        float v0 = o[nf][0] * inv0;
        float v1 = o[nf][1] * inv0;
        float v2 = o[nf][2] * inv1;
        float v3 = o[nf][3] * inv1;
        float h0 = __bfloat162float(__float2bfloat16_rn(v0));
        float h1 = __bfloat162float(__float2bfloat16_rn(v1));
        float h2 = __bfloat162float(__float2bfloat16_rn(v2));
        float h3 = __bfloat162float(__float2bfloat16_rn(v3));
        *(uint32_t*)&g_goh[(size_t)rowA * DIM + col] = pack_bf16(h0, h1);
        *(uint32_t*)&g_gol[(size_t)rowA * DIM + col] = pack_bf16(v0 - h0, v1 - h1);
        *(uint32_t*)&g_goh[(size_t)(rowA + 8) * DIM + col] = pack_bf16(h2, h3);
        *(uint32_t*)&g_gol[(size_t)(rowA + 8) * DIM + col] = pack_bf16(v2 - h2, v3 - h3);
    }
}

// ===========================================================================
// Launch
// ===========================================================================
extern "C" void kernel_launch(void* const* d_in, const int* in_sizes, int n_in,
                              void* d_out, int out_size) {
    const float* x1 = (const float*)d_in[0];
    const float* x2 = (const float*)d_in[1];
    const float* wq = (const float*)d_in[2];
    const float* wk = (const float*)d_in[3];
    const float* wv = (const float*)d_in[4];
    const float* wo = (const float*)d_in[5];
    const float* bo = (const float*)d_in[6];
    float* out = (float*)d_out;

    const int NX = MROWS * DIM;
    const int NW = DIM * DIM;

    cudaFuncSetAttribute(gemm_mma,
                         cudaFuncAttributeMaxDynamicSharedMemorySize,
                         GEMM_SMEM_BYTES);

    split_kernel<<<1024, 256>>>(x1, BF_X1H, BF_X1L, NX);
    split_kernel<<<1024, 256>>>(x2, BF_X2H, BF_X2L, NX);
    split_kernel<<<512, 256>>>(wq, BF_WQH, BF_WQL, NW);
    split_kernel<<<512, 256>>>(wk, BF_WKH, BF_WKL, NW);
    split_kernel<<<512, 256>>>(wv, BF_WVH, BF_WVL, NW);
    split_kernel<<<512, 256>>>(wo, BF_WOH, BF_WOL, NW);

    dim3 gg(GM_N / 128, GM_M / 128);  // (8, 32)
    gemm_mma<<<gg, 256, GEMM_SMEM_BYTES>>>(BF_X1H, BF_X1L, BF_WQH, BF_WQL,
                                           nullptr, BF_QH, BF_QL, nullptr);
    gemm_mma<<<gg, 256, GEMM_SMEM_BYTES>>>(BF_X2H, BF_X2L, BF_WKH, BF_WKL,
                                           nullptr, BF_KH, BF_KL, nullptr);
    gemm_mma<<<gg, 256, GEMM_SMEM_BYTES>>>(BF_X2H, BF_X2L, BF_WVH, BF_WVL,
                                           nullptr, BF_VH, BF_VL, nullptr);

    attn_mma<<<dim3(NSEQ / 128, B * HEADS), 256>>>();

    gemm_mma<<<gg, 256, GEMM_SMEM_BYTES>>>(BF_GOH, BF_GOL, BF_WOH, BF_WOL,
                                           out, -1, -1, bo);
}

// round 11
// speedup vs baseline: 2.6893x; 1.1535x over previous
#include <cuda_runtime.h>
#include <cuda_bf16.h>
#include <cstdint>
#include <math.h>

// Problem shapes (fixed)
#define B 2
#define NSEQ 2048
#define DIM 1024
#define HEADS 16
#define HDIM 64
#define MROWS (B * NSEQ)   // 4096
#define ATT_SCALE 0.125f   // 64^-0.5

#define GM_M 4096
#define GM_N 1024
#define GM_K 1024

// ===========================================================================
// Scratch: bf16 hi/lo split arrays (device globals)
// ===========================================================================
__device__ __nv_bfloat16 g_x1h[MROWS * DIM];
__device__ __nv_bfloat16 g_x1l[MROWS * DIM];
__device__ __nv_bfloat16 g_x2h[MROWS * DIM];
__device__ __nv_bfloat16 g_x2l[MROWS * DIM];
__device__ __nv_bfloat16 g_wqh[DIM * DIM];
__device__ __nv_bfloat16 g_wql[DIM * DIM];
__device__ __nv_bfloat16 g_wkh[DIM * DIM];
__device__ __nv_bfloat16 g_wkl[DIM * DIM];
__device__ __nv_bfloat16 g_wvh[DIM * DIM];
__device__ __nv_bfloat16 g_wvl[DIM * DIM];
__device__ __nv_bfloat16 g_woh[DIM * DIM];
__device__ __nv_bfloat16 g_wol[DIM * DIM];
__device__ __nv_bfloat16 g_qh[MROWS * DIM];
__device__ __nv_bfloat16 g_ql[MROWS * DIM];
__device__ __nv_bfloat16 g_kh[MROWS * DIM];
__device__ __nv_bfloat16 g_kl[MROWS * DIM];
__device__ __nv_bfloat16 g_vh[MROWS * DIM];
__device__ __nv_bfloat16 g_vl[MROWS * DIM];
__device__ __nv_bfloat16 g_goh[MROWS * DIM];
__device__ __nv_bfloat16 g_gol[MROWS * DIM];

#define BF_X1H 0
#define BF_X1L 1
#define BF_X2H 2
#define BF_X2L 3
#define BF_WQH 4
#define BF_WQL 5
#define BF_WKH 6
#define BF_WKL 7
#define BF_WVH 8
#define BF_WVL 9
#define BF_WOH 10
#define BF_WOL 11
#define BF_QH 12
#define BF_QL 13
#define BF_KH 14
#define BF_KL 15
#define BF_VH 16
#define BF_VL 17
#define BF_GOH 18
#define BF_GOL 19
__device__ __nv_bfloat16* const g_bf[20] = {
    g_x1h, g_x1l, g_x2h, g_x2l,
    g_wqh, g_wql, g_wkh, g_wkl, g_wvh, g_wvl, g_woh, g_wol,
    g_qh, g_ql, g_kh, g_kl, g_vh, g_vl, g_goh, g_gol
};

// ===========================================================================
// Helpers
// ===========================================================================
__device__ __forceinline__ uint32_t pack_bf16(float x, float y) {
    __nv_bfloat162 v = __floats2bfloat162_rn(x, y);   // .x = low = x
    return *(uint32_t*)&v;
}

__device__ __forceinline__ void mma_bf16(float* c, const uint32_t* a,
                                         const uint32_t* b) {
    asm volatile(
        "mma.sync.aligned.m16n8k16.row.col.f32.bf16.bf16.f32 "
        "{%0,%1,%2,%3}, {%4,%5,%6,%7}, {%8,%9}, {%0,%1,%2,%3};"
        : "+f"(c[0]), "+f"(c[1]), "+f"(c[2]), "+f"(c[3])
        : "r"(a[0]), "r"(a[1]), "r"(a[2]), "r"(a[3]),
          "r"(b[0]), "r"(b[1]));
}

__device__ __forceinline__ void cp16(void* smem_dst, const void* gsrc) {
    uint32_t d = (uint32_t)__cvta_generic_to_shared(smem_dst);
    asm volatile("cp.async.cg.shared.global [%0], [%1], 16;"
                 :: "r"(d), "l"(gsrc));
}
#define CP_COMMIT() asm volatile("cp.async.commit_group;" ::: "memory")
#define CP_WAIT(n)  asm volatile("cp.async.wait_group %0;" :: "n"(n) : "memory")

__device__ __forceinline__ uint32_t smem_u32(const void* p) {
    return (uint32_t)__cvta_generic_to_shared(p);
}
__device__ __forceinline__ void ldm_x4(uint32_t* r, uint32_t addr) {
    asm volatile("ldmatrix.sync.aligned.m8n8.x4.shared.b16 {%0,%1,%2,%3}, [%4];"
                 : "=r"(r[0]), "=r"(r[1]), "=r"(r[2]), "=r"(r[3]) : "r"(addr));
}
__device__ __forceinline__ void ldm_x4_t(uint32_t* r, uint32_t addr) {
    asm volatile("ldmatrix.sync.aligned.m8n8.x4.trans.shared.b16 {%0,%1,%2,%3}, [%4];"
                 : "=r"(r[0]), "=r"(r[1]), "=r"(r[2]), "=r"(r[3]) : "r"(addr));
}

// ===========================================================================
// fp32 -> (bf16 hi, bf16 lo) split (external inputs only)
// ===========================================================================
__global__ void split_kernel(const float* __restrict__ src,
                             int hiIdx, int loIdx, int n) {
    __nv_bfloat16* hi = g_bf[hiIdx];
    __nv_bfloat16* lo = g_bf[loIdx];
    for (int i = blockIdx.x * blockDim.x + threadIdx.x; i < n;
         i += gridDim.x * blockDim.x) {
        float x = src[i];
        __nv_bfloat16 h = __float2bfloat16_rn(x);
        float r = x - __bfloat162float(h);
        hi[i] = h;
        lo[i] = __float2bfloat16_rn(r);
    }
}

// ===========================================================================
// Split-bf16 tensor-core GEMM: C = A * Bw^T (+bias), C = Ah*Bh+Ah*Bl+Al*Bh.
// Two-stage cp.async pipeline in dynamic smem. Fragments via ldmatrix.x4.
// Epilogue: hiIdx>=0 -> write split bf16 (hi,lo); else fp32 + bias to Cext.
// ===========================================================================
#define BKC 32
#define APAD 40
#define GTILE (128 * APAD)            // elems per tile
#define GSTAGE (4 * GTILE)            // elems per stage (Ah,Al,Bh,Bl)
#define GEMM_SMEM_BYTES (2 * GSTAGE * 2)  // 81920 B
#define NCHUNK (GM_K / BKC)           // 32

__global__ __launch_bounds__(256, 1)
void gemm_mma(int ahIdx, int alIdx, int bhIdx, int blIdx,
              float* __restrict__ Cext, int hiIdx, int loIdx,
              const float* __restrict__ bias) {
    extern __shared__ __align__(16) __nv_bfloat16 dyn[];

    const int t   = threadIdx.x;
    const int wid = t >> 5;
    const int lid = t & 31;
    const int wm  = wid >> 2;
    const int wn  = wid & 3;
    const int n0  = blockIdx.x * 128;
    const int m0  = blockIdx.y * 128;
    const int qr  = lid >> 2;
    const int qc  = (lid & 3) * 2;

    // ldmatrix lane offsets
    const int a_ro = (lid & 7) + (lid & 8);      // A: row offset
    const int a_co = (lid & 16) >> 1;            // A: col offset (0 or 8)
    const int b_ro = (lid & 7) + ((lid & 16) >> 1); // B: n-row offset
    const int b_co = (lid & 8);                  // B: k-col offset (0 or 8)

    const __nv_bfloat16* pAh = g_bf[ahIdx] + (size_t)m0 * GM_K;
    const __nv_bfloat16* pAl = g_bf[alIdx] + (size_t)m0 * GM_K;
    const __nv_bfloat16* pBh = g_bf[bhIdx] + (size_t)n0 * GM_K;
    const __nv_bfloat16* pBl = g_bf[blIdx] + (size_t)n0 * GM_K;

    // per-thread load coords (2 int4 units per array per chunk)
    const int r0 = t >> 2;
    const int c80 = (t & 3) * 8;
    const int r1 = (t + 256) >> 2;
    const int c81 = ((t + 256) & 3) * 8;

    float acc[4][4][4];
    #pragma unroll
    for (int i = 0; i < 4; i++)
        #pragma unroll
        for (int j = 0; j < 4; j++)
            #pragma unroll
            for (int q = 0; q < 4; q++) acc[i][j][q] = 0.f;

    auto load_stage = [&](int stage, int k0) {
        __nv_bfloat16* s = dyn + stage * GSTAGE;
        size_t g0 = (size_t)r0 * GM_K + k0 + c80;
        size_t g1 = (size_t)r1 * GM_K + k0 + c81;
        cp16(&s[0 * GTILE + r0 * APAD + c80], pAh + g0);
        cp16(&s[0 * GTILE + r1 * APAD + c81], pAh + g1);
        cp16(&s[1 * GTILE + r0 * APAD + c80], pAl + g0);
        cp16(&s[1 * GTILE + r1 * APAD + c81], pAl + g1);
        cp16(&s[2 * GTILE + r0 * APAD + c80], pBh + g0);
        cp16(&s[2 * GTILE + r1 * APAD + c81], pBh + g1);
        cp16(&s[3 * GTILE + r0 * APAD + c80], pBl + g0);
        cp16(&s[3 * GTILE + r1 * APAD + c81], pBl + g1);
    };

    load_stage(0, 0);
    CP_COMMIT();

    for (int c = 0; c < NCHUNK; c++) {
        if (c + 1 < NCHUNK) {
            load_stage((c + 1) & 1, (c + 1) * BKC);
            CP_COMMIT();
            CP_WAIT(1);
        } else {
            CP_WAIT(0);
        }
        __syncthreads();

        const __nv_bfloat16* Ahs = dyn + (c & 1) * GSTAGE + 0 * GTILE;
        const __nv_bfloat16* Als = dyn + (c & 1) * GSTAGE + 1 * GTILE;
        const __nv_bfloat16* Bhs = dyn + (c & 1) * GSTAGE + 2 * GTILE;
        const __nv_bfloat16* Bls = dyn + (c & 1) * GSTAGE + 3 * GTILE;

        #pragma unroll
        for (int ks = 0; ks < 2; ks++) {
            const int kk = ks * 16;
            uint32_t ah[4][4], al[4][4];
            #pragma unroll
            for (int mf = 0; mf < 4; mf++) {
                int r = wm * 64 + mf * 16 + a_ro;
                ldm_x4(ah[mf], smem_u32(&Ahs[r * APAD + kk + a_co]));
                ldm_x4(al[mf], smem_u32(&Als[r * APAD + kk + a_co]));
            }
            uint32_t bh[4][2], bl[4][2];
            #pragma unroll
            for (int nfp = 0; nfp < 2; nfp++) {
                int cc = wn * 32 + nfp * 16 + b_ro;
                uint32_t b4h[4], b4l[4];
                ldm_x4(b4h, smem_u32(&Bhs[cc * APAD + kk + b_co]));
                ldm_x4(b4l, smem_u32(&Bls[cc * APAD + kk + b_co]));
                bh[2*nfp][0] = b4h[0]; bh[2*nfp][1] = b4h[1];
                bh[2*nfp+1][0] = b4h[2]; bh[2*nfp+1][1] = b4h[3];
                bl[2*nfp][0] = b4l[0]; bl[2*nfp][1] = b4l[1];
                bl[2*nfp+1][0] = b4l[2]; bl[2*nfp+1][1] = b4l[3];
            }
            #pragma unroll
            for (int mf = 0; mf < 4; mf++)
                #pragma unroll
                for (int nf = 0; nf < 4; nf++) {
                    mma_bf16(acc[mf][nf], ah[mf], bh[nf]);
                    mma_bf16(acc[mf][nf], ah[mf], bl[nf]);
                    mma_bf16(acc[mf][nf], al[mf], bh[nf]);
                }
        }
        __syncthreads();
    }

    if (hiIdx >= 0) {
        __nv_bfloat16* Ch = g_bf[hiIdx];
        __nv_bfloat16* Cl = g_bf[loIdx];
        #pragma unroll
        for (int mf = 0; mf < 4; mf++) {
            int row = m0 + wm * 64 + mf * 16 + qr;
            #pragma unroll
            for (int nf = 0; nf < 4; nf++) {
                int col = n0 + wn * 32 + nf * 8 + qc;
                #pragma unroll
                for (int half = 0; half < 2; half++) {
                    int r = row + half * 8;
                    float v0 = acc[mf][nf][half * 2 + 0];
                    float v1 = acc[mf][nf][half * 2 + 1];
                    float h0 = __bfloat162float(__float2bfloat16_rn(v0));
                    float h1 = __bfloat162float(__float2bfloat16_rn(v1));
                    *(uint32_t*)&Ch[(size_t)r * GM_N + col] = pack_bf16(h0, h1);
                    *(uint32_t*)&Cl[(size_t)r * GM_N + col] =
                        pack_bf16(v0 - h0, v1 - h1);
                }
            }
        }
    } else {
        #pragma unroll
        for (int mf = 0; mf < 4; mf++) {
            int row = m0 + wm * 64 + mf * 16 + qr;
            #pragma unroll
            for (int nf = 0; nf < 4; nf++) {
                int col = n0 + wn * 32 + nf * 8 + qc;
                float b0 = bias ? bias[col] : 0.f;
                float b1 = bias ? bias[col + 1] : 0.f;
                float2 v0 = make_float2(acc[mf][nf][0] + b0, acc[mf][nf][1] + b1);
                float2 v1 = make_float2(acc[mf][nf][2] + b0, acc[mf][nf][3] + b1);
                *(float2*)(Cext + (size_t)row * GM_N + col) = v0;
                *(float2*)(Cext + (size_t)(row + 8) * GM_N + col) = v1;
            }
        }
    }
}

// ===========================================================================
// Flash attention via mma.sync, split-bf16 everywhere.
// Block: 256 threads = 8 warps; warp w owns query rows [16w, 16w+16) of a
// 128-row q tile. KV tile 64. K and V stored raw [kv][d] via cp.async;
// K fragments via ldmatrix.x4 (col-major B), V via ldmatrix.x4.trans
// (no scalar transpose). Online softmax in registers.
// KPAD=72: 144 B row stride (16B multiple, ldmatrix conflict-free).
// ===========================================================================
#define AKT 64
#define KPAD 72

__global__ __launch_bounds__(256, 1)
void attn_mma() {
    __shared__ __align__(16) __nv_bfloat16 Khs[AKT][KPAD];
    __shared__ __align__(16) __nv_bfloat16 Kls[AKT][KPAD];
    __shared__ __align__(16) __nv_bfloat16 Vhs[AKT][KPAD];
    __shared__ __align__(16) __nv_bfloat16 Vls[AKT][KPAD];

    const int t   = threadIdx.x;
    const int wid = t >> 5;            // 0..7
    const int lid = t & 31;
    const int gr  = lid >> 2;          // 0..7
    const int qc  = (lid & 3) * 2;     // 0,2,4,6
    const int qt  = blockIdx.x;        // 0..15
    const int bh  = blockIdx.y;        // 0..31
    const int b   = bh >> 4;
    const int h   = bh & 15;
    const int n0  = qt * 128;
    const int row0 = n0 + wid * 16;

    // ldmatrix lane offsets
    const int kb_ro = (lid & 7) + ((lid & 16) >> 1); // K: n(kv)-row offset
    const int kb_co = (lid & 8);                     // K: k(d)-col offset
    const int vb_ro = (lid & 7) + (lid & 8);         // V: kv-row offset
    const int vb_co = (lid & 16) >> 1;               // V: d-col offset

    const size_t batch_off = (size_t)b * NSEQ * DIM + (size_t)h * HDIM;
    const __nv_bfloat16* Qh = g_qh + batch_off;
    const __nv_bfloat16* Ql = g_ql + batch_off;
    const __nv_bfloat16* Kh = g_kh + batch_off;
    const __nv_bfloat16* Kl = g_kl + batch_off;
    const __nv_bfloat16* Vh = g_vh + batch_off;
    const __nv_bfloat16* Vl = g_vl + batch_off;

    // Q fragments in registers: [kf][4], hi and lo
    uint32_t qfh[4][4], qfl[4][4];
    {
        const int rA = row0 + gr;
        const int rB = rA + 8;
        #pragma unroll
        for (int kf = 0; kf < 4; kf++) {
            int c = kf * 16 + qc;
            qfh[kf][0] = *(const uint32_t*)&Qh[(size_t)rA * DIM + c];
            qfh[kf][1] = *(const uint32_t*)&Qh[(size_t)rB * DIM + c];
            qfh[kf][2] = *(const uint32_t*)&Qh[(size_t)rA * DIM + c + 8];
            qfh[kf][3] = *(const uint32_t*)&Qh[(size_t)rB * DIM + c + 8];
            qfl[kf][0] = *(const uint32_t*)&Ql[(size_t)rA * DIM + c];
            qfl[kf][1] = *(const uint32_t*)&Ql[(size_t)rB * DIM + c];
            qfl[kf][2] = *(const uint32_t*)&Ql[(size_t)rA * DIM + c + 8];
            qfl[kf][3] = *(const uint32_t*)&Ql[(size_t)rB * DIM + c + 8];
        }
    }

    float om0 = -1e30f, om1 = -1e30f;
    float osum0 = 0.f, osum1 = 0.f;
    float o[8][4];
    #pragma unroll
    for (int nf = 0; nf < 8; nf++)
        #pragma unroll
        for (int q = 0; q < 4; q++) o[nf][q] = 0.f;

    for (int kt = 0; kt < NSEQ / AKT; kt++) {
        const int kv0 = kt * AKT;

        __syncthreads();
        // K + V tiles via cp.async: 512 int4 units per array / 256 threads
        #pragma unroll
        for (int i = 0; i < 2; i++) {
            int unit = t + i * 256;
            int r  = unit >> 3;
            int c8 = (unit & 7) * 8;
            size_t goff = (size_t)(kv0 + r) * DIM + c8;
            cp16(&Khs[r][c8], Kh + goff);
            cp16(&Kls[r][c8], Kl + goff);
            cp16(&Vhs[r][c8], Vh + goff);
            cp16(&Vls[r][c8], Vl + goff);
        }
        CP_COMMIT();
        CP_WAIT(0);
        __syncthreads();

        // S = Q K^T (split 3-product); K frags via ldmatrix.x4
        float s[8][4];
        #pragma unroll
        for (int nf = 0; nf < 8; nf++)
            #pragma unroll
            for (int q = 0; q < 4; q++) s[nf][q] = 0.f;
        #pragma unroll
        for (int kf = 0; kf < 4; kf++) {
            const int kk = kf * 16;
            #pragma unroll
            for (int nfp = 0; nfp < 4; nfp++) {
                uint32_t b4h[4], b4l[4];
                int cc = nfp * 16 + kb_ro;
                ldm_x4(b4h, smem_u32(&Khs[cc][kk + kb_co]));
                ldm_x4(b4l, smem_u32(&Kls[cc][kk + kb_co]));
                mma_bf16(s[2*nfp    ], qfh[kf], b4h + 0);
                mma_bf16(s[2*nfp    ], qfh[kf], b4l + 0);
                mma_bf16(s[2*nfp    ], qfl[kf], b4h + 0);
                mma_bf16(s[2*nfp + 1], qfh[kf], b4h + 2);
                mma_bf16(s[2*nfp + 1], qfh[kf], b4l + 2);
                mma_bf16(s[2*nfp + 1], qfl[kf], b4h + 2);
            }
        }

        // Online softmax. Row gr -> c0,c1; row gr+8 -> c2,c3.
        float tmax0 = -1e30f, tmax1 = -1e30f;
        #pragma unroll
        for (int nf = 0; nf < 8; nf++) {
            tmax0 = fmaxf(tmax0, fmaxf(s[nf][0], s[nf][1]));
            tmax1 = fmaxf(tmax1, fmaxf(s[nf][2], s[nf][3]));
        }
        tmax0 = fmaxf(tmax0, __shfl_xor_sync(0xffffffff, tmax0, 1));
        tmax0 = fmaxf(tmax0, __shfl_xor_sync(0xffffffff, tmax0, 2));
        tmax1 = fmaxf(tmax1, __shfl_xor_sync(0xffffffff, tmax1, 1));
        tmax1 = fmaxf(tmax1, __shfl_xor_sync(0xffffffff, tmax1, 2));

        float mn0 = fmaxf(om0, tmax0);
        float mn1 = fmaxf(om1, tmax1);
        float alpha0 = __expf((om0 - mn0) * ATT_SCALE);
        float alpha1 = __expf((om1 - mn1) * ATT_SCALE);
        om0 = mn0; om1 = mn1;

        uint32_t ph0[8], ph1[8], pl0[8], pl1[8];
        float lsum0 = 0.f, lsum1 = 0.f;
        #pragma unroll
        for (int nf = 0; nf < 8; nf++) {
            float p0 = __expf((s[nf][0] - mn0) * ATT_SCALE);
            float p1 = __expf((s[nf][1] - mn0) * ATT_SCALE);
            float p2 = __expf((s[nf][2] - mn1) * ATT_SCALE);
            float p3 = __expf((s[nf][3] - mn1) * ATT_SCALE);
            lsum0 += p0 + p1;
            lsum1 += p2 + p3;
            float h0 = __bfloat162float(__float2bfloat16_rn(p0));
            float h1 = __bfloat162float(__float2bfloat16_rn(p1));
            float h2 = __bfloat162float(__float2bfloat16_rn(p2));
            float h3 = __bfloat162float(__float2bfloat16_rn(p3));
            ph0[nf] = pack_bf16(h0, h1);
            ph1[nf] = pack_bf16(h2, h3);
            pl0[nf] = pack_bf16(p0 - h0, p1 - h1);
            pl1[nf] = pack_bf16(p2 - h2, p3 - h3);
        }
        lsum0 += __shfl_xor_sync(0xffffffff, lsum0, 1);
        lsum0 += __shfl_xor_sync(0xffffffff, lsum0, 2);
        lsum1 += __shfl_xor_sync(0xffffffff, lsum1, 1);
        lsum1 += __shfl_xor_sync(0xffffffff, lsum1, 2);
        osum0 = osum0 * alpha0 + lsum0;
        osum1 = osum1 * alpha1 + lsum1;

        #pragma unroll
        for (int nf = 0; nf < 8; nf++) {
            o[nf][0] *= alpha0; o[nf][1] *= alpha0;
            o[nf][2] *= alpha1; o[nf][3] *= alpha1;
        }

        // O += P V (split 3-product); V frags via ldmatrix.x4.trans
        #pragma unroll
        for (int kf = 0; kf < 4; kf++) {
            uint32_t pah[4] = {ph0[2*kf], ph1[2*kf], ph0[2*kf+1], ph1[2*kf+1]};
            uint32_t pal[4] = {pl0[2*kf], pl1[2*kf], pl0[2*kf+1], pl1[2*kf+1]};
            const int kk = kf * 16;
            #pragma unroll
            for (int nfp = 0; nfp < 4; nfp++) {
                uint32_t b4h[4], b4l[4];
                int rr = kk + vb_ro;
                int cc = nfp * 16 + vb_co;
                ldm_x4_t(b4h, smem_u32(&Vhs[rr][cc]));
                ldm_x4_t(b4l, smem_u32(&Vls[rr][cc]));
                mma_bf16(o[2*nfp    ], pah, b4h + 0);
                mma_bf16(o[2*nfp    ], pah, b4l + 0);
                mma_bf16(o[2*nfp    ], pal, b4h + 0);
                mma_bf16(o[2*nfp + 1], pah, b4h + 2);
                mma_bf16(o[2*nfp + 1], pah, b4l + 2);
                mma_bf16(o[2*nfp + 1], pal, b4h + 2);
            }
        }
    }

    // Epilogue: normalize, split, store to g_goh/g_gol
    const float inv0 = 1.0f / osum0;
    const float inv1 = 1.0f / osum1;
    const int rowA = b * NSEQ + row0 + gr;
    #pragma unroll
    for (int nf = 0; nf < 8; nf++) {
        int col = h * HDIM + nf * 8 + qc;
        float v0 = o[nf][0] * inv0;
        float v1 = o[nf][1] * inv0;
        float v2 = o[nf][2] * inv1;
        float v3 = o[nf][3] * inv1;
        float h0 = __bfloat162float(__float2bfloat16_rn(v0));
        float h1 = __bfloat162float(__float2bfloat16_rn(v1));
        float h2 = __bfloat162float(__float2bfloat16_rn(v2));
        float h3 = __bfloat162float(__float2bfloat16_rn(v3));
        *(uint32_t*)&g_goh[(size_t)rowA * DIM + col] = pack_bf16(h0, h1);
        *(uint32_t*)&g_gol[(size_t)rowA * DIM + col] = pack_bf16(v0 - h0, v1 - h1);
        *(uint32_t*)&g_goh[(size_t)(rowA + 8) * DIM + col] = pack_bf16(h2, h3);
        *(uint32_t*)&g_gol[(size_t)(rowA + 8) * DIM + col] = pack_bf16(v2 - h2, v3 - h3);
    }
}

// ===========================================================================
// Launch
// ===========================================================================
extern "C" void kernel_launch(void* const* d_in, const int* in_sizes, int n_in,
                              void* d_out, int out_size) {
    const float* x1 = (const float*)d_in[0];
    const float* x2 = (const float*)d_in[1];
    const float* wq = (const float*)d_in[2];
    const float* wk = (const float*)d_in[3];
    const float* wv = (const float*)d_in[4];
    const float* wo = (const float*)d_in[5];
    const float* bo = (const float*)d_in[6];
    float* out = (float*)d_out;

    const int NX = MROWS * DIM;
    const int NW = DIM * DIM;

    cudaFuncSetAttribute(gemm_mma,
                         cudaFuncAttributeMaxDynamicSharedMemorySize,
                         GEMM_SMEM_BYTES);

    split_kernel<<<1024, 256>>>(x1, BF_X1H, BF_X1L, NX);
    split_kernel<<<1024, 256>>>(x2, BF_X2H, BF_X2L, NX);
    split_kernel<<<512, 256>>>(wq, BF_WQH, BF_WQL, NW);
    split_kernel<<<512, 256>>>(wk, BF_WKH, BF_WKL, NW);
    split_kernel<<<512, 256>>>(wv, BF_WVH, BF_WVL, NW);
    split_kernel<<<512, 256>>>(wo, BF_WOH, BF_WOL, NW);

    dim3 gg(GM_N / 128, GM_M / 128);  // (8, 32)
    gemm_mma<<<gg, 256, GEMM_SMEM_BYTES>>>(BF_X1H, BF_X1L, BF_WQH, BF_WQL,
                                           nullptr, BF_QH, BF_QL, nullptr);
    gemm_mma<<<gg, 256, GEMM_SMEM_BYTES>>>(BF_X2H, BF_X2L, BF_WKH, BF_WKL,
                                           nullptr, BF_KH, BF_KL, nullptr);
    gemm_mma<<<gg, 256, GEMM_SMEM_BYTES>>>(BF_X2H, BF_X2L, BF_WVH, BF_WVL,
                                           nullptr, BF_VH, BF_VL, nullptr);

    attn_mma<<<dim3(NSEQ / 128, B * HEADS), 256>>>();

    gemm_mma<<<gg, 256, GEMM_SMEM_BYTES>>>(BF_GOH, BF_GOL, BF_WOH, BF_WOL,
                                           out, -1, -1, bo);
}

// round 12
// speedup vs baseline: 3.0544x; 1.1358x over previous
#include <cuda_runtime.h>
#include <cuda_bf16.h>
#include <cstdint>
#include <math.h>

// Problem shapes (fixed)
#define B 2
#define NSEQ 2048
#define DIM 1024
#define HEADS 16
#define HDIM 64
#define MROWS (B * NSEQ)   // 4096
#define ATT_SCALE 0.125f   // 64^-0.5

#define GM_M 4096
#define GM_N 1024
#define GM_K 1024

// ===========================================================================
// Scratch: bf16 hi/lo split arrays (device globals)
// ===========================================================================
__device__ __nv_bfloat16 g_x1h[MROWS * DIM];
__device__ __nv_bfloat16 g_x1l[MROWS * DIM];
__device__ __nv_bfloat16 g_x2h[MROWS * DIM];
__device__ __nv_bfloat16 g_x2l[MROWS * DIM];
__device__ __nv_bfloat16 g_wqh[DIM * DIM];
__device__ __nv_bfloat16 g_wql[DIM * DIM];
__device__ __nv_bfloat16 g_wkh[DIM * DIM];
__device__ __nv_bfloat16 g_wkl[DIM * DIM];
__device__ __nv_bfloat16 g_wvh[DIM * DIM];
__device__ __nv_bfloat16 g_wvl[DIM * DIM];
__device__ __nv_bfloat16 g_woh[DIM * DIM];
__device__ __nv_bfloat16 g_wol[DIM * DIM];
__device__ __nv_bfloat16 g_qh[MROWS * DIM];
__device__ __nv_bfloat16 g_ql[MROWS * DIM];
__device__ __nv_bfloat16 g_kh[MROWS * DIM];
__device__ __nv_bfloat16 g_kl[MROWS * DIM];
__device__ __nv_bfloat16 g_vh[MROWS * DIM];
__device__ __nv_bfloat16 g_vl[MROWS * DIM];
__device__ __nv_bfloat16 g_goh[MROWS * DIM];
__device__ __nv_bfloat16 g_gol[MROWS * DIM];

#define BF_X1H 0
#define BF_X1L 1
#define BF_X2H 2
#define BF_X2L 3
#define BF_WQH 4
#define BF_WQL 5
#define BF_WKH 6
#define BF_WKL 7
#define BF_WVH 8
#define BF_WVL 9
#define BF_WOH 10
#define BF_WOL 11
#define BF_QH 12
#define BF_QL 13
#define BF_KH 14
#define BF_KL 15
#define BF_VH 16
#define BF_VL 17
#define BF_GOH 18
#define BF_GOL 19
__device__ __nv_bfloat16* const g_bf[20] = {
    g_x1h, g_x1l, g_x2h, g_x2l,
    g_wqh, g_wql, g_wkh, g_wkl, g_wvh, g_wvl, g_woh, g_wol,
    g_qh, g_ql, g_kh, g_kl, g_vh, g_vl, g_goh, g_gol
};

// ===========================================================================
// Helpers
// ===========================================================================
__device__ __forceinline__ uint32_t pack_bf16(float x, float y) {
    __nv_bfloat162 v = __floats2bfloat162_rn(x, y);   // .x = low = x
    return *(uint32_t*)&v;
}

__device__ __forceinline__ void mma_bf16(float* c, const uint32_t* a,
                                         const uint32_t* b) {
    asm volatile(
        "mma.sync.aligned.m16n8k16.row.col.f32.bf16.bf16.f32 "
        "{%0,%1,%2,%3}, {%4,%5,%6,%7}, {%8,%9}, {%0,%1,%2,%3};"
        : "+f"(c[0]), "+f"(c[1]), "+f"(c[2]), "+f"(c[3])
        : "r"(a[0]), "r"(a[1]), "r"(a[2]), "r"(a[3]),
          "r"(b[0]), "r"(b[1]));
}

__device__ __forceinline__ void cp16(void* smem_dst, const void* gsrc) {
    uint32_t d = (uint32_t)__cvta_generic_to_shared(smem_dst);
    asm volatile("cp.async.cg.shared.global [%0], [%1], 16;"
                 :: "r"(d), "l"(gsrc));
}
#define CP_COMMIT() asm volatile("cp.async.commit_group;" ::: "memory")
#define CP_WAIT(n)  asm volatile("cp.async.wait_group %0;" :: "n"(n) : "memory")

__device__ __forceinline__ uint32_t smem_u32(const void* p) {
    return (uint32_t)__cvta_generic_to_shared(p);
}
__device__ __forceinline__ void ldm_x4(uint32_t* r, uint32_t addr) {
    asm volatile("ldmatrix.sync.aligned.m8n8.x4.shared.b16 {%0,%1,%2,%3}, [%4];"
                 : "=r"(r[0]), "=r"(r[1]), "=r"(r[2]), "=r"(r[3]) : "r"(addr));
}
__device__ __forceinline__ void ldm_x4_t(uint32_t* r, uint32_t addr) {
    asm volatile("ldmatrix.sync.aligned.m8n8.x4.trans.shared.b16 {%0,%1,%2,%3}, [%4];"
                 : "=r"(r[0]), "=r"(r[1]), "=r"(r[2]), "=r"(r[3]) : "r"(addr));
}

// ===========================================================================
// fp32 -> (bf16 hi, bf16 lo) split (external inputs only)
// ===========================================================================
__global__ void split_kernel(const float* __restrict__ src,
                             int hiIdx, int loIdx, int n) {
    __nv_bfloat16* hi = g_bf[hiIdx];
    __nv_bfloat16* lo = g_bf[loIdx];
    for (int i = blockIdx.x * blockDim.x + threadIdx.x; i < n;
         i += gridDim.x * blockDim.x) {
        float x = src[i];
        __nv_bfloat16 h = __float2bfloat16_rn(x);
        float r = x - __bfloat162float(h);
        hi[i] = h;
        lo[i] = __float2bfloat16_rn(r);
    }
}

// ===========================================================================
// Split-bf16 tensor-core GEMM: C = A * Bw^T (+bias), C = Ah*Bh+Ah*Bl+Al*Bh.
// Two-stage cp.async pipeline, K chunk 64 (halved sync cadence vs BKC=32).
// Fragments via ldmatrix.x4. APAD=72 -> 144B row stride (16B multiple,
// conflict-free 8-row ldmatrix phases).
// Epilogue: hiIdx>=0 -> write split bf16 (hi,lo); else fp32 + bias to Cext.
// ===========================================================================
#define BKC 64
#define APAD 72
#define GTILE (128 * APAD)            // elems per tile
#define GSTAGE (4 * GTILE)            // elems per stage (Ah,Al,Bh,Bl)
#define GEMM_SMEM_BYTES (2 * GSTAGE * 2)  // 147456 B
#define NCHUNK (GM_K / BKC)           // 16

__global__ __launch_bounds__(256, 1)
void gemm_mma(int ahIdx, int alIdx, int bhIdx, int blIdx,
              float* __restrict__ Cext, int hiIdx, int loIdx,
              const float* __restrict__ bias) {
    extern __shared__ __align__(16) __nv_bfloat16 dyn[];

    const int t   = threadIdx.x;
    const int wid = t >> 5;
    const int lid = t & 31;
    const int wm  = wid >> 2;
    const int wn  = wid & 3;
    const int n0  = blockIdx.x * 128;
    const int m0  = blockIdx.y * 128;
    const int qr  = lid >> 2;
    const int qc  = (lid & 3) * 2;

    // ldmatrix lane offsets
    const int a_ro = (lid & 7) + (lid & 8);         // A: row offset
    const int a_co = (lid & 16) >> 1;               // A: col offset (0 or 8)
    const int b_ro = (lid & 7) + ((lid & 16) >> 1); // B: n-row offset
    const int b_co = (lid & 8);                     // B: k-col offset (0 or 8)

    const __nv_bfloat16* pAh = g_bf[ahIdx] + (size_t)m0 * GM_K;
    const __nv_bfloat16* pAl = g_bf[alIdx] + (size_t)m0 * GM_K;
    const __nv_bfloat16* pBh = g_bf[bhIdx] + (size_t)n0 * GM_K;
    const __nv_bfloat16* pBl = g_bf[blIdx] + (size_t)n0 * GM_K;

    float acc[4][4][4];
    #pragma unroll
    for (int i = 0; i < 4; i++)
        #pragma unroll
        for (int j = 0; j < 4; j++)
            #pragma unroll
            for (int q = 0; q < 4; q++) acc[i][j][q] = 0.f;

    // stage loader: 128x64 tiles -> 1024 int4 units / 256 thr = 4 per array
    auto load_stage = [&](int stage, int k0) {
        __nv_bfloat16* s = dyn + stage * GSTAGE;
        #pragma unroll
        for (int i = 0; i < 4; i++) {
            int unit = t + i * 256;
            int r  = unit >> 3;
            int c8 = (unit & 7) * 8;
            size_t g = (size_t)r * GM_K + k0 + c8;
            int so = r * APAD + c8;
            cp16(&s[0 * GTILE + so], pAh + g);
            cp16(&s[1 * GTILE + so], pAl + g);
            cp16(&s[2 * GTILE + so], pBh + g);
            cp16(&s[3 * GTILE + so], pBl + g);
        }
    };

    load_stage(0, 0);
    CP_COMMIT();

    for (int c = 0; c < NCHUNK; c++) {
        if (c + 1 < NCHUNK) {
            load_stage((c + 1) & 1, (c + 1) * BKC);
            CP_COMMIT();
            CP_WAIT(1);
        } else {
            CP_WAIT(0);
        }
        __syncthreads();

        const __nv_bfloat16* Ahs = dyn + (c & 1) * GSTAGE + 0 * GTILE;
        const __nv_bfloat16* Als = dyn + (c & 1) * GSTAGE + 1 * GTILE;
        const __nv_bfloat16* Bhs = dyn + (c & 1) * GSTAGE + 2 * GTILE;
        const __nv_bfloat16* Bls = dyn + (c & 1) * GSTAGE + 3 * GTILE;

        #pragma unroll
        for (int ks = 0; ks < 4; ks++) {
            const int kk = ks * 16;
            uint32_t ah[4][4], al[4][4];
            #pragma unroll
            for (int mf = 0; mf < 4; mf++) {
                int r = wm * 64 + mf * 16 + a_ro;
                ldm_x4(ah[mf], smem_u32(&Ahs[r * APAD + kk + a_co]));
                ldm_x4(al[mf], smem_u32(&Als[r * APAD + kk + a_co]));
            }
            uint32_t bh[4][2], bl[4][2];
            #pragma unroll
            for (int nfp = 0; nfp < 2; nfp++) {
                int cc = wn * 32 + nfp * 16 + b_ro;
                uint32_t b4h[4], b4l[4];
                ldm_x4(b4h, smem_u32(&Bhs[cc * APAD + kk + b_co]));
                ldm_x4(b4l, smem_u32(&Bls[cc * APAD + kk + b_co]));
                bh[2*nfp][0] = b4h[0]; bh[2*nfp][1] = b4h[1];
                bh[2*nfp+1][0] = b4h[2]; bh[2*nfp+1][1] = b4h[3];
                bl[2*nfp][0] = b4l[0]; bl[2*nfp][1] = b4l[1];
                bl[2*nfp+1][0] = b4l[2]; bl[2*nfp+1][1] = b4l[3];
            }
            #pragma unroll
            for (int mf = 0; mf < 4; mf++)
                #pragma unroll
                for (int nf = 0; nf < 4; nf++) {
                    mma_bf16(acc[mf][nf], ah[mf], bh[nf]);
                    mma_bf16(acc[mf][nf], ah[mf], bl[nf]);
                    mma_bf16(acc[mf][nf], al[mf], bh[nf]);
                }
        }
        __syncthreads();
    }

    if (hiIdx >= 0) {
        __nv_bfloat16* Ch = g_bf[hiIdx];
        __nv_bfloat16* Cl = g_bf[loIdx];
        #pragma unroll
        for (int mf = 0; mf < 4; mf++) {
            int row = m0 + wm * 64 + mf * 16 + qr;
            #pragma unroll
            for (int nf = 0; nf < 4; nf++) {
                int col = n0 + wn * 32 + nf * 8 + qc;
                #pragma unroll
                for (int half = 0; half < 2; half++) {
                    int r = row + half * 8;
                    float v0 = acc[mf][nf][half * 2 + 0];
                    float v1 = acc[mf][nf][half * 2 + 1];
                    float h0 = __bfloat162float(__float2bfloat16_rn(v0));
                    float h1 = __bfloat162float(__float2bfloat16_rn(v1));
                    *(uint32_t*)&Ch[(size_t)r * GM_N + col] = pack_bf16(h0, h1);
                    *(uint32_t*)&Cl[(size_t)r * GM_N + col] =
                        pack_bf16(v0 - h0, v1 - h1);
                }
            }
        }
    } else {
        #pragma unroll
        for (int mf = 0; mf < 4; mf++) {
            int row = m0 + wm * 64 + mf * 16 + qr;
            #pragma unroll
            for (int nf = 0; nf < 4; nf++) {
                int col = n0 + wn * 32 + nf * 8 + qc;
                float b0 = bias ? bias[col] : 0.f;
                float b1 = bias ? bias[col + 1] : 0.f;
                float2 v0 = make_float2(acc[mf][nf][0] + b0, acc[mf][nf][1] + b1);
                float2 v1 = make_float2(acc[mf][nf][2] + b0, acc[mf][nf][3] + b1);
                *(float2*)(Cext + (size_t)row * GM_N + col) = v0;
                *(float2*)(Cext + (size_t)(row + 8) * GM_N + col) = v1;
            }
        }
    }
}

// ===========================================================================
// Flash attention via mma.sync, split-bf16, two-stage cp.async KV pipeline.
// Block: 256 threads = 8 warps; warp w owns query rows [16w, 16w+16) of a
// 128-row q tile. KV tile 64 raw [kv][d]; K frags via ldmatrix.x4,
// V via ldmatrix.x4.trans. Online softmax in registers.
// Dynamic smem: 2 stages x (Kh,Kl,Vh,Vl) of 64x72 bf16 = 73728 B.
// ===========================================================================
#define AKT 64
#define KPAD 72
#define ATILE (AKT * KPAD)            // 4608 elems
#define ASTAGE (4 * ATILE)            // per stage
#define ATTN_SMEM_BYTES (2 * ASTAGE * 2)  // 73728 B
#define NKT (NSEQ / AKT)              // 32

__global__ __launch_bounds__(256, 1)
void attn_mma() {
    extern __shared__ __align__(16) __nv_bfloat16 adyn[];

    const int t   = threadIdx.x;
    const int wid = t >> 5;            // 0..7
    const int lid = t & 31;
    const int gr  = lid >> 2;          // 0..7
    const int qc  = (lid & 3) * 2;     // 0,2,4,6
    const int qt  = blockIdx.x;        // 0..15
    const int bh  = blockIdx.y;        // 0..31
    const int b   = bh >> 4;
    const int h   = bh & 15;
    const int n0  = qt * 128;
    const int row0 = n0 + wid * 16;

    // ldmatrix lane offsets
    const int kb_ro = (lid & 7) + ((lid & 16) >> 1); // K: n(kv)-row offset
    const int kb_co = (lid & 8);                     // K: k(d)-col offset
    const int vb_ro = (lid & 7) + (lid & 8);         // V: kv-row offset
    const int vb_co = (lid & 16) >> 1;               // V: d-col offset

    const size_t batch_off = (size_t)b * NSEQ * DIM + (size_t)h * HDIM;
    const __nv_bfloat16* Qh = g_qh + batch_off;
    const __nv_bfloat16* Ql = g_ql + batch_off;
    const __nv_bfloat16* Kh = g_kh + batch_off;
    const __nv_bfloat16* Kl = g_kl + batch_off;
    const __nv_bfloat16* Vh = g_vh + batch_off;
    const __nv_bfloat16* Vl = g_vl + batch_off;

    // Q fragments in registers: [kf][4], hi and lo
    uint32_t qfh[4][4], qfl[4][4];
    {
        const int rA = row0 + gr;
        const int rB = rA + 8;
        #pragma unroll
        for (int kf = 0; kf < 4; kf++) {
            int c = kf * 16 + qc;
            qfh[kf][0] = *(const uint32_t*)&Qh[(size_t)rA * DIM + c];
            qfh[kf][1] = *(const uint32_t*)&Qh[(size_t)rB * DIM + c];
            qfh[kf][2] = *(const uint32_t*)&Qh[(size_t)rA * DIM + c + 8];
            qfh[kf][3] = *(const uint32_t*)&Qh[(size_t)rB * DIM + c + 8];
            qfl[kf][0] = *(const uint32_t*)&Ql[(size_t)rA * DIM + c];
            qfl[kf][1] = *(const uint32_t*)&Ql[(size_t)rB * DIM + c];
            qfl[kf][2] = *(const uint32_t*)&Ql[(size_t)rA * DIM + c + 8];
            qfl[kf][3] = *(const uint32_t*)&Ql[(size_t)rB * DIM + c + 8];
        }
    }

    // KV stage loader: 512 int4 units per array / 256 threads = 2 each
    auto load_kv = [&](int stage, int kv0) {
        __nv_bfloat16* s = adyn + stage * ASTAGE;
        #pragma unroll
        for (int i = 0; i < 2; i++) {
            int unit = t + i * 256;
            int r  = unit >> 3;
            int c8 = (unit & 7) * 8;
            size_t goff = (size_t)(kv0 + r) * DIM + c8;
            int so = r * KPAD + c8;
            cp16(&s[0 * ATILE + so], Kh + goff);
            cp16(&s[1 * ATILE + so], Kl + goff);
            cp16(&s[2 * ATILE + so], Vh + goff);
            cp16(&s[3 * ATILE + so], Vl + goff);
        }
    };

    float om0 = -1e30f, om1 = -1e30f;
    float osum0 = 0.f, osum1 = 0.f;
    float o[8][4];
    #pragma unroll
    for (int nf = 0; nf < 8; nf++)
        #pragma unroll
        for (int q = 0; q < 4; q++) o[nf][q] = 0.f;

    load_kv(0, 0);
    CP_COMMIT();

    for (int kt = 0; kt < NKT; kt++) {
        if (kt + 1 < NKT) {
            load_kv((kt + 1) & 1, (kt + 1) * AKT);
            CP_COMMIT();
            CP_WAIT(1);
        } else {
            CP_WAIT(0);
        }
        __syncthreads();

        const __nv_bfloat16* Khs = adyn + (kt & 1) * ASTAGE + 0 * ATILE;
        const __nv_bfloat16* Kls = adyn + (kt & 1) * ASTAGE + 1 * ATILE;
        const __nv_bfloat16* Vhs = adyn + (kt & 1) * ASTAGE + 2 * ATILE;
        const __nv_bfloat16* Vls = adyn + (kt & 1) * ASTAGE + 3 * ATILE;

        // S = Q K^T (split 3-product); K frags via ldmatrix.x4
        float s[8][4];
        #pragma unroll
        for (int nf = 0; nf < 8; nf++)
            #pragma unroll
            for (int q = 0; q < 4; q++) s[nf][q] = 0.f;
        #pragma unroll
        for (int kf = 0; kf < 4; kf++) {
            const int kk = kf * 16;
            #pragma unroll
            for (int nfp = 0; nfp < 4; nfp++) {
                uint32_t b4h[4], b4l[4];
                int cc = nfp * 16 + kb_ro;
                ldm_x4(b4h, smem_u32(&Khs[cc * KPAD + kk + kb_co]));
                ldm_x4(b4l, smem_u32(&Kls[cc * KPAD + kk + kb_co]));
                mma_bf16(s[2*nfp    ], qfh[kf], b4h + 0);
                mma_bf16(s[2*nfp    ], qfh[kf], b4l + 0);
                mma_bf16(s[2*nfp    ], qfl[kf], b4h + 0);
                mma_bf16(s[2*nfp + 1], qfh[kf], b4h + 2);
                mma_bf16(s[2*nfp + 1], qfh[kf], b4l + 2);
                mma_bf16(s[2*nfp + 1], qfl[kf], b4h + 2);
            }
        }

        // Online softmax. Row gr -> c0,c1; row gr+8 -> c2,c3.
        float tmax0 = -1e30f, tmax1 = -1e30f;
        #pragma unroll
        for (int nf = 0; nf < 8; nf++) {
            tmax0 = fmaxf(tmax0, fmaxf(s[nf][0], s[nf][1]));
            tmax1 = fmaxf(tmax1, fmaxf(s[nf][2], s[nf][3]));
        }
        tmax0 = fmaxf(tmax0, __shfl_xor_sync(0xffffffff, tmax0, 1));
        tmax0 = fmaxf(tmax0, __shfl_xor_sync(0xffffffff, tmax0, 2));
        tmax1 = fmaxf(tmax1, __shfl_xor_sync(0xffffffff, tmax1, 1));
        tmax1 = fmaxf(tmax1, __shfl_xor_sync(0xffffffff, tmax1, 2));

        float mn0 = fmaxf(om0, tmax0);
        float mn1 = fmaxf(om1, tmax1);
        float alpha0 = __expf((om0 - mn0) * ATT_SCALE);
        float alpha1 = __expf((om1 - mn1) * ATT_SCALE);
        om0 = mn0; om1 = mn1;

        uint32_t ph0[8], ph1[8], pl0[8], pl1[8];
        float lsum0 = 0.f, lsum1 = 0.f;
        #pragma unroll
        for (int nf = 0; nf < 8; nf++) {
            float p0 = __expf((s[nf][0] - mn0) * ATT_SCALE);
            float p1 = __expf((s[nf][1] - mn0) * ATT_SCALE);
            float p2 = __expf((s[nf][2] - mn1) * ATT_SCALE);
            float p3 = __expf((s[nf][3] - mn1) * ATT_SCALE);
            lsum0 += p0 + p1;
            lsum1 += p2 + p3;
            float h0 = __bfloat162float(__float2bfloat16_rn(p0));
            float h1 = __bfloat162float(__float2bfloat16_rn(p1));
            float h2 = __bfloat162float(__float2bfloat16_rn(p2));
            float h3 = __bfloat162float(__float2bfloat16_rn(p3));
            ph0[nf] = pack_bf16(h0, h1);
            ph1[nf] = pack_bf16(h2, h3);
            pl0[nf] = pack_bf16(p0 - h0, p1 - h1);
            pl1[nf] = pack_bf16(p2 - h2, p3 - h3);
        }
        lsum0 += __shfl_xor_sync(0xffffffff, lsum0, 1);
        lsum0 += __shfl_xor_sync(0xffffffff, lsum0, 2);
        lsum1 += __shfl_xor_sync(0xffffffff, lsum1, 1);
        lsum1 += __shfl_xor_sync(0xffffffff, lsum1, 2);
        osum0 = osum0 * alpha0 + lsum0;
        osum1 = osum1 * alpha1 + lsum1;

        #pragma unroll
        for (int nf = 0; nf < 8; nf++) {
            o[nf][0] *= alpha0; o[nf][1] *= alpha0;
            o[nf][2] *= alpha1; o[nf][3] *= alpha1;
        }

        // O += P V (split 3-product); V frags via ldmatrix.x4.trans
        #pragma unroll
        for (int kf = 0; kf < 4; kf++) {
            uint32_t pah[4] = {ph0[2*kf], ph1[2*kf], ph0[2*kf+1], ph1[2*kf+1]};
            uint32_t pal[4] = {pl0[2*kf], pl1[2*kf], pl0[2*kf+1], pl1[2*kf+1]};
            const int kk = kf * 16;
            #pragma unroll
            for (int nfp = 0; nfp < 4; nfp++) {
                uint32_t b4h[4], b4l[4];
                int rr = kk + vb_ro;
                int cc = nfp * 16 + vb_co;
                ldm_x4_t(b4h, smem_u32(&Vhs[rr * KPAD + cc]));
                ldm_x4_t(b4l, smem_u32(&Vls[rr * KPAD + cc]));
                mma_bf16(o[2*nfp    ], pah, b4h + 0);
                mma_bf16(o[2*nfp    ], pah, b4l + 0);
                mma_bf16(o[2*nfp    ], pal, b4h + 0);
                mma_bf16(o[2*nfp + 1], pah, b4h + 2);
                mma_bf16(o[2*nfp + 1], pah, b4l + 2);
                mma_bf16(o[2*nfp + 1], pal, b4h + 2);
            }
        }
        __syncthreads();
    }

    // Epilogue: normalize, split, store to g_goh/g_gol
    const float inv0 = 1.0f / osum0;
    const float inv1 = 1.0f / osum1;
    const int rowA = b * NSEQ + row0 + gr;
    #pragma unroll
    for (int nf = 0; nf < 8; nf++) {
        int col = h * HDIM + nf * 8 + qc;
        float v0 = o[nf][0] * inv0;
        float v1 = o[nf][1] * inv0;
        float v2 = o[nf][2] * inv1;
        float v3 = o[nf][3] * inv1;
        float h0 = __bfloat162float(__float2bfloat16_rn(v0));
        float h1 = __bfloat162float(__float2bfloat16_rn(v1));
        float h2 = __bfloat162float(__float2bfloat16_rn(v2));
        float h3 = __bfloat162float(__float2bfloat16_rn(v3));
        *(uint32_t*)&g_goh[(size_t)rowA * DIM + col] = pack_bf16(h0, h1);
        *(uint32_t*)&g_gol[(size_t)rowA * DIM + col] = pack_bf16(v0 - h0, v1 - h1);
        *(uint32_t*)&g_goh[(size_t)(rowA + 8) * DIM + col] = pack_bf16(h2, h3);
        *(uint32_t*)&g_gol[(size_t)(rowA + 8) * DIM + col] = pack_bf16(v2 - h2, v3 - h3);
    }
}

// ===========================================================================
// Launch
// ===========================================================================
extern "C" void kernel_launch(void* const* d_in, const int* in_sizes, int n_in,
                              void* d_out, int out_size) {
    const float* x1 = (const float*)d_in[0];
    const float* x2 = (const float*)d_in[1];
    const float* wq = (const float*)d_in[2];
    const float* wk = (const float*)d_in[3];
    const float* wv = (const float*)d_in[4];
    const float* wo = (const float*)d_in[5];
    const float* bo = (const float*)d_in[6];
    float* out = (float*)d_out;

    const int NX = MROWS * DIM;
    const int NW = DIM * DIM;

    cudaFuncSetAttribute(gemm_mma,
                         cudaFuncAttributeMaxDynamicSharedMemorySize,
                         GEMM_SMEM_BYTES);
    cudaFuncSetAttribute(attn_mma,
                         cudaFuncAttributeMaxDynamicSharedMemorySize,
                         ATTN_SMEM_BYTES);

    split_kernel<<<1024, 256>>>(x1, BF_X1H, BF_X1L, NX);
    split_kernel<<<1024, 256>>>(x2, BF_X2H, BF_X2L, NX);
    split_kernel<<<512, 256>>>(wq, BF_WQH, BF_WQL, NW);
    split_kernel<<<512, 256>>>(wk, BF_WKH, BF_WKL, NW);
    split_kernel<<<512, 256>>>(wv, BF_WVH, BF_WVL, NW);
    split_kernel<<<512, 256>>>(wo, BF_WOH, BF_WOL, NW);

    dim3 gg(GM_N / 128, GM_M / 128);  // (8, 32)
    gemm_mma<<<gg, 256, GEMM_SMEM_BYTES>>>(BF_X1H, BF_X1L, BF_WQH, BF_WQL,
                                           nullptr, BF_QH, BF_QL, nullptr);
    gemm_mma<<<gg, 256, GEMM_SMEM_BYTES>>>(BF_X2H, BF_X2L, BF_WKH, BF_WKL,
                                           nullptr, BF_KH, BF_KL, nullptr);
    gemm_mma<<<gg, 256, GEMM_SMEM_BYTES>>>(BF_X2H, BF_X2L, BF_WVH, BF_WVL,
                                           nullptr, BF_VH, BF_VL, nullptr);

    attn_mma<<<dim3(NSEQ / 128, B * HEADS), 256, ATTN_SMEM_BYTES>>>();

    gemm_mma<<<gg, 256, GEMM_SMEM_BYTES>>>(BF_GOH, BF_GOL, BF_WOH, BF_WOL,
                                           out, -1, -1, bo);
}

// round 13
// speedup vs baseline: 3.1138x; 1.0194x over previous
#include <cuda_runtime.h>
#include <cuda_bf16.h>
#include <cstdint>
#include <math.h>

// Problem shapes (fixed)
#define B 2
#define NSEQ 2048
#define DIM 1024
#define HEADS 16
#define HDIM 64
#define MROWS (B * NSEQ)   // 4096
#define ATT_SCALE 0.125f   // 64^-0.5

#define GM_M 4096
#define GM_N 1024
#define GM_K 1024

// ===========================================================================
// Scratch: bf16 hi/lo split arrays (device globals)
// ===========================================================================
__device__ __nv_bfloat16 g_x1h[MROWS * DIM];
__device__ __nv_bfloat16 g_x1l[MROWS * DIM];
__device__ __nv_bfloat16 g_x2h[MROWS * DIM];
__device__ __nv_bfloat16 g_x2l[MROWS * DIM];
__device__ __nv_bfloat16 g_wqh[DIM * DIM];
__device__ __nv_bfloat16 g_wql[DIM * DIM];
__device__ __nv_bfloat16 g_wkh[DIM * DIM];
__device__ __nv_bfloat16 g_wkl[DIM * DIM];
__device__ __nv_bfloat16 g_wvh[DIM * DIM];
__device__ __nv_bfloat16 g_wvl[DIM * DIM];
__device__ __nv_bfloat16 g_woh[DIM * DIM];
__device__ __nv_bfloat16 g_wol[DIM * DIM];
__device__ __nv_bfloat16 g_qh[MROWS * DIM];
__device__ __nv_bfloat16 g_ql[MROWS * DIM];
__device__ __nv_bfloat16 g_kh[MROWS * DIM];
__device__ __nv_bfloat16 g_kl[MROWS * DIM];
__device__ __nv_bfloat16 g_vh[MROWS * DIM];
__device__ __nv_bfloat16 g_vl[MROWS * DIM];
__device__ __nv_bfloat16 g_goh[MROWS * DIM];
__device__ __nv_bfloat16 g_gol[MROWS * DIM];

#define BF_X1H 0
#define BF_X1L 1
#define BF_X2H 2
#define BF_X2L 3
#define BF_WQH 4
#define BF_WQL 5
#define BF_WKH 6
#define BF_WKL 7
#define BF_WVH 8
#define BF_WVL 9
#define BF_WOH 10
#define BF_WOL 11
#define BF_QH 12
#define BF_QL 13
#define BF_KH 14
#define BF_KL 15
#define BF_VH 16
#define BF_VL 17
#define BF_GOH 18
#define BF_GOL 19
__device__ __nv_bfloat16* const g_bf[20] = {
    g_x1h, g_x1l, g_x2h, g_x2l,
    g_wqh, g_wql, g_wkh, g_wkl, g_wvh, g_wvl, g_woh, g_wol,
    g_qh, g_ql, g_kh, g_kl, g_vh, g_vl, g_goh, g_gol
};

// ===========================================================================
// Helpers
// ===========================================================================
__device__ __forceinline__ uint32_t pack_bf16(float x, float y) {
    __nv_bfloat162 v = __floats2bfloat162_rn(x, y);   // .x = low = x
    return *(uint32_t*)&v;
}

__device__ __forceinline__ void mma_bf16(float* c, const uint32_t* a,
                                         const uint32_t* b) {
    asm volatile(
        "mma.sync.aligned.m16n8k16.row.col.f32.bf16.bf16.f32 "
        "{%0,%1,%2,%3}, {%4,%5,%6,%7}, {%8,%9}, {%0,%1,%2,%3};"
        : "+f"(c[0]), "+f"(c[1]), "+f"(c[2]), "+f"(c[3])
        : "r"(a[0]), "r"(a[1]), "r"(a[2]), "r"(a[3]),
          "r"(b[0]), "r"(b[1]));
}

__device__ __forceinline__ void cp16(void* smem_dst, const void* gsrc) {
    uint32_t d = (uint32_t)__cvta_generic_to_shared(smem_dst);
    asm volatile("cp.async.cg.shared.global [%0], [%1], 16;"
                 :: "r"(d), "l"(gsrc));
}
#define CP_COMMIT() asm volatile("cp.async.commit_group;" ::: "memory")
#define CP_WAIT(n)  asm volatile("cp.async.wait_group %0;" :: "n"(n) : "memory")

__device__ __forceinline__ uint32_t smem_u32(const void* p) {
    return (uint32_t)__cvta_generic_to_shared(p);
}
__device__ __forceinline__ void ldm_x4(uint32_t* r, uint32_t addr) {
    asm volatile("ldmatrix.sync.aligned.m8n8.x4.shared.b16 {%0,%1,%2,%3}, [%4];"
                 : "=r"(r[0]), "=r"(r[1]), "=r"(r[2]), "=r"(r[3]) : "r"(addr));
}
__device__ __forceinline__ void ldm_x4_t(uint32_t* r, uint32_t addr) {
    asm volatile("ldmatrix.sync.aligned.m8n8.x4.trans.shared.b16 {%0,%1,%2,%3}, [%4];"
                 : "=r"(r[0]), "=r"(r[1]), "=r"(r[2]), "=r"(r[3]) : "r"(addr));
}

// ===========================================================================
// fp32 -> (bf16 hi, bf16 lo) splits, fused launches.
// split2: two activation tensors (blockIdx.y selects).
// split4: four weight tensors (blockIdx.y selects).
// ===========================================================================
__global__ void split2_kernel(const float* __restrict__ s0,
                              const float* __restrict__ s1, int n) {
    const float* src = (blockIdx.y == 0) ? s0 : s1;
    __nv_bfloat16* hi = (blockIdx.y == 0) ? g_x1h : g_x2h;
    __nv_bfloat16* lo = (blockIdx.y == 0) ? g_x1l : g_x2l;
    for (int i = blockIdx.x * blockDim.x + threadIdx.x; i < n;
         i += gridDim.x * blockDim.x) {
        float x = src[i];
        __nv_bfloat16 h = __float2bfloat16_rn(x);
        hi[i] = h;
        lo[i] = __float2bfloat16_rn(x - __bfloat162float(h));
    }
}

__global__ void split4_kernel(const float* __restrict__ s0,
                              const float* __restrict__ s1,
                              const float* __restrict__ s2,
                              const float* __restrict__ s3, int n) {
    int w = blockIdx.y;
    const float* src = (w == 0) ? s0 : (w == 1) ? s1 : (w == 2) ? s2 : s3;
    __nv_bfloat16* hi = g_bf[BF_WQH + 2 * w];
    __nv_bfloat16* lo = g_bf[BF_WQL + 2 * w];
    for (int i = blockIdx.x * blockDim.x + threadIdx.x; i < n;
         i += gridDim.x * blockDim.x) {
        float x = src[i];
        __nv_bfloat16 h = __float2bfloat16_rn(x);
        hi[i] = h;
        lo[i] = __float2bfloat16_rn(x - __bfloat162float(h));
    }
}

// ===========================================================================
// Split-bf16 tensor-core GEMM: C = A * Bw^T (+bias), C = Ah*Bh+Ah*Bl+Al*Bh.
// Two-stage cp.async pipeline, K chunk 64. Fragments via ldmatrix.x4.
// MMA issued in 3 product passes (hh, hl, lh) over all 16 accumulators:
// reuse distance 16 hides HMMA RAW latency; per-acc add order unchanged.
// ===========================================================================
#define BKC 64
#define APAD 72
#define GTILE (128 * APAD)
#define GSTAGE (4 * GTILE)
#define GEMM_SMEM_BYTES (2 * GSTAGE * 2)  // 147456 B
#define NCHUNK (GM_K / BKC)               // 16

__global__ __launch_bounds__(256, 1)
void gemm_mma(int ahIdx, int alIdx, int bhIdx, int blIdx,
              float* __restrict__ Cext, int hiIdx, int loIdx,
              const float* __restrict__ bias) {
    extern __shared__ __align__(16) __nv_bfloat16 dyn[];

    const int t   = threadIdx.x;
    const int wid = t >> 5;
    const int lid = t & 31;
    const int wm  = wid >> 2;
    const int wn  = wid & 3;
    const int n0  = blockIdx.x * 128;
    const int m0  = blockIdx.y * 128;
    const int qr  = lid >> 2;
    const int qc  = (lid & 3) * 2;

    const int a_ro = (lid & 7) + (lid & 8);
    const int a_co = (lid & 16) >> 1;
    const int b_ro = (lid & 7) + ((lid & 16) >> 1);
    const int b_co = (lid & 8);

    const __nv_bfloat16* pAh = g_bf[ahIdx] + (size_t)m0 * GM_K;
    const __nv_bfloat16* pAl = g_bf[alIdx] + (size_t)m0 * GM_K;
    const __nv_bfloat16* pBh = g_bf[bhIdx] + (size_t)n0 * GM_K;
    const __nv_bfloat16* pBl = g_bf[blIdx] + (size_t)n0 * GM_K;

    float acc[4][4][4];
    #pragma unroll
    for (int i = 0; i < 4; i++)
        #pragma unroll
        for (int j = 0; j < 4; j++)
            #pragma unroll
            for (int q = 0; q < 4; q++) acc[i][j][q] = 0.f;

    auto load_stage = [&](int stage, int k0) {
        __nv_bfloat16* s = dyn + stage * GSTAGE;
        #pragma unroll
        for (int i = 0; i < 4; i++) {
            int unit = t + i * 256;
            int r  = unit >> 3;
            int c8 = (unit & 7) * 8;
            size_t g = (size_t)r * GM_K + k0 + c8;
            int so = r * APAD + c8;
            cp16(&s[0 * GTILE + so], pAh + g);
            cp16(&s[1 * GTILE + so], pAl + g);
            cp16(&s[2 * GTILE + so], pBh + g);
            cp16(&s[3 * GTILE + so], pBl + g);
        }
    };

    load_stage(0, 0);
    CP_COMMIT();

    for (int c = 0; c < NCHUNK; c++) {
        if (c + 1 < NCHUNK) {
            load_stage((c + 1) & 1, (c + 1) * BKC);
            CP_COMMIT();
            CP_WAIT(1);
        } else {
            CP_WAIT(0);
        }
        __syncthreads();

        const __nv_bfloat16* Ahs = dyn + (c & 1) * GSTAGE + 0 * GTILE;
        const __nv_bfloat16* Als = dyn + (c & 1) * GSTAGE + 1 * GTILE;
        const __nv_bfloat16* Bhs = dyn + (c & 1) * GSTAGE + 2 * GTILE;
        const __nv_bfloat16* Bls = dyn + (c & 1) * GSTAGE + 3 * GTILE;

        #pragma unroll
        for (int ks = 0; ks < 4; ks++) {
            const int kk = ks * 16;
            uint32_t ah[4][4], al[4][4];
            #pragma unroll
            for (int mf = 0; mf < 4; mf++) {
                int r = wm * 64 + mf * 16 + a_ro;
                ldm_x4(ah[mf], smem_u32(&Ahs[r * APAD + kk + a_co]));
                ldm_x4(al[mf], smem_u32(&Als[r * APAD + kk + a_co]));
            }
            uint32_t bh[4][2], bl[4][2];
            #pragma unroll
            for (int nfp = 0; nfp < 2; nfp++) {
                int cc = wn * 32 + nfp * 16 + b_ro;
                uint32_t b4h[4], b4l[4];
                ldm_x4(b4h, smem_u32(&Bhs[cc * APAD + kk + b_co]));
                ldm_x4(b4l, smem_u32(&Bls[cc * APAD + kk + b_co]));
                bh[2*nfp][0] = b4h[0]; bh[2*nfp][1] = b4h[1];
                bh[2*nfp+1][0] = b4h[2]; bh[2*nfp+1][1] = b4h[3];
                bl[2*nfp][0] = b4l[0]; bl[2*nfp][1] = b4l[1];
                bl[2*nfp+1][0] = b4l[2]; bl[2*nfp+1][1] = b4l[3];
            }
            // Product pass 1: hh over all 16 accumulators
            #pragma unroll
            for (int mf = 0; mf < 4; mf++)
                #pragma unroll
                for (int nf = 0; nf < 4; nf++)
                    mma_bf16(acc[mf][nf], ah[mf], bh[nf]);
            // Product pass 2: hl
            #pragma unroll
            for (int mf = 0; mf < 4; mf++)
                #pragma unroll
                for (int nf = 0; nf < 4; nf++)
                    mma_bf16(acc[mf][nf], ah[mf], bl[nf]);
            // Product pass 3: lh
            #pragma unroll
            for (int mf = 0; mf < 4; mf++)
                #pragma unroll
                for (int nf = 0; nf < 4; nf++)
                    mma_bf16(acc[mf][nf], al[mf], bh[nf]);
        }
        __syncthreads();
    }

    if (hiIdx >= 0) {
        __nv_bfloat16* Ch = g_bf[hiIdx];
        __nv_bfloat16* Cl = g_bf[loIdx];
        #pragma unroll
        for (int mf = 0; mf < 4; mf++) {
            int row = m0 + wm * 64 + mf * 16 + qr;
            #pragma unroll
            for (int nf = 0; nf < 4; nf++) {
                int col = n0 + wn * 32 + nf * 8 + qc;
                #pragma unroll
                for (int half = 0; half < 2; half++) {
                    int r = row + half * 8;
                    float v0 = acc[mf][nf][half * 2 + 0];
                    float v1 = acc[mf][nf][half * 2 + 1];
                    float h0 = __bfloat162float(__float2bfloat16_rn(v0));
                    float h1 = __bfloat162float(__float2bfloat16_rn(v1));
                    *(uint32_t*)&Ch[(size_t)r * GM_N + col] = pack_bf16(h0, h1);
                    *(uint32_t*)&Cl[(size_t)r * GM_N + col] =
                        pack_bf16(v0 - h0, v1 - h1);
                }
            }
        }
    } else {
        #pragma unroll
        for (int mf = 0; mf < 4; mf++) {
            int row = m0 + wm * 64 + mf * 16 + qr;
            #pragma unroll
            for (int nf = 0; nf < 4; nf++) {
                int col = n0 + wn * 32 + nf * 8 + qc;
                float b0 = bias ? bias[col] : 0.f;
                float b1 = bias ? bias[col + 1] : 0.f;
                float2 v0 = make_float2(acc[mf][nf][0] + b0, acc[mf][nf][1] + b1);
                float2 v1 = make_float2(acc[mf][nf][2] + b0, acc[mf][nf][3] + b1);
                *(float2*)(Cext + (size_t)row * GM_N + col) = v0;
                *(float2*)(Cext + (size_t)(row + 8) * GM_N + col) = v1;
            }
        }
    }
}

// ===========================================================================
// Flash attention via mma.sync, split-bf16, two-stage cp.async KV pipeline.
// MMA in 3 product passes over preloaded fragments (RAW hiding).
// Block: 256 threads = 8 warps; 128-row q tile; KV tile 64.
// ===========================================================================
#define AKT 64
#define KPAD 72
#define ATILE (AKT * KPAD)
#define ASTAGE (4 * ATILE)
#define ATTN_SMEM_BYTES (2 * ASTAGE * 2)  // 73728 B
#define NKT (NSEQ / AKT)                  // 32

__global__ __launch_bounds__(256, 1)
void attn_mma() {
    extern __shared__ __align__(16) __nv_bfloat16 adyn[];

    const int t   = threadIdx.x;
    const int wid = t >> 5;
    const int lid = t & 31;
    const int gr  = lid >> 2;
    const int qc  = (lid & 3) * 2;
    const int qt  = blockIdx.x;
    const int bh  = blockIdx.y;
    const int b   = bh >> 4;
    const int h   = bh & 15;
    const int n0  = qt * 128;
    const int row0 = n0 + wid * 16;

    const int kb_ro = (lid & 7) + ((lid & 16) >> 1);
    const int kb_co = (lid & 8);
    const int vb_ro = (lid & 7) + (lid & 8);
    const int vb_co = (lid & 16) >> 1;

    const size_t batch_off = (size_t)b * NSEQ * DIM + (size_t)h * HDIM;
    const __nv_bfloat16* Qh = g_qh + batch_off;
    const __nv_bfloat16* Ql = g_ql + batch_off;
    const __nv_bfloat16* Kh = g_kh + batch_off;
    const __nv_bfloat16* Kl = g_kl + batch_off;
    const __nv_bfloat16* Vh = g_vh + batch_off;
    const __nv_bfloat16* Vl = g_vl + batch_off;

    uint32_t qfh[4][4], qfl[4][4];
    {
        const int rA = row0 + gr;
        const int rB = rA + 8;
        #pragma unroll
        for (int kf = 0; kf < 4; kf++) {
            int c = kf * 16 + qc;
            qfh[kf][0] = *(const uint32_t*)&Qh[(size_t)rA * DIM + c];
            qfh[kf][1] = *(const uint32_t*)&Qh[(size_t)rB * DIM + c];
            qfh[kf][2] = *(const uint32_t*)&Qh[(size_t)rA * DIM + c + 8];
            qfh[kf][3] = *(const uint32_t*)&Qh[(size_t)rB * DIM + c + 8];
            qfl[kf][0] = *(const uint32_t*)&Ql[(size_t)rA * DIM + c];
            qfl[kf][1] = *(const uint32_t*)&Ql[(size_t)rB * DIM + c];
            qfl[kf][2] = *(const uint32_t*)&Ql[(size_t)rA * DIM + c + 8];
            qfl[kf][3] = *(const uint32_t*)&Ql[(size_t)rB * DIM + c + 8];
        }
    }

    auto load_kv = [&](int stage, int kv0) {
        __nv_bfloat16* s = adyn + stage * ASTAGE;
        #pragma unroll
        for (int i = 0; i < 2; i++) {
            int unit = t + i * 256;
            int r  = unit >> 3;
            int c8 = (unit & 7) * 8;
            size_t goff = (size_t)(kv0 + r) * DIM + c8;
            int so = r * KPAD + c8;
            cp16(&s[0 * ATILE + so], Kh + goff);
            cp16(&s[1 * ATILE + so], Kl + goff);
            cp16(&s[2 * ATILE + so], Vh + goff);
            cp16(&s[3 * ATILE + so], Vl + goff);
        }
    };

    float om0 = -1e30f, om1 = -1e30f;
    float osum0 = 0.f, osum1 = 0.f;
    float o[8][4];
    #pragma unroll
    for (int nf = 0; nf < 8; nf++)
        #pragma unroll
        for (int q = 0; q < 4; q++) o[nf][q] = 0.f;

    load_kv(0, 0);
    CP_COMMIT();

    for (int kt = 0; kt < NKT; kt++) {
        if (kt + 1 < NKT) {
            load_kv((kt + 1) & 1, (kt + 1) * AKT);
            CP_COMMIT();
            CP_WAIT(1);
        } else {
            CP_WAIT(0);
        }
        __syncthreads();

        const __nv_bfloat16* Khs = adyn + (kt & 1) * ASTAGE + 0 * ATILE;
        const __nv_bfloat16* Kls = adyn + (kt & 1) * ASTAGE + 1 * ATILE;
        const __nv_bfloat16* Vhs = adyn + (kt & 1) * ASTAGE + 2 * ATILE;
        const __nv_bfloat16* Vls = adyn + (kt & 1) * ASTAGE + 3 * ATILE;

        // S = Q K^T (split 3-product): preload K frags, then 3 passes
        float s[8][4];
        #pragma unroll
        for (int nf = 0; nf < 8; nf++)
            #pragma unroll
            for (int q = 0; q < 4; q++) s[nf][q] = 0.f;
        #pragma unroll
        for (int kf = 0; kf < 4; kf++) {
            const int kk = kf * 16;
            uint32_t kbh[4][4], kbl[4][4];
            #pragma unroll
            for (int nfp = 0; nfp < 4; nfp++) {
                int cc = nfp * 16 + kb_ro;
                ldm_x4(kbh[nfp], smem_u32(&Khs[cc * KPAD + kk + kb_co]));
                ldm_x4(kbl[nfp], smem_u32(&Kls[cc * KPAD + kk + kb_co]));
            }
            #pragma unroll
            for (int nfp = 0; nfp < 4; nfp++) {
                mma_bf16(s[2*nfp    ], qfh[kf], kbh[nfp] + 0);
                mma_bf16(s[2*nfp + 1], qfh[kf], kbh[nfp] + 2);
            }
            #pragma unroll
            for (int nfp = 0; nfp < 4; nfp++) {
                mma_bf16(s[2*nfp    ], qfh[kf], kbl[nfp] + 0);
                mma_bf16(s[2*nfp + 1], qfh[kf], kbl[nfp] + 2);
            }
            #pragma unroll
            for (int nfp = 0; nfp < 4; nfp++) {
                mma_bf16(s[2*nfp    ], qfl[kf], kbh[nfp] + 0);
                mma_bf16(s[2*nfp + 1], qfl[kf], kbh[nfp] + 2);
            }
        }

        // Online softmax. Row gr -> c0,c1; row gr+8 -> c2,c3.
        float tmax0 = -1e30f, tmax1 = -1e30f;
        #pragma unroll
        for (int nf = 0; nf < 8; nf++) {
            tmax0 = fmaxf(tmax0, fmaxf(s[nf][0], s[nf][1]));
            tmax1 = fmaxf(tmax1, fmaxf(s[nf][2], s[nf][3]));
        }
        tmax0 = fmaxf(tmax0, __shfl_xor_sync(0xffffffff, tmax0, 1));
        tmax0 = fmaxf(tmax0, __shfl_xor_sync(0xffffffff, tmax0, 2));
        tmax1 = fmaxf(tmax1, __shfl_xor_sync(0xffffffff, tmax1, 1));
        tmax1 = fmaxf(tmax1, __shfl_xor_sync(0xffffffff, tmax1, 2));

        float mn0 = fmaxf(om0, tmax0);
        float mn1 = fmaxf(om1, tmax1);
        float alpha0 = __expf((om0 - mn0) * ATT_SCALE);
        float alpha1 = __expf((om1 - mn1) * ATT_SCALE);
        om0 = mn0; om1 = mn1;

        uint32_t ph0[8], ph1[8], pl0[8], pl1[8];
        float lsum0 = 0.f, lsum1 = 0.f;
        #pragma unroll
        for (int nf = 0; nf < 8; nf++) {
            float p0 = __expf((s[nf][0] - mn0) * ATT_SCALE);
            float p1 = __expf((s[nf][1] - mn0) * ATT_SCALE);
            float p2 = __expf((s[nf][2] - mn1) * ATT_SCALE);
            float p3 = __expf((s[nf][3] - mn1) * ATT_SCALE);
            lsum0 += p0 + p1;
            lsum1 += p2 + p3;
            float h0 = __bfloat162float(__float2bfloat16_rn(p0));
            float h1 = __bfloat162float(__float2bfloat16_rn(p1));
            float h2 = __bfloat162float(__float2bfloat16_rn(p2));
            float h3 = __bfloat162float(__float2bfloat16_rn(p3));
            ph0[nf] = pack_bf16(h0, h1);
            ph1[nf] = pack_bf16(h2, h3);
            pl0[nf] = pack_bf16(p0 - h0, p1 - h1);
            pl1[nf] = pack_bf16(p2 - h2, p3 - h3);
        }
        lsum0 += __shfl_xor_sync(0xffffffff, lsum0, 1);
        lsum0 += __shfl_xor_sync(0xffffffff, lsum0, 2);
        lsum1 += __shfl_xor_sync(0xffffffff, lsum1, 1);
        lsum1 += __shfl_xor_sync(0xffffffff, lsum1, 2);
        osum0 = osum0 * alpha0 + lsum0;
        osum1 = osum1 * alpha1 + lsum1;

        #pragma unroll
        for (int nf = 0; nf < 8; nf++) {
            o[nf][0] *= alpha0; o[nf][1] *= alpha0;
            o[nf][2] *= alpha1; o[nf][3] *= alpha1;
        }

        // O += P V (split 3-product): preload V frags per kf, 3 passes
        #pragma unroll
        for (int kf = 0; kf < 4; kf++) {
            uint32_t pah[4] = {ph0[2*kf], ph1[2*kf], ph0[2*kf+1], ph1[2*kf+1]};
            uint32_t pal[4] = {pl0[2*kf], pl1[2*kf], pl0[2*kf+1], pl1[2*kf+1]};
            const int kk = kf * 16;
            uint32_t vbh[4][4], vbl[4][4];
            #pragma unroll
            for (int nfp = 0; nfp < 4; nfp++) {
                int rr = kk + vb_ro;
                int cc = nfp * 16 + vb_co;
                ldm_x4_t(vbh[nfp], smem_u32(&Vhs[rr * KPAD + cc]));
                ldm_x4_t(vbl[nfp], smem_u32(&Vls[rr * KPAD + cc]));
            }
            #pragma unroll
            for (int nfp = 0; nfp < 4; nfp++) {
                mma_bf16(o[2*nfp    ], pah, vbh[nfp] + 0);
                mma_bf16(o[2*nfp + 1], pah, vbh[nfp] + 2);
            }
            #pragma unroll
            for (int nfp = 0; nfp < 4; nfp++) {
                mma_bf16(o[2*nfp    ], pah, vbl[nfp] + 0);
                mma_bf16(o[2*nfp + 1], pah, vbl[nfp] + 2);
            }
            #pragma unroll
            for (int nfp = 0; nfp < 4; nfp++) {
                mma_bf16(o[2*nfp    ], pal, vbh[nfp] + 0);
                mma_bf16(o[2*nfp + 1], pal, vbh[nfp] + 2);
            }
        }
        __syncthreads();
    }

    // Epilogue: normalize, split, store to g_goh/g_gol
    const float inv0 = 1.0f / osum0;
    const float inv1 = 1.0f / osum1;
    const int rowA = b * NSEQ + row0 + gr;
    #pragma unroll
    for (int nf = 0; nf < 8; nf++) {
        int col = h * HDIM + nf * 8 + qc;
        float v0 = o[nf][0] * inv0;
        float v1 = o[nf][1] * inv0;
        float v2 = o[nf][2] * inv1;
        float v3 = o[nf][3] * inv1;
        float h0 = __bfloat162float(__float2bfloat16_rn(v0));
        float h1 = __bfloat162float(__float2bfloat16_rn(v1));
        float h2 = __bfloat162float(__float2bfloat16_rn(v2));
        float h3 = __bfloat162float(__float2bfloat16_rn(v3));
        *(uint32_t*)&g_goh[(size_t)rowA * DIM + col] = pack_bf16(h0, h1);
        *(uint32_t*)&g_gol[(size_t)rowA * DIM + col] = pack_bf16(v0 - h0, v1 - h1);
        *(uint32_t*)&g_goh[(size_t)(rowA + 8) * DIM + col] = pack_bf16(h2, h3);
        *(uint32_t*)&g_gol[(size_t)(rowA + 8) * DIM + col] = pack_bf16(v2 - h2, v3 - h3);
    }
}

// ===========================================================================
// Launch
// ===========================================================================
extern "C" void kernel_launch(void* const* d_in, const int* in_sizes, int n_in,
                              void* d_out, int out_size) {
    const float* x1 = (const float*)d_in[0];
    const float* x2 = (const float*)d_in[1];
    const float* wq = (const float*)d_in[2];
    const float* wk = (const float*)d_in[3];
    const float* wv = (const float*)d_in[4];
    const float* wo = (const float*)d_in[5];
    const float* bo = (const float*)d_in[6];
    float* out = (float*)d_out;

    const int NX = MROWS * DIM;
    const int NW = DIM * DIM;

    cudaFuncSetAttribute(gemm_mma,
                         cudaFuncAttributeMaxDynamicSharedMemorySize,
                         GEMM_SMEM_BYTES);
    cudaFuncSetAttribute(attn_mma,
                         cudaFuncAttributeMaxDynamicSharedMemorySize,
                         ATTN_SMEM_BYTES);

    split2_kernel<<<dim3(512, 2), 256>>>(x1, x2, NX);
    split4_kernel<<<dim3(256, 4), 256>>>(wq, wk, wv, wo, NW);

    dim3 gg(GM_N / 128, GM_M / 128);  // (8, 32)
    gemm_mma<<<gg, 256, GEMM_SMEM_BYTES>>>(BF_X1H, BF_X1L, BF_WQH, BF_WQL,
                                           nullptr, BF_QH, BF_QL, nullptr);
    gemm_mma<<<gg, 256, GEMM_SMEM_BYTES>>>(BF_X2H, BF_X2L, BF_WKH, BF_WKL,
                                           nullptr, BF_KH, BF_KL, nullptr);
    gemm_mma<<<gg, 256, GEMM_SMEM_BYTES>>>(BF_X2H, BF_X2L, BF_WVH, BF_WVL,
                                           nullptr, BF_VH, BF_VL, nullptr);

    attn_mma<<<dim3(NSEQ / 128, B * HEADS), 256, ATTN_SMEM_BYTES>>>();

    gemm_mma<<<gg, 256, GEMM_SMEM_BYTES>>>(BF_GOH, BF_GOL, BF_WOH, BF_WOL,
                                           out, -1, -1, bo);
}

// round 14
// speedup vs baseline: 3.1545x; 1.0131x over previous
#include <cuda_runtime.h>
#include <cuda_bf16.h>
#include <cstdint>
#include <math.h>

// Problem shapes (fixed)
#define B 2
#define NSEQ 2048
#define DIM 1024
#define HEADS 16
#define HDIM 64
#define MROWS (B * NSEQ)   // 4096
#define ATT_SCALE 0.125f   // 64^-0.5

#define GM_M 4096
#define GM_N 1024
#define GM_K 1024

// ===========================================================================
// Scratch: bf16 hi/lo split arrays (device globals)
// ===========================================================================
__device__ __nv_bfloat16 g_x1h[MROWS * DIM];
__device__ __nv_bfloat16 g_x1l[MROWS * DIM];
__device__ __nv_bfloat16 g_x2h[MROWS * DIM];
__device__ __nv_bfloat16 g_x2l[MROWS * DIM];
__device__ __nv_bfloat16 g_wqh[DIM * DIM];
__device__ __nv_bfloat16 g_wql[DIM * DIM];
__device__ __nv_bfloat16 g_wkh[DIM * DIM];
__device__ __nv_bfloat16 g_wkl[DIM * DIM];
__device__ __nv_bfloat16 g_wvh[DIM * DIM];
__device__ __nv_bfloat16 g_wvl[DIM * DIM];
__device__ __nv_bfloat16 g_woh[DIM * DIM];
__device__ __nv_bfloat16 g_wol[DIM * DIM];
__device__ __nv_bfloat16 g_qh[MROWS * DIM];
__device__ __nv_bfloat16 g_ql[MROWS * DIM];
__device__ __nv_bfloat16 g_kh[MROWS * DIM];
__device__ __nv_bfloat16 g_kl[MROWS * DIM];
__device__ __nv_bfloat16 g_vh[MROWS * DIM];
__device__ __nv_bfloat16 g_vl[MROWS * DIM];
__device__ __nv_bfloat16 g_goh[MROWS * DIM];
__device__ __nv_bfloat16 g_gol[MROWS * DIM];

#define BF_X1H 0
#define BF_X1L 1
#define BF_X2H 2
#define BF_X2L 3
#define BF_WQH 4
#define BF_WQL 5
#define BF_WKH 6
#define BF_WKL 7
#define BF_WVH 8
#define BF_WVL 9
#define BF_WOH 10
#define BF_WOL 11
#define BF_QH 12
#define BF_QL 13
#define BF_KH 14
#define BF_KL 15
#define BF_VH 16
#define BF_VL 17
#define BF_GOH 18
#define BF_GOL 19
__device__ __nv_bfloat16* const g_bf[20] = {
    g_x1h, g_x1l, g_x2h, g_x2l,
    g_wqh, g_wql, g_wkh, g_wkl, g_wvh, g_wvl, g_woh, g_wol,
    g_qh, g_ql, g_kh, g_kl, g_vh, g_vl, g_goh, g_gol
};

// Fused QKV operand table: {Ah, Al, Bh, Bl, Chi, Clo} per z
__device__ const int c_qkv[3][6] = {
    {BF_X1H, BF_X1L, BF_WQH, BF_WQL, BF_QH, BF_QL},
    {BF_X2H, BF_X2L, BF_WKH, BF_WKL, BF_KH, BF_KL},
    {BF_X2H, BF_X2L, BF_WVH, BF_WVL, BF_VH, BF_VL}
};

// ===========================================================================
// Helpers
// ===========================================================================
__device__ __forceinline__ uint32_t pack_bf16(float x, float y) {
    __nv_bfloat162 v = __floats2bfloat162_rn(x, y);   // .x = low = x
    return *(uint32_t*)&v;
}

__device__ __forceinline__ void mma_bf16(float* c, const uint32_t* a,
                                         const uint32_t* b) {
    asm volatile(
        "mma.sync.aligned.m16n8k16.row.col.f32.bf16.bf16.f32 "
        "{%0,%1,%2,%3}, {%4,%5,%6,%7}, {%8,%9}, {%0,%1,%2,%3};"
        : "+f"(c[0]), "+f"(c[1]), "+f"(c[2]), "+f"(c[3])
        : "r"(a[0]), "r"(a[1]), "r"(a[2]), "r"(a[3]),
          "r"(b[0]), "r"(b[1]));
}

__device__ __forceinline__ void cp16(void* smem_dst, const void* gsrc) {
    uint32_t d = (uint32_t)__cvta_generic_to_shared(smem_dst);
    asm volatile("cp.async.cg.shared.global [%0], [%1], 16;"
                 :: "r"(d), "l"(gsrc));
}
#define CP_COMMIT() asm volatile("cp.async.commit_group;" ::: "memory")
#define CP_WAIT(n)  asm volatile("cp.async.wait_group %0;" :: "n"(n) : "memory")

__device__ __forceinline__ uint32_t smem_u32(const void* p) {
    return (uint32_t)__cvta_generic_to_shared(p);
}
__device__ __forceinline__ void ldm_x4(uint32_t* r, uint32_t addr) {
    asm volatile("ldmatrix.sync.aligned.m8n8.x4.shared.b16 {%0,%1,%2,%3}, [%4];"
                 : "=r"(r[0]), "=r"(r[1]), "=r"(r[2]), "=r"(r[3]) : "r"(addr));
}
__device__ __forceinline__ void ldm_x4_t(uint32_t* r, uint32_t addr) {
    asm volatile("ldmatrix.sync.aligned.m8n8.x4.trans.shared.b16 {%0,%1,%2,%3}, [%4];"
                 : "=r"(r[0]), "=r"(r[1]), "=r"(r[2]), "=r"(r[3]) : "r"(addr));
}

// ===========================================================================
// fp32 -> (bf16 hi, bf16 lo) splits, fused launches.
// ===========================================================================
__global__ void split2_kernel(const float* __restrict__ s0,
                              const float* __restrict__ s1, int n) {
    const float* src = (blockIdx.y == 0) ? s0 : s1;
    __nv_bfloat16* hi = (blockIdx.y == 0) ? g_x1h : g_x2h;
    __nv_bfloat16* lo = (blockIdx.y == 0) ? g_x1l : g_x2l;
    for (int i = blockIdx.x * blockDim.x + threadIdx.x; i < n;
         i += gridDim.x * blockDim.x) {
        float x = src[i];
        __nv_bfloat16 h = __float2bfloat16_rn(x);
        hi[i] = h;
        lo[i] = __float2bfloat16_rn(x - __bfloat162float(h));
    }
}

__global__ void split4_kernel(const float* __restrict__ s0,
                              const float* __restrict__ s1,
                              const float* __restrict__ s2,
                              const float* __restrict__ s3, int n) {
    int w = blockIdx.y;
    const float* src = (w == 0) ? s0 : (w == 1) ? s1 : (w == 2) ? s2 : s3;
    __nv_bfloat16* hi = g_bf[BF_WQH + 2 * w];
    __nv_bfloat16* lo = g_bf[BF_WQL + 2 * w];
    for (int i = blockIdx.x * blockDim.x + threadIdx.x; i < n;
         i += gridDim.x * blockDim.x) {
        float x = src[i];
        __nv_bfloat16 h = __float2bfloat16_rn(x);
        hi[i] = h;
        lo[i] = __float2bfloat16_rn(x - __bfloat162float(h));
    }
}

// ===========================================================================
// Split-bf16 tensor-core GEMM: C = A * Bw^T (+bias), C = Ah*Bh+Ah*Bl+Al*Bh.
// Two-stage cp.async pipeline, K chunk 64, ldmatrix.x4 fragments with
// cross-ks register double-buffering: ks+1 frags loaded between product
// passes of ks (hides LDS latency under in-flight HMMAs).
// fused=1: operand indices from c_qkv[blockIdx.z], split-bf16 epilogue.
// fused=0: explicit indices, fp32+bias epilogue to Cext.
// ===========================================================================
#define BKC 64
#define APAD 72
#define GTILE (128 * APAD)
#define GSTAGE (4 * GTILE)
#define GEMM_SMEM_BYTES (2 * GSTAGE * 2)  // 147456 B
#define NCHUNK (GM_K / BKC)               // 16

// load fragments for one 16-wide k-step into buffers
#define LOAD_FRAGS(DST_AH, DST_AL, DST_BH, DST_BL, KK)                        \
    do {                                                                      \
        _Pragma("unroll")                                                     \
        for (int mf = 0; mf < 4; mf++) {                                      \
            int r = wm * 64 + mf * 16 + a_ro;                                 \
            ldm_x4(DST_AH[mf], smem_u32(&Ahs[r * APAD + (KK) + a_co]));       \
            ldm_x4(DST_AL[mf], smem_u32(&Als[r * APAD + (KK) + a_co]));       \
        }                                                                     \
        _Pragma("unroll")                                                     \
        for (int nfp = 0; nfp < 2; nfp++) {                                   \
            int cc = wn * 32 + nfp * 16 + b_ro;                               \
            uint32_t b4h[4], b4l[4];                                          \
            ldm_x4(b4h, smem_u32(&Bhs[cc * APAD + (KK) + b_co]));             \
            ldm_x4(b4l, smem_u32(&Bls[cc * APAD + (KK) + b_co]));             \
            DST_BH[2*nfp][0] = b4h[0]; DST_BH[2*nfp][1] = b4h[1];             \
            DST_BH[2*nfp+1][0] = b4h[2]; DST_BH[2*nfp+1][1] = b4h[3];         \
            DST_BL[2*nfp][0] = b4l[0]; DST_BL[2*nfp][1] = b4l[1];             \
            DST_BL[2*nfp+1][0] = b4l[2]; DST_BL[2*nfp+1][1] = b4l[3];         \
        }                                                                     \
    } while (0)

__global__ __launch_bounds__(256, 1)
void gemm_mma(int fused, int ahIdx, int alIdx, int bhIdx, int blIdx,
              float* __restrict__ Cext, int hiIdx, int loIdx,
              const float* __restrict__ bias) {
    extern __shared__ __align__(16) __nv_bfloat16 dyn[];

    if (fused) {
        const int* tab = c_qkv[blockIdx.z];
        ahIdx = tab[0]; alIdx = tab[1];
        bhIdx = tab[2]; blIdx = tab[3];
        hiIdx = tab[4]; loIdx = tab[5];
    }

    const int t   = threadIdx.x;
    const int wid = t >> 5;
    const int lid = t & 31;
    const int wm  = wid >> 2;
    const int wn  = wid & 3;
    const int n0  = blockIdx.x * 128;
    const int m0  = blockIdx.y * 128;
    const int qr  = lid >> 2;
    const int qc  = (lid & 3) * 2;

    const int a_ro = (lid & 7) + (lid & 8);
    const int a_co = (lid & 16) >> 1;
    const int b_ro = (lid & 7) + ((lid & 16) >> 1);
    const int b_co = (lid & 8);

    const __nv_bfloat16* pAh = g_bf[ahIdx] + (size_t)m0 * GM_K;
    const __nv_bfloat16* pAl = g_bf[alIdx] + (size_t)m0 * GM_K;
    const __nv_bfloat16* pBh = g_bf[bhIdx] + (size_t)n0 * GM_K;
    const __nv_bfloat16* pBl = g_bf[blIdx] + (size_t)n0 * GM_K;

    float acc[4][4][4];
    #pragma unroll
    for (int i = 0; i < 4; i++)
        #pragma unroll
        for (int j = 0; j < 4; j++)
            #pragma unroll
            for (int q = 0; q < 4; q++) acc[i][j][q] = 0.f;

    auto load_stage = [&](int stage, int k0) {
        __nv_bfloat16* s = dyn + stage * GSTAGE;
        #pragma unroll
        for (int i = 0; i < 4; i++) {
            int unit = t + i * 256;
            int r  = unit >> 3;
            int c8 = (unit & 7) * 8;
            size_t g = (size_t)r * GM_K + k0 + c8;
            int so = r * APAD + c8;
            cp16(&s[0 * GTILE + so], pAh + g);
            cp16(&s[1 * GTILE + so], pAl + g);
            cp16(&s[2 * GTILE + so], pBh + g);
            cp16(&s[3 * GTILE + so], pBl + g);
        }
    };

    load_stage(0, 0);
    CP_COMMIT();

    for (int c = 0; c < NCHUNK; c++) {
        if (c + 1 < NCHUNK) {
            load_stage((c + 1) & 1, (c + 1) * BKC);
            CP_COMMIT();
            CP_WAIT(1);
        } else {
            CP_WAIT(0);
        }
        __syncthreads();

        const __nv_bfloat16* Ahs = dyn + (c & 1) * GSTAGE + 0 * GTILE;
        const __nv_bfloat16* Als = dyn + (c & 1) * GSTAGE + 1 * GTILE;
        const __nv_bfloat16* Bhs = dyn + (c & 1) * GSTAGE + 2 * GTILE;
        const __nv_bfloat16* Bls = dyn + (c & 1) * GSTAGE + 3 * GTILE;

        // double-buffered fragments across the 4 k-steps of this chunk
        uint32_t ah[2][4][4], al[2][4][4], bh[2][4][2], bl[2][4][2];
        LOAD_FRAGS(ah[0], al[0], bh[0], bl[0], 0);

        #pragma unroll
        for (int ks = 0; ks < 4; ks++) {
            const int cur = ks & 1, nxt = cur ^ 1;
            // pass 1: hh (frees nothing, but gives the pipe 16 HMMAs)
            #pragma unroll
            for (int mf = 0; mf < 4; mf++)
                #pragma unroll
                for (int nf = 0; nf < 4; nf++)
                    mma_bf16(acc[mf][nf], ah[cur][mf], bh[cur][nf]);
            // prefetch next k-step's fragments under the in-flight HMMAs
            if (ks < 3) {
                const int kk = (ks + 1) * 16;
                LOAD_FRAGS(ah[nxt], al[nxt], bh[nxt], bl[nxt], kk);
            }
            // pass 2: hl
            #pragma unroll
            for (int mf = 0; mf < 4; mf++)
                #pragma unroll
                for (int nf = 0; nf < 4; nf++)
                    mma_bf16(acc[mf][nf], ah[cur][mf], bl[cur][nf]);
            // pass 3: lh
            #pragma unroll
            for (int mf = 0; mf < 4; mf++)
                #pragma unroll
                for (int nf = 0; nf < 4; nf++)
                    mma_bf16(acc[mf][nf], al[cur][mf], bh[cur][nf]);
        }
        __syncthreads();
    }

    if (hiIdx >= 0) {
        __nv_bfloat16* Ch = g_bf[hiIdx];
        __nv_bfloat16* Cl = g_bf[loIdx];
        #pragma unroll
        for (int mf = 0; mf < 4; mf++) {
            int row = m0 + wm * 64 + mf * 16 + qr;
            #pragma unroll
            for (int nf = 0; nf < 4; nf++) {
                int col = n0 + wn * 32 + nf * 8 + qc;
                #pragma unroll
                for (int half = 0; half < 2; half++) {
                    int r = row + half * 8;
                    float v0 = acc[mf][nf][half * 2 + 0];
                    float v1 = acc[mf][nf][half * 2 + 1];
                    float h0 = __bfloat162float(__float2bfloat16_rn(v0));
                    float h1 = __bfloat162float(__float2bfloat16_rn(v1));
                    *(uint32_t*)&Ch[(size_t)r * GM_N + col] = pack_bf16(h0, h1);
                    *(uint32_t*)&Cl[(size_t)r * GM_N + col] =
                        pack_bf16(v0 - h0, v1 - h1);
                }
            }
        }
    } else {
        #pragma unroll
        for (int mf = 0; mf < 4; mf++) {
            int row = m0 + wm * 64 + mf * 16 + qr;
            #pragma unroll
            for (int nf = 0; nf < 4; nf++) {
                int col = n0 + wn * 32 + nf * 8 + qc;
                float b0 = bias ? bias[col] : 0.f;
                float b1 = bias ? bias[col + 1] : 0.f;
                float2 v0 = make_float2(acc[mf][nf][0] + b0, acc[mf][nf][1] + b1);
                float2 v1 = make_float2(acc[mf][nf][2] + b0, acc[mf][nf][3] + b1);
                *(float2*)(Cext + (size_t)row * GM_N + col) = v0;
                *(float2*)(Cext + (size_t)(row + 8) * GM_N + col) = v1;
            }
        }
    }
}

// ===========================================================================
// Flash attention via mma.sync, split-bf16, two-stage cp.async KV pipeline.
// MMA in 3 product passes over preloaded fragments (RAW hiding).
// Block: 256 threads = 8 warps; 128-row q tile; KV tile 64.
// ===========================================================================
#define AKT 64
#define KPAD 72
#define ATILE (AKT * KPAD)
#define ASTAGE (4 * ATILE)
#define ATTN_SMEM_BYTES (2 * ASTAGE * 2)  // 73728 B
#define NKT (NSEQ / AKT)                  // 32

__global__ __launch_bounds__(256, 1)
void attn_mma() {
    extern __shared__ __align__(16) __nv_bfloat16 adyn[];

    const int t   = threadIdx.x;
    const int wid = t >> 5;
    const int lid = t & 31;
    const int gr  = lid >> 2;
    const int qc  = (lid & 3) * 2;
    const int qt  = blockIdx.x;
    const int bh  = blockIdx.y;
    const int b   = bh >> 4;
    const int h   = bh & 15;
    const int n0  = qt * 128;
    const int row0 = n0 + wid * 16;

    const int kb_ro = (lid & 7) + ((lid & 16) >> 1);
    const int kb_co = (lid & 8);
    const int vb_ro = (lid & 7) + (lid & 8);
    const int vb_co = (lid & 16) >> 1;

    const size_t batch_off = (size_t)b * NSEQ * DIM + (size_t)h * HDIM;
    const __nv_bfloat16* Qh = g_qh + batch_off;
    const __nv_bfloat16* Ql = g_ql + batch_off;
    const __nv_bfloat16* Kh = g_kh + batch_off;
    const __nv_bfloat16* Kl = g_kl + batch_off;
    const __nv_bfloat16* Vh = g_vh + batch_off;
    const __nv_bfloat16* Vl = g_vl + batch_off;

    uint32_t qfh[4][4], qfl[4][4];
    {
        const int rA = row0 + gr;
        const int rB = rA + 8;
        #pragma unroll
        for (int kf = 0; kf < 4; kf++) {
            int c = kf * 16 + qc;
            qfh[kf][0] = *(const uint32_t*)&Qh[(size_t)rA * DIM + c];
            qfh[kf][1] = *(const uint32_t*)&Qh[(size_t)rB * DIM + c];
            qfh[kf][2] = *(const uint32_t*)&Qh[(size_t)rA * DIM + c + 8];
            qfh[kf][3] = *(const uint32_t*)&Qh[(size_t)rB * DIM + c + 8];
            qfl[kf][0] = *(const uint32_t*)&Ql[(size_t)rA * DIM + c];
            qfl[kf][1] = *(const uint32_t*)&Ql[(size_t)rB * DIM + c];
            qfl[kf][2] = *(const uint32_t*)&Ql[(size_t)rA * DIM + c + 8];
            qfl[kf][3] = *(const uint32_t*)&Ql[(size_t)rB * DIM + c + 8];
        }
    }

    auto load_kv = [&](int stage, int kv0) {
        __nv_bfloat16* s = adyn + stage * ASTAGE;
        #pragma unroll
        for (int i = 0; i < 2; i++) {
            int unit = t + i * 256;
            int r  = unit >> 3;
            int c8 = (unit & 7) * 8;
            size_t goff = (size_t)(kv0 + r) * DIM + c8;
            int so = r * KPAD + c8;
            cp16(&s[0 * ATILE + so], Kh + goff);
            cp16(&s[1 * ATILE + so], Kl + goff);
            cp16(&s[2 * ATILE + so], Vh + goff);
            cp16(&s[3 * ATILE + so], Vl + goff);
        }
    };

    float om0 = -1e30f, om1 = -1e30f;
    float osum0 = 0.f, osum1 = 0.f;
    float o[8][4];
    #pragma unroll
    for (int nf = 0; nf < 8; nf++)
        #pragma unroll
        for (int q = 0; q < 4; q++) o[nf][q] = 0.f;

    load_kv(0, 0);
    CP_COMMIT();

    for (int kt = 0; kt < NKT; kt++) {
        if (kt + 1 < NKT) {
            load_kv((kt + 1) & 1, (kt + 1) * AKT);
            CP_COMMIT();
            CP_WAIT(1);
        } else {
            CP_WAIT(0);
        }
        __syncthreads();

        const __nv_bfloat16* Khs = adyn + (kt & 1) * ASTAGE + 0 * ATILE;
        const __nv_bfloat16* Kls = adyn + (kt & 1) * ASTAGE + 1 * ATILE;
        const __nv_bfloat16* Vhs = adyn + (kt & 1) * ASTAGE + 2 * ATILE;
        const __nv_bfloat16* Vls = adyn + (kt & 1) * ASTAGE + 3 * ATILE;

        // S = Q K^T (split 3-product): preload K frags, then 3 passes
        float s[8][4];
        #pragma unroll
        for (int nf = 0; nf < 8; nf++)
            #pragma unroll
            for (int q = 0; q < 4; q++) s[nf][q] = 0.f;
        #pragma unroll
        for (int kf = 0; kf < 4; kf++) {
            const int kk = kf * 16;
            uint32_t kbh[4][4], kbl[4][4];
            #pragma unroll
            for (int nfp = 0; nfp < 4; nfp++) {
                int cc = nfp * 16 + kb_ro;
                ldm_x4(kbh[nfp], smem_u32(&Khs[cc * KPAD + kk + kb_co]));
                ldm_x4(kbl[nfp], smem_u32(&Kls[cc * KPAD + kk + kb_co]));
            }
            #pragma unroll
            for (int nfp = 0; nfp < 4; nfp++) {
                mma_bf16(s[2*nfp    ], qfh[kf], kbh[nfp] + 0);
                mma_bf16(s[2*nfp + 1], qfh[kf], kbh[nfp] + 2);
            }
            #pragma unroll
            for (int nfp = 0; nfp < 4; nfp++) {
                mma_bf16(s[2*nfp    ], qfh[kf], kbl[nfp] + 0);
                mma_bf16(s[2*nfp + 1], qfh[kf], kbl[nfp] + 2);
            }
            #pragma unroll
            for (int nfp = 0; nfp < 4; nfp++) {
                mma_bf16(s[2*nfp    ], qfl[kf], kbh[nfp] + 0);
                mma_bf16(s[2*nfp + 1], qfl[kf], kbh[nfp] + 2);
            }
        }

        // Online softmax. Row gr -> c0,c1; row gr+8 -> c2,c3.
        float tmax0 = -1e30f, tmax1 = -1e30f;
        #pragma unroll
        for (int nf = 0; nf < 8; nf++) {
            tmax0 = fmaxf(tmax0, fmaxf(s[nf][0], s[nf][1]));
            tmax1 = fmaxf(tmax1, fmaxf(s[nf][2], s[nf][3]));
        }
        tmax0 = fmaxf(tmax0, __shfl_xor_sync(0xffffffff, tmax0, 1));
        tmax0 = fmaxf(tmax0, __shfl_xor_sync(0xffffffff, tmax0, 2));
        tmax1 = fmaxf(tmax1, __shfl_xor_sync(0xffffffff, tmax1, 1));
        tmax1 = fmaxf(tmax1, __shfl_xor_sync(0xffffffff, tmax1, 2));

        float mn0 = fmaxf(om0, tmax0);
        float mn1 = fmaxf(om1, tmax1);
        float alpha0 = __expf((om0 - mn0) * ATT_SCALE);
        float alpha1 = __expf((om1 - mn1) * ATT_SCALE);
        om0 = mn0; om1 = mn1;

        uint32_t ph0[8], ph1[8], pl0[8], pl1[8];
        float lsum0 = 0.f, lsum1 = 0.f;
        #pragma unroll
        for (int nf = 0; nf < 8; nf++) {
            float p0 = __expf((s[nf][0] - mn0) * ATT_SCALE);
            float p1 = __expf((s[nf][1] - mn0) * ATT_SCALE);
            float p2 = __expf((s[nf][2] - mn1) * ATT_SCALE);
            float p3 = __expf((s[nf][3] - mn1) * ATT_SCALE);
            lsum0 += p0 + p1;
            lsum1 += p2 + p3;
            float h0 = __bfloat162float(__float2bfloat16_rn(p0));
            float h1 = __bfloat162float(__float2bfloat16_rn(p1));
            float h2 = __bfloat162float(__float2bfloat16_rn(p2));
            float h3 = __bfloat162float(__float2bfloat16_rn(p3));
            ph0[nf] = pack_bf16(h0, h1);
            ph1[nf] = pack_bf16(h2, h3);
            pl0[nf] = pack_bf16(p0 - h0, p1 - h1);
            pl1[nf] = pack_bf16(p2 - h2, p3 - h3);
        }
        lsum0 += __shfl_xor_sync(0xffffffff, lsum0, 1);
        lsum0 += __shfl_xor_sync(0xffffffff, lsum0, 2);
        lsum1 += __shfl_xor_sync(0xffffffff, lsum1, 1);
        lsum1 += __shfl_xor_sync(0xffffffff, lsum1, 2);
        osum0 = osum0 * alpha0 + lsum0;
        osum1 = osum1 * alpha1 + lsum1;

        #pragma unroll
        for (int nf = 0; nf < 8; nf++) {
            o[nf][0] *= alpha0; o[nf][1] *= alpha0;
            o[nf][2] *= alpha1; o[nf][3] *= alpha1;
        }

        // O += P V (split 3-product): preload V frags per kf, 3 passes
        #pragma unroll
        for (int kf = 0; kf < 4; kf++) {
            uint32_t pah[4] = {ph0[2*kf], ph1[2*kf], ph0[2*kf+1], ph1[2*kf+1]};
            uint32_t pal[4] = {pl0[2*kf], pl1[2*kf], pl0[2*kf+1], pl1[2*kf+1]};
            const int kk = kf * 16;
            uint32_t vbh[4][4], vbl[4][4];
            #pragma unroll
            for (int nfp = 0; nfp < 4; nfp++) {
                int rr = kk + vb_ro;
                int cc = nfp * 16 + vb_co;
                ldm_x4_t(vbh[nfp], smem_u32(&Vhs[rr * KPAD + cc]));
                ldm_x4_t(vbl[nfp], smem_u32(&Vls[rr * KPAD + cc]));
            }
            #pragma unroll
            for (int nfp = 0; nfp < 4; nfp++) {
                mma_bf16(o[2*nfp    ], pah, vbh[nfp] + 0);
                mma_bf16(o[2*nfp + 1], pah, vbh[nfp] + 2);
            }
            #pragma unroll
            for (int nfp = 0; nfp < 4; nfp++) {
                mma_bf16(o[2*nfp    ], pah, vbl[nfp] + 0);
                mma_bf16(o[2*nfp + 1], pah, vbl[nfp] + 2);
            }
            #pragma unroll
            for (int nfp = 0; nfp < 4; nfp++) {
                mma_bf16(o[2*nfp    ], pal, vbh[nfp] + 0);
                mma_bf16(o[2*nfp + 1], pal, vbh[nfp] + 2);
            }
        }
        __syncthreads();
    }

    // Epilogue: normalize, split, store to g_goh/g_gol
    const float inv0 = 1.0f / osum0;
    const float inv1 = 1.0f / osum1;
    const int rowA = b * NSEQ + row0 + gr;
    #pragma unroll
    for (int nf = 0; nf < 8; nf++) {
        int col = h * HDIM + nf * 8 + qc;
        float v0 = o[nf][0] * inv0;
        float v1 = o[nf][1] * inv0;
        float v2 = o[nf][2] * inv1;
        float v3 = o[nf][3] * inv1;
        float h0 = __bfloat162float(__float2bfloat16_rn(v0));
        float h1 = __bfloat162float(__float2bfloat16_rn(v1));
        float h2 = __bfloat162float(__float2bfloat16_rn(v2));
        float h3 = __bfloat162float(__float2bfloat16_rn(v3));
        *(uint32_t*)&g_goh[(size_t)rowA * DIM + col] = pack_bf16(h0, h1);
        *(uint32_t*)&g_gol[(size_t)rowA * DIM + col] = pack_bf16(v0 - h0, v1 - h1);
        *(uint32_t*)&g_goh[(size_t)(rowA + 8) * DIM + col] = pack_bf16(h2, h3);
        *(uint32_t*)&g_gol[(size_t)(rowA + 8) * DIM + col] = pack_bf16(v2 - h2, v3 - h3);
    }
}

// ===========================================================================
// Launch
// ===========================================================================
extern "C" void kernel_launch(void* const* d_in, const int* in_sizes, int n_in,
                              void* d_out, int out_size) {
    const float* x1 = (const float*)d_in[0];
    const float* x2 = (const float*)d_in[1];
    const float* wq = (const float*)d_in[2];
    const float* wk = (const float*)d_in[3];
    const float* wv = (const float*)d_in[4];
    const float* wo = (const float*)d_in[5];
    const float* bo = (const float*)d_in[6];
    float* out = (float*)d_out;

    const int NX = MROWS * DIM;
    const int NW = DIM * DIM;

    cudaFuncSetAttribute(gemm_mma,
                         cudaFuncAttributeMaxDynamicSharedMemorySize,
                         GEMM_SMEM_BYTES);
    cudaFuncSetAttribute(attn_mma,
                         cudaFuncAttributeMaxDynamicSharedMemorySize,
                         ATTN_SMEM_BYTES);

    split2_kernel<<<dim3(512, 2), 256>>>(x1, x2, NX);
    split4_kernel<<<dim3(256, 4), 256>>>(wq, wk, wv, wo, NW);

    // Fused Q/K/V projections: one launch, 3 z-slices
    gemm_mma<<<dim3(GM_N / 128, GM_M / 128, 3), 256, GEMM_SMEM_BYTES>>>(
        1, 0, 0, 0, 0, nullptr, 0, 0, nullptr);

    attn_mma<<<dim3(NSEQ / 128, B * HEADS), 256, ATTN_SMEM_BYTES>>>();

    gemm_mma<<<dim3(GM_N / 128, GM_M / 128, 1), 256, GEMM_SMEM_BYTES>>>(
        0, BF_GOH, BF_GOL, BF_WOH, BF_WOL, out, -1, -1, bo);
}

// round 15
// speedup vs baseline: 3.2698x; 1.0365x over previous
#include <cuda_runtime.h>
#include <cuda_bf16.h>
#include <cstdint>
#include <math.h>

// Problem shapes (fixed)
#define B 2
#define NSEQ 2048
#define DIM 1024
#define HEADS 16
#define HDIM 64
#define MROWS (B * NSEQ)   // 4096
#define ATT_SCALE 0.125f   // 64^-0.5

#define GM_M 4096
#define GM_N 1024
#define GM_K 1024

// ===========================================================================
// Scratch: bf16 hi/lo split arrays (device globals)
// ===========================================================================
__device__ __nv_bfloat16 g_x1h[MROWS * DIM];
__device__ __nv_bfloat16 g_x1l[MROWS * DIM];
__device__ __nv_bfloat16 g_x2h[MROWS * DIM];
__device__ __nv_bfloat16 g_x2l[MROWS * DIM];
__device__ __nv_bfloat16 g_wqh[DIM * DIM];
__device__ __nv_bfloat16 g_wql[DIM * DIM];
__device__ __nv_bfloat16 g_wkh[DIM * DIM];
__device__ __nv_bfloat16 g_wkl[DIM * DIM];
__device__ __nv_bfloat16 g_wvh[DIM * DIM];
__device__ __nv_bfloat16 g_wvl[DIM * DIM];
__device__ __nv_bfloat16 g_woh[DIM * DIM];
__device__ __nv_bfloat16 g_wol[DIM * DIM];
__device__ __nv_bfloat16 g_qh[MROWS * DIM];
__device__ __nv_bfloat16 g_ql[MROWS * DIM];
__device__ __nv_bfloat16 g_kh[MROWS * DIM];
__device__ __nv_bfloat16 g_kl[MROWS * DIM];
__device__ __nv_bfloat16 g_vh[MROWS * DIM];
__device__ __nv_bfloat16 g_vl[MROWS * DIM];
__device__ __nv_bfloat16 g_goh[MROWS * DIM];
__device__ __nv_bfloat16 g_gol[MROWS * DIM];

#define BF_X1H 0
#define BF_X1L 1
#define BF_X2H 2
#define BF_X2L 3
#define BF_WQH 4
#define BF_WQL 5
#define BF_WKH 6
#define BF_WKL 7
#define BF_WVH 8
#define BF_WVL 9
#define BF_WOH 10
#define BF_WOL 11
#define BF_QH 12
#define BF_QL 13
#define BF_KH 14
#define BF_KL 15
#define BF_VH 16
#define BF_VL 17
#define BF_GOH 18
#define BF_GOL 19
__device__ __nv_bfloat16* const g_bf[20] = {
    g_x1h, g_x1l, g_x2h, g_x2l,
    g_wqh, g_wql, g_wkh, g_wkl, g_wvh, g_wvl, g_woh, g_wol,
    g_qh, g_ql, g_kh, g_kl, g_vh, g_vl, g_goh, g_gol
};

// Fused QKV operand table: {Ah, Al, Bh, Bl, Chi, Clo} per z
__device__ const int c_qkv[3][6] = {
    {BF_X1H, BF_X1L, BF_WQH, BF_WQL, BF_QH, BF_QL},
    {BF_X2H, BF_X2L, BF_WKH, BF_WKL, BF_KH, BF_KL},
    {BF_X2H, BF_X2L, BF_WVH, BF_WVL, BF_VH, BF_VL}
};

// ===========================================================================
// Helpers
// ===========================================================================
__device__ __forceinline__ uint32_t pack_bf16(float x, float y) {
    __nv_bfloat162 v = __floats2bfloat162_rn(x, y);   // .x = low = x
    return *(uint32_t*)&v;
}

__device__ __forceinline__ void mma_bf16(float* c, const uint32_t* a,
                                         const uint32_t* b) {
    asm volatile(
        "mma.sync.aligned.m16n8k16.row.col.f32.bf16.bf16.f32 "
        "{%0,%1,%2,%3}, {%4,%5,%6,%7}, {%8,%9}, {%0,%1,%2,%3};"
        : "+f"(c[0]), "+f"(c[1]), "+f"(c[2]), "+f"(c[3])
        : "r"(a[0]), "r"(a[1]), "r"(a[2]), "r"(a[3]),
          "r"(b[0]), "r"(b[1]));
}

__device__ __forceinline__ void cp16(void* smem_dst, const void* gsrc) {
    uint32_t d = (uint32_t)__cvta_generic_to_shared(smem_dst);
    asm volatile("cp.async.cg.shared.global [%0], [%1], 16;"
                 :: "r"(d), "l"(gsrc));
}
#define CP_COMMIT() asm volatile("cp.async.commit_group;" ::: "memory")
#define CP_WAIT(n)  asm volatile("cp.async.wait_group %0;" :: "n"(n) : "memory")

__device__ __forceinline__ uint32_t smem_u32(const void* p) {
    return (uint32_t)__cvta_generic_to_shared(p);
}
__device__ __forceinline__ void ldm_x4(uint32_t* r, uint32_t addr) {
    asm volatile("ldmatrix.sync.aligned.m8n8.x4.shared.b16 {%0,%1,%2,%3}, [%4];"
                 : "=r"(r[0]), "=r"(r[1]), "=r"(r[2]), "=r"(r[3]) : "r"(addr));
}
__device__ __forceinline__ void ldm_x4_t(uint32_t* r, uint32_t addr) {
    asm volatile("ldmatrix.sync.aligned.m8n8.x4.trans.shared.b16 {%0,%1,%2,%3}, [%4];"
                 : "=r"(r[0]), "=r"(r[1]), "=r"(r[2]), "=r"(r[3]) : "r"(addr));
}

// ===========================================================================
// fp32 -> (bf16 hi, bf16 lo) splits, fused launches.
// ===========================================================================
__global__ void split2_kernel(const float* __restrict__ s0,
                              const float* __restrict__ s1, int n) {
    const float* src = (blockIdx.y == 0) ? s0 : s1;
    __nv_bfloat16* hi = (blockIdx.y == 0) ? g_x1h : g_x2h;
    __nv_bfloat16* lo = (blockIdx.y == 0) ? g_x1l : g_x2l;
    for (int i = blockIdx.x * blockDim.x + threadIdx.x; i < n;
         i += gridDim.x * blockDim.x) {
        float x = src[i];
        __nv_bfloat16 h = __float2bfloat16_rn(x);
        hi[i] = h;
        lo[i] = __float2bfloat16_rn(x - __bfloat162float(h));
    }
}

__global__ void split4_kernel(const float* __restrict__ s0,
                              const float* __restrict__ s1,
                              const float* __restrict__ s2,
                              const float* __restrict__ s3, int n) {
    int w = blockIdx.y;
    const float* src = (w == 0) ? s0 : (w == 1) ? s1 : (w == 2) ? s2 : s3;
    __nv_bfloat16* hi = g_bf[BF_WQH + 2 * w];
    __nv_bfloat16* lo = g_bf[BF_WQL + 2 * w];
    for (int i = blockIdx.x * blockDim.x + threadIdx.x; i < n;
         i += gridDim.x * blockDim.x) {
        float x = src[i];
        __nv_bfloat16 h = __float2bfloat16_rn(x);
        hi[i] = h;
        lo[i] = __float2bfloat16_rn(x - __bfloat162float(h));
    }
}

// ===========================================================================
// Split-bf16 tensor-core GEMM: C = A * Bw^T (+bias), C = Ah*Bh+Ah*Bl+Al*Bh.
// Two-stage cp.async pipeline, K chunk 64, ldmatrix.x4 fragments with
// cross-ks register double-buffering.
// fused=1: operand indices from c_qkv[blockIdx.z], split-bf16 epilogue.
// ===========================================================================
#define BKC 64
#define APAD 72
#define GTILE (128 * APAD)
#define GSTAGE (4 * GTILE)
#define GEMM_SMEM_BYTES (2 * GSTAGE * 2)  // 147456 B
#define NCHUNK (GM_K / BKC)               // 16

#define LOAD_FRAGS(DST_AH, DST_AL, DST_BH, DST_BL, KK)                        \
    do {                                                                      \
        _Pragma("unroll")                                                     \
        for (int mf = 0; mf < 4; mf++) {                                      \
            int r = wm * 64 + mf * 16 + a_ro;                                 \
            ldm_x4(DST_AH[mf], smem_u32(&Ahs[r * APAD + (KK) + a_co]));       \
            ldm_x4(DST_AL[mf], smem_u32(&Als[r * APAD + (KK) + a_co]));       \
        }                                                                     \
        _Pragma("unroll")                                                     \
        for (int nfp = 0; nfp < 2; nfp++) {                                   \
            int cc = wn * 32 + nfp * 16 + b_ro;                               \
            uint32_t b4h[4], b4l[4];                                          \
            ldm_x4(b4h, smem_u32(&Bhs[cc * APAD + (KK) + b_co]));             \
            ldm_x4(b4l, smem_u32(&Bls[cc * APAD + (KK) + b_co]));             \
            DST_BH[2*nfp][0] = b4h[0]; DST_BH[2*nfp][1] = b4h[1];             \
            DST_BH[2*nfp+1][0] = b4h[2]; DST_BH[2*nfp+1][1] = b4h[3];         \
            DST_BL[2*nfp][0] = b4l[0]; DST_BL[2*nfp][1] = b4l[1];             \
            DST_BL[2*nfp+1][0] = b4l[2]; DST_BL[2*nfp+1][1] = b4l[3];         \
        }                                                                     \
    } while (0)

__global__ __launch_bounds__(256, 1)
void gemm_mma(int fused, int ahIdx, int alIdx, int bhIdx, int blIdx,
              float* __restrict__ Cext, int hiIdx, int loIdx,
              const float* __restrict__ bias) {
    extern __shared__ __align__(16) __nv_bfloat16 dyn[];

    if (fused) {
        const int* tab = c_qkv[blockIdx.z];
        ahIdx = tab[0]; alIdx = tab[1];
        bhIdx = tab[2]; blIdx = tab[3];
        hiIdx = tab[4]; loIdx = tab[5];
    }

    const int t   = threadIdx.x;
    const int wid = t >> 5;
    const int lid = t & 31;
    const int wm  = wid >> 2;
    const int wn  = wid & 3;
    const int n0  = blockIdx.x * 128;
    const int m0  = blockIdx.y * 128;
    const int qr  = lid >> 2;
    const int qc  = (lid & 3) * 2;

    const int a_ro = (lid & 7) + (lid & 8);
    const int a_co = (lid & 16) >> 1;
    const int b_ro = (lid & 7) + ((lid & 16) >> 1);
    const int b_co = (lid & 8);

    const __nv_bfloat16* pAh = g_bf[ahIdx] + (size_t)m0 * GM_K;
    const __nv_bfloat16* pAl = g_bf[alIdx] + (size_t)m0 * GM_K;
    const __nv_bfloat16* pBh = g_bf[bhIdx] + (size_t)n0 * GM_K;
    const __nv_bfloat16* pBl = g_bf[blIdx] + (size_t)n0 * GM_K;

    float acc[4][4][4];
    #pragma unroll
    for (int i = 0; i < 4; i++)
        #pragma unroll
        for (int j = 0; j < 4; j++)
            #pragma unroll
            for (int q = 0; q < 4; q++) acc[i][j][q] = 0.f;

    auto load_stage = [&](int stage, int k0) {
        __nv_bfloat16* s = dyn + stage * GSTAGE;
        #pragma unroll
        for (int i = 0; i < 4; i++) {
            int unit = t + i * 256;
            int r  = unit >> 3;
            int c8 = (unit & 7) * 8;
            size_t g = (size_t)r * GM_K + k0 + c8;
            int so = r * APAD + c8;
            cp16(&s[0 * GTILE + so], pAh + g);
            cp16(&s[1 * GTILE + so], pAl + g);
            cp16(&s[2 * GTILE + so], pBh + g);
            cp16(&s[3 * GTILE + so], pBl + g);
        }
    };

    load_stage(0, 0);
    CP_COMMIT();

    for (int c = 0; c < NCHUNK; c++) {
        if (c + 1 < NCHUNK) {
            load_stage((c + 1) & 1, (c + 1) * BKC);
            CP_COMMIT();
            CP_WAIT(1);
        } else {
            CP_WAIT(0);
        }
        __syncthreads();

        const __nv_bfloat16* Ahs = dyn + (c & 1) * GSTAGE + 0 * GTILE;
        const __nv_bfloat16* Als = dyn + (c & 1) * GSTAGE + 1 * GTILE;
        const __nv_bfloat16* Bhs = dyn + (c & 1) * GSTAGE + 2 * GTILE;
        const __nv_bfloat16* Bls = dyn + (c & 1) * GSTAGE + 3 * GTILE;

        uint32_t ah[2][4][4], al[2][4][4], bh[2][4][2], bl[2][4][2];
        LOAD_FRAGS(ah[0], al[0], bh[0], bl[0], 0);

        #pragma unroll
        for (int ks = 0; ks < 4; ks++) {
            const int cur = ks & 1, nxt = cur ^ 1;
            #pragma unroll
            for (int mf = 0; mf < 4; mf++)
                #pragma unroll
                for (int nf = 0; nf < 4; nf++)
                    mma_bf16(acc[mf][nf], ah[cur][mf], bh[cur][nf]);
            if (ks < 3) {
                const int kk = (ks + 1) * 16;
                LOAD_FRAGS(ah[nxt], al[nxt], bh[nxt], bl[nxt], kk);
            }
            #pragma unroll
            for (int mf = 0; mf < 4; mf++)
                #pragma unroll
                for (int nf = 0; nf < 4; nf++)
                    mma_bf16(acc[mf][nf], ah[cur][mf], bl[cur][nf]);
            #pragma unroll
            for (int mf = 0; mf < 4; mf++)
                #pragma unroll
                for (int nf = 0; nf < 4; nf++)
                    mma_bf16(acc[mf][nf], al[cur][mf], bh[cur][nf]);
        }
        __syncthreads();
    }

    if (hiIdx >= 0) {
        __nv_bfloat16* Ch = g_bf[hiIdx];
        __nv_bfloat16* Cl = g_bf[loIdx];
        #pragma unroll
        for (int mf = 0; mf < 4; mf++) {
            int row = m0 + wm * 64 + mf * 16 + qr;
            #pragma unroll
            for (int nf = 0; nf < 4; nf++) {
                int col = n0 + wn * 32 + nf * 8 + qc;
                #pragma unroll
                for (int half = 0; half < 2; half++) {
                    int r = row + half * 8;
                    float v0 = acc[mf][nf][half * 2 + 0];
                    float v1 = acc[mf][nf][half * 2 + 1];
                    float h0 = __bfloat162float(__float2bfloat16_rn(v0));
                    float h1 = __bfloat162float(__float2bfloat16_rn(v1));
                    *(uint32_t*)&Ch[(size_t)r * GM_N + col] = pack_bf16(h0, h1);
                    *(uint32_t*)&Cl[(size_t)r * GM_N + col] =
                        pack_bf16(v0 - h0, v1 - h1);
                }
            }
        }
    } else {
        #pragma unroll
        for (int mf = 0; mf < 4; mf++) {
            int row = m0 + wm * 64 + mf * 16 + qr;
            #pragma unroll
            for (int nf = 0; nf < 4; nf++) {
                int col = n0 + wn * 32 + nf * 8 + qc;
                float b0 = bias ? bias[col] : 0.f;
                float b1 = bias ? bias[col + 1] : 0.f;
                float2 v0 = make_float2(acc[mf][nf][0] + b0, acc[mf][nf][1] + b1);
                float2 v1 = make_float2(acc[mf][nf][2] + b0, acc[mf][nf][3] + b1);
                *(float2*)(Cext + (size_t)row * GM_N + col) = v0;
                *(float2*)(Cext + (size_t)(row + 8) * GM_N + col) = v1;
            }
        }
    }
}

// ===========================================================================
// Flash attention via mma.sync, split-bf16, two-stage cp.async KV pipeline.
// Block: 128 threads = 4 warps; 64-row q tile (warp w owns rows [16w,16w+16)).
// Small CTAs -> 2-3 resident CTAs/SM: one CTA's softmax overlaps another's
// MMA bursts (R14 profile: 1 CTA/SM serialized them; tensor pipe 52.7%).
// KV tile 64 raw [kv][d]; K frags ldmatrix.x4, V ldmatrix.x4.trans.
// ===========================================================================
#define AKT 64
#define KPAD 72
#define ATILE (AKT * KPAD)
#define ASTAGE (4 * ATILE)
#define ATTN_SMEM_BYTES (2 * ASTAGE * 2)  // 73728 B
#define NKT (NSEQ / AKT)                  // 32

__global__ __launch_bounds__(128, 2)
void attn_mma() {
    extern __shared__ __align__(16) __nv_bfloat16 adyn[];

    const int t   = threadIdx.x;
    const int wid = t >> 5;            // 0..3
    const int lid = t & 31;
    const int gr  = lid >> 2;
    const int qc  = (lid & 3) * 2;
    const int qt  = blockIdx.x;        // 0..31
    const int bh  = blockIdx.y;        // 0..31
    const int b   = bh >> 4;
    const int h   = bh & 15;
    const int n0  = qt * 64;
    const int row0 = n0 + wid * 16;

    const int kb_ro = (lid & 7) + ((lid & 16) >> 1);
    const int kb_co = (lid & 8);
    const int vb_ro = (lid & 7) + (lid & 8);
    const int vb_co = (lid & 16) >> 1;

    const size_t batch_off = (size_t)b * NSEQ * DIM + (size_t)h * HDIM;
    const __nv_bfloat16* Qh = g_qh + batch_off;
    const __nv_bfloat16* Ql = g_ql + batch_off;
    const __nv_bfloat16* Kh = g_kh + batch_off;
    const __nv_bfloat16* Kl = g_kl + batch_off;
    const __nv_bfloat16* Vh = g_vh + batch_off;
    const __nv_bfloat16* Vl = g_vl + batch_off;

    uint32_t qfh[4][4], qfl[4][4];
    {
        const int rA = row0 + gr;
        const int rB = rA + 8;
        #pragma unroll
        for (int kf = 0; kf < 4; kf++) {
            int c = kf * 16 + qc;
            qfh[kf][0] = *(const uint32_t*)&Qh[(size_t)rA * DIM + c];
            qfh[kf][1] = *(const uint32_t*)&Qh[(size_t)rB * DIM + c];
            qfh[kf][2] = *(const uint32_t*)&Qh[(size_t)rA * DIM + c + 8];
            qfh[kf][3] = *(const uint32_t*)&Qh[(size_t)rB * DIM + c + 8];
            qfl[kf][0] = *(const uint32_t*)&Ql[(size_t)rA * DIM + c];
            qfl[kf][1] = *(const uint32_t*)&Ql[(size_t)rB * DIM + c];
            qfl[kf][2] = *(const uint32_t*)&Ql[(size_t)rA * DIM + c + 8];
            qfl[kf][3] = *(const uint32_t*)&Ql[(size_t)rB * DIM + c + 8];
        }
    }

    // KV stage loader: 512 int4 units per array / 128 threads = 4 each
    auto load_kv = [&](int stage, int kv0) {
        __nv_bfloat16* s = adyn + stage * ASTAGE;
        #pragma unroll
        for (int i = 0; i < 4; i++) {
            int unit = t + i * 128;
            int r  = unit >> 3;
            int c8 = (unit & 7) * 8;
            size_t goff = (size_t)(kv0 + r) * DIM + c8;
            int so = r * KPAD + c8;
            cp16(&s[0 * ATILE + so], Kh + goff);
            cp16(&s[1 * ATILE + so], Kl + goff);
            cp16(&s[2 * ATILE + so], Vh + goff);
            cp16(&s[3 * ATILE + so], Vl + goff);
        }
    };

    float om0 = -1e30f, om1 = -1e30f;
    float osum0 = 0.f, osum1 = 0.f;
    float o[8][4];
    #pragma unroll
    for (int nf = 0; nf < 8; nf++)
        #pragma unroll
        for (int q = 0; q < 4; q++) o[nf][q] = 0.f;

    load_kv(0, 0);
    CP_COMMIT();

    for (int kt = 0; kt < NKT; kt++) {
        if (kt + 1 < NKT) {
            load_kv((kt + 1) & 1, (kt + 1) * AKT);
            CP_COMMIT();
            CP_WAIT(1);
        } else {
            CP_WAIT(0);
        }
        __syncthreads();

        const __nv_bfloat16* Khs = adyn + (kt & 1) * ASTAGE + 0 * ATILE;
        const __nv_bfloat16* Kls = adyn + (kt & 1) * ASTAGE + 1 * ATILE;
        const __nv_bfloat16* Vhs = adyn + (kt & 1) * ASTAGE + 2 * ATILE;
        const __nv_bfloat16* Vls = adyn + (kt & 1) * ASTAGE + 3 * ATILE;

        // S = Q K^T (split 3-product): preload K frags, then 3 passes
        float s[8][4];
        #pragma unroll
        for (int nf = 0; nf < 8; nf++)
            #pragma unroll
            for (int q = 0; q < 4; q++) s[nf][q] = 0.f;
        #pragma unroll
        for (int kf = 0; kf < 4; kf++) {
            const int kk = kf * 16;
            uint32_t kbh[4][4], kbl[4][4];
            #pragma unroll
            for (int nfp = 0; nfp < 4; nfp++) {
                int cc = nfp * 16 + kb_ro;
                ldm_x4(kbh[nfp], smem_u32(&Khs[cc * KPAD + kk + kb_co]));
                ldm_x4(kbl[nfp], smem_u32(&Kls[cc * KPAD + kk + kb_co]));
            }
            #pragma unroll
            for (int nfp = 0; nfp < 4; nfp++) {
                mma_bf16(s[2*nfp    ], qfh[kf], kbh[nfp] + 0);
                mma_bf16(s[2*nfp + 1], qfh[kf], kbh[nfp] + 2);
            }
            #pragma unroll
            for (int nfp = 0; nfp < 4; nfp++) {
                mma_bf16(s[2*nfp    ], qfh[kf], kbl[nfp] + 0);
                mma_bf16(s[2*nfp + 1], qfh[kf], kbl[nfp] + 2);
            }
            #pragma unroll
            for (int nfp = 0; nfp < 4; nfp++) {
                mma_bf16(s[2*nfp    ], qfl[kf], kbh[nfp] + 0);
                mma_bf16(s[2*nfp + 1], qfl[kf], kbh[nfp] + 2);
            }
        }

        // Online softmax. Row gr -> c0,c1; row gr+8 -> c2,c3.
        float tmax0 = -1e30f, tmax1 = -1e30f;
        #pragma unroll
        for (int nf = 0; nf < 8; nf++) {
            tmax0 = fmaxf(tmax0, fmaxf(s[nf][0], s[nf][1]));
            tmax1 = fmaxf(tmax1, fmaxf(s[nf][2], s[nf][3]));
        }
        tmax0 = fmaxf(tmax0, __shfl_xor_sync(0xffffffff, tmax0, 1));
        tmax0 = fmaxf(tmax0, __shfl_xor_sync(0xffffffff, tmax0, 2));
        tmax1 = fmaxf(tmax1, __shfl_xor_sync(0xffffffff, tmax1, 1));
        tmax1 = fmaxf(tmax1, __shfl_xor_sync(0xffffffff, tmax1, 2));

        float mn0 = fmaxf(om0, tmax0);
        float mn1 = fmaxf(om1, tmax1);
        float alpha0 = __expf((om0 - mn0) * ATT_SCALE);
        float alpha1 = __expf((om1 - mn1) * ATT_SCALE);
        om0 = mn0; om1 = mn1;

        uint32_t ph0[8], ph1[8], pl0[8], pl1[8];
        float lsum0 = 0.f, lsum1 = 0.f;
        #pragma unroll
        for (int nf = 0; nf < 8; nf++) {
            float p0 = __expf((s[nf][0] - mn0) * ATT_SCALE);
            float p1 = __expf((s[nf][1] - mn0) * ATT_SCALE);
            float p2 = __expf((s[nf][2] - mn1) * ATT_SCALE);
            float p3 = __expf((s[nf][3] - mn1) * ATT_SCALE);
            lsum0 += p0 + p1;
            lsum1 += p2 + p3;
            float h0 = __bfloat162float(__float2bfloat16_rn(p0));
            float h1 = __bfloat162float(__float2bfloat16_rn(p1));
            float h2 = __bfloat162float(__float2bfloat16_rn(p2));
            float h3 = __bfloat162float(__float2bfloat16_rn(p3));
            ph0[nf] = pack_bf16(h0, h1);
            ph1[nf] = pack_bf16(h2, h3);
            pl0[nf] = pack_bf16(p0 - h0, p1 - h1);
            pl1[nf] = pack_bf16(p2 - h2, p3 - h3);
        }
        lsum0 += __shfl_xor_sync(0xffffffff, lsum0, 1);
        lsum0 += __shfl_xor_sync(0xffffffff, lsum0, 2);
        lsum1 += __shfl_xor_sync(0xffffffff, lsum1, 1);
        lsum1 += __shfl_xor_sync(0xffffffff, lsum1, 2);
        osum0 = osum0 * alpha0 + lsum0;
        osum1 = osum1 * alpha1 + lsum1;

        #pragma unroll
        for (int nf = 0; nf < 8; nf++) {
            o[nf][0] *= alpha0; o[nf][1] *= alpha0;
            o[nf][2] *= alpha1; o[nf][3] *= alpha1;
        }

        // O += P V (split 3-product): preload V frags per kf, 3 passes
        #pragma unroll
        for (int kf = 0; kf < 4; kf++) {
            uint32_t pah[4] = {ph0[2*kf], ph1[2*kf], ph0[2*kf+1], ph1[2*kf+1]};
            uint32_t pal[4] = {pl0[2*kf], pl1[2*kf], pl0[2*kf+1], pl1[2*kf+1]};
            const int kk = kf * 16;
            uint32_t vbh[4][4], vbl[4][4];
            #pragma unroll
            for (int nfp = 0; nfp < 4; nfp++) {
                int rr = kk + vb_ro;
                int cc = nfp * 16 + vb_co;
                ldm_x4_t(vbh[nfp], smem_u32(&Vhs[rr * KPAD + cc]));
                ldm_x4_t(vbl[nfp], smem_u32(&Vls[rr * KPAD + cc]));
            }
            #pragma unroll
            for (int nfp = 0; nfp < 4; nfp++) {
                mma_bf16(o[2*nfp    ], pah, vbh[nfp] + 0);
                mma_bf16(o[2*nfp + 1], pah, vbh[nfp] + 2);
            }
            #pragma unroll
            for (int nfp = 0; nfp < 4; nfp++) {
                mma_bf16(o[2*nfp    ], pah, vbl[nfp] + 0);
                mma_bf16(o[2*nfp + 1], pah, vbl[nfp] + 2);
            }
            #pragma unroll
            for (int nfp = 0; nfp < 4; nfp++) {
                mma_bf16(o[2*nfp    ], pal, vbh[nfp] + 0);
                mma_bf16(o[2*nfp + 1], pal, vbh[nfp] + 2);
            }
        }
        __syncthreads();
    }

    // Epilogue: normalize, split, store to g_goh/g_gol
    const float inv0 = 1.0f / osum0;
    const float inv1 = 1.0f / osum1;
    const int rowA = b * NSEQ + row0 + gr;
    #pragma unroll
    for (int nf = 0; nf < 8; nf++) {
        int col = h * HDIM + nf * 8 + qc;
        float v0 = o[nf][0] * inv0;
        float v1 = o[nf][1] * inv0;
        float v2 = o[nf][2] * inv1;
        float v3 = o[nf][3] * inv1;
        float h0 = __bfloat162float(__float2bfloat16_rn(v0));
        float h1 = __bfloat162float(__float2bfloat16_rn(v1));
        float h2 = __bfloat162float(__float2bfloat16_rn(v2));
        float h3 = __bfloat162float(__float2bfloat16_rn(v3));
        *(uint32_t*)&g_goh[(size_t)rowA * DIM + col] = pack_bf16(h0, h1);
        *(uint32_t*)&g_gol[(size_t)rowA * DIM + col] = pack_bf16(v0 - h0, v1 - h1);
        *(uint32_t*)&g_goh[(size_t)(rowA + 8) * DIM + col] = pack_bf16(h2, h3);
        *(uint32_t*)&g_gol[(size_t)(rowA + 8) * DIM + col] = pack_bf16(v2 - h2, v3 - h3);
    }
}

// ===========================================================================
// Launch
// ===========================================================================
extern "C" void kernel_launch(void* const* d_in, const int* in_sizes, int n_in,
                              void* d_out, int out_size) {
    const float* x1 = (const float*)d_in[0];
    const float* x2 = (const float*)d_in[1];
    const float* wq = (const float*)d_in[2];
    const float* wk = (const float*)d_in[3];
    const float* wv = (const float*)d_in[4];
    const float* wo = (const float*)d_in[5];
    const float* bo = (const float*)d_in[6];
    float* out = (float*)d_out;

    const int NX = MROWS * DIM;
    const int NW = DIM * DIM;

    cudaFuncSetAttribute(gemm_mma,
                         cudaFuncAttributeMaxDynamicSharedMemorySize,
                         GEMM_SMEM_BYTES);
    cudaFuncSetAttribute(attn_mma,
                         cudaFuncAttributeMaxDynamicSharedMemorySize,
                         ATTN_SMEM_BYTES);

    split2_kernel<<<dim3(512, 2), 256>>>(x1, x2, NX);
    split4_kernel<<<dim3(256, 4), 256>>>(wq, wk, wv, wo, NW);

    // Fused Q/K/V projections: one launch, 3 z-slices
    gemm_mma<<<dim3(GM_N / 128, GM_M / 128, 3), 256, GEMM_SMEM_BYTES>>>(
        1, 0, 0, 0, 0, nullptr, 0, 0, nullptr);

    attn_mma<<<dim3(NSEQ / 64, B * HEADS), 128, ATTN_SMEM_BYTES>>>();

    gemm_mma<<<dim3(GM_N / 128, GM_M / 128, 1), 256, GEMM_SMEM_BYTES>>>(
        0, BF_GOH, BF_GOL, BF_WOH, BF_WOL, out, -1, -1, bo);
}

// round 16
// speedup vs baseline: 3.3739x; 1.0318x over previous
#include <cuda_runtime.h>
#include <cuda_bf16.h>
#include <cstdint>
#include <math.h>

// Problem shapes (fixed)
#define B 2
#define NSEQ 2048
#define DIM 1024
#define HEADS 16
#define HDIM 64
#define MROWS (B * NSEQ)   // 4096
#define ATT_SCALE 0.125f   // 64^-0.5

#define GM_M 4096
#define GM_N 1024
#define GM_K 1024

// ===========================================================================
// Scratch: bf16 hi/lo split arrays (device globals)
// ===========================================================================
__device__ __nv_bfloat16 g_x1h[MROWS * DIM];
__device__ __nv_bfloat16 g_x1l[MROWS * DIM];
__device__ __nv_bfloat16 g_x2h[MROWS * DIM];
__device__ __nv_bfloat16 g_x2l[MROWS * DIM];
__device__ __nv_bfloat16 g_wqh[DIM * DIM];
__device__ __nv_bfloat16 g_wql[DIM * DIM];
__device__ __nv_bfloat16 g_wkh[DIM * DIM];
__device__ __nv_bfloat16 g_wkl[DIM * DIM];
__device__ __nv_bfloat16 g_wvh[DIM * DIM];
__device__ __nv_bfloat16 g_wvl[DIM * DIM];
__device__ __nv_bfloat16 g_woh[DIM * DIM];
__device__ __nv_bfloat16 g_wol[DIM * DIM];
__device__ __nv_bfloat16 g_qh[MROWS * DIM];
__device__ __nv_bfloat16 g_ql[MROWS * DIM];
__device__ __nv_bfloat16 g_kh[MROWS * DIM];
__device__ __nv_bfloat16 g_kl[MROWS * DIM];
__device__ __nv_bfloat16 g_vh[MROWS * DIM];
__device__ __nv_bfloat16 g_vl[MROWS * DIM];
__device__ __nv_bfloat16 g_goh[MROWS * DIM];
__device__ __nv_bfloat16 g_gol[MROWS * DIM];

#define BF_X1H 0
#define BF_X1L 1
#define BF_X2H 2
#define BF_X2L 3
#define BF_WQH 4
#define BF_WQL 5
#define BF_WKH 6
#define BF_WKL 7
#define BF_WVH 8
#define BF_WVL 9
#define BF_WOH 10
#define BF_WOL 11
#define BF_QH 12
#define BF_QL 13
#define BF_KH 14
#define BF_KL 15
#define BF_VH 16
#define BF_VL 17
#define BF_GOH 18
#define BF_GOL 19
__device__ __nv_bfloat16* const g_bf[20] = {
    g_x1h, g_x1l, g_x2h, g_x2l,
    g_wqh, g_wql, g_wkh, g_wkl, g_wvh, g_wvl, g_woh, g_wol,
    g_qh, g_ql, g_kh, g_kl, g_vh, g_vl, g_goh, g_gol
};

// Fused QKV operand table: {Ah, Al, Bh, Bl, Chi, Clo} per z
__device__ const int c_qkv[3][6] = {
    {BF_X1H, BF_X1L, BF_WQH, BF_WQL, BF_QH, BF_QL},
    {BF_X2H, BF_X2L, BF_WKH, BF_WKL, BF_KH, BF_KL},
    {BF_X2H, BF_X2L, BF_WVH, BF_WVL, BF_VH, BF_VL}
};

// ===========================================================================
// Helpers
// ===========================================================================
__device__ __forceinline__ uint32_t pack_bf16(float x, float y) {
    __nv_bfloat162 v = __floats2bfloat162_rn(x, y);   // .x = low = x
    return *(uint32_t*)&v;
}

__device__ __forceinline__ void mma_bf16(float* c, const uint32_t* a,
                                         const uint32_t* b) {
    asm volatile(
        "mma.sync.aligned.m16n8k16.row.col.f32.bf16.bf16.f32 "
        "{%0,%1,%2,%3}, {%4,%5,%6,%7}, {%8,%9}, {%0,%1,%2,%3};"
        : "+f"(c[0]), "+f"(c[1]), "+f"(c[2]), "+f"(c[3])
        : "r"(a[0]), "r"(a[1]), "r"(a[2]), "r"(a[3]),
          "r"(b[0]), "r"(b[1]));
}

__device__ __forceinline__ void cp16(void* smem_dst, const void* gsrc) {
    uint32_t d = (uint32_t)__cvta_generic_to_shared(smem_dst);
    asm volatile("cp.async.cg.shared.global [%0], [%1], 16;"
                 :: "r"(d), "l"(gsrc));
}
#define CP_COMMIT() asm volatile("cp.async.commit_group;" ::: "memory")
#define CP_WAIT(n)  asm volatile("cp.async.wait_group %0;" :: "n"(n) : "memory")

__device__ __forceinline__ uint32_t smem_u32(const void* p) {
    return (uint32_t)__cvta_generic_to_shared(p);
}
__device__ __forceinline__ void ldm_x4(uint32_t* r, uint32_t addr) {
    asm volatile("ldmatrix.sync.aligned.m8n8.x4.shared.b16 {%0,%1,%2,%3}, [%4];"
                 : "=r"(r[0]), "=r"(r[1]), "=r"(r[2]), "=r"(r[3]) : "r"(addr));
}
__device__ __forceinline__ void ldm_x4_t(uint32_t* r, uint32_t addr) {
    asm volatile("ldmatrix.sync.aligned.m8n8.x4.trans.shared.b16 {%0,%1,%2,%3}, [%4];"
                 : "=r"(r[0]), "=r"(r[1]), "=r"(r[2]), "=r"(r[3]) : "r"(addr));
}

// ===========================================================================
// fp32 -> (bf16 hi, bf16 lo) splits, fused launches.
// ===========================================================================
__global__ void split2_kernel(const float* __restrict__ s0,
                              const float* __restrict__ s1, int n) {
    const float* src = (blockIdx.y == 0) ? s0 : s1;
    __nv_bfloat16* hi = (blockIdx.y == 0) ? g_x1h : g_x2h;
    __nv_bfloat16* lo = (blockIdx.y == 0) ? g_x1l : g_x2l;
    for (int i = blockIdx.x * blockDim.x + threadIdx.x; i < n;
         i += gridDim.x * blockDim.x) {
        float x = src[i];
        __nv_bfloat16 h = __float2bfloat16_rn(x);
        hi[i] = h;
        lo[i] = __float2bfloat16_rn(x - __bfloat162float(h));
    }
}

__global__ void split4_kernel(const float* __restrict__ s0,
                              const float* __restrict__ s1,
                              const float* __restrict__ s2,
                              const float* __restrict__ s3, int n) {
    int w = blockIdx.y;
    const float* src = (w == 0) ? s0 : (w == 1) ? s1 : (w == 2) ? s2 : s3;
    __nv_bfloat16* hi = g_bf[BF_WQH + 2 * w];
    __nv_bfloat16* lo = g_bf[BF_WQL + 2 * w];
    for (int i = blockIdx.x * blockDim.x + threadIdx.x; i < n;
         i += gridDim.x * blockDim.x) {
        float x = src[i];
        __nv_bfloat16 h = __float2bfloat16_rn(x);
        hi[i] = h;
        lo[i] = __float2bfloat16_rn(x - __bfloat162float(h));
    }
}

// ===========================================================================
// Split-bf16 tensor-core GEMM: C = A * Bw^T (+bias), C = Ah*Bh+Ah*Bl+Al*Bh.
// Two-stage cp.async pipeline, K chunk 64, ldmatrix.x4 fragments with
// cross-ks register double-buffering.
// fused=1: operand indices from c_qkv[blockIdx.z], split-bf16 epilogue.
// ===========================================================================
#define BKC 64
#define APAD 72
#define GTILE (128 * APAD)
#define GSTAGE (4 * GTILE)
#define GEMM_SMEM_BYTES (2 * GSTAGE * 2)  // 147456 B
#define NCHUNK (GM_K / BKC)               // 16

#define LOAD_FRAGS(DST_AH, DST_AL, DST_BH, DST_BL, KK)                        \
    do {                                                                      \
        _Pragma("unroll")                                                     \
        for (int mf = 0; mf < 4; mf++) {                                      \
            int r = wm * 64 + mf * 16 + a_ro;                                 \
            ldm_x4(DST_AH[mf], smem_u32(&Ahs[r * APAD + (KK) + a_co]));       \
            ldm_x4(DST_AL[mf], smem_u32(&Als[r * APAD + (KK) + a_co]));       \
        }                                                                     \
        _Pragma("unroll")                                                     \
        for (int nfp = 0; nfp < 2; nfp++) {                                   \
            int cc = wn * 32 + nfp * 16 + b_ro;                               \
            uint32_t b4h[4], b4l[4];                                          \
            ldm_x4(b4h, smem_u32(&Bhs[cc * APAD + (KK) + b_co]));             \
            ldm_x4(b4l, smem_u32(&Bls[cc * APAD + (KK) + b_co]));             \
            DST_BH[2*nfp][0] = b4h[0]; DST_BH[2*nfp][1] = b4h[1];             \
            DST_BH[2*nfp+1][0] = b4h[2]; DST_BH[2*nfp+1][1] = b4h[3];         \
            DST_BL[2*nfp][0] = b4l[0]; DST_BL[2*nfp][1] = b4l[1];             \
            DST_BL[2*nfp+1][0] = b4l[2]; DST_BL[2*nfp+1][1] = b4l[3];         \
        }                                                                     \
    } while (0)

__global__ __launch_bounds__(256, 1)
void gemm_mma(int fused, int ahIdx, int alIdx, int bhIdx, int blIdx,
              float* __restrict__ Cext, int hiIdx, int loIdx,
              const float* __restrict__ bias) {
    extern __shared__ __align__(16) __nv_bfloat16 dyn[];

    if (fused) {
        const int* tab = c_qkv[blockIdx.z];
        ahIdx = tab[0]; alIdx = tab[1];
        bhIdx = tab[2]; blIdx = tab[3];
        hiIdx = tab[4]; loIdx = tab[5];
    }

    const int t   = threadIdx.x;
    const int wid = t >> 5;
    const int lid = t & 31;
    const int wm  = wid >> 2;
    const int wn  = wid & 3;
    const int n0  = blockIdx.x * 128;
    const int m0  = blockIdx.y * 128;
    const int qr  = lid >> 2;
    const int qc  = (lid & 3) * 2;

    const int a_ro = (lid & 7) + (lid & 8);
    const int a_co = (lid & 16) >> 1;
    const int b_ro = (lid & 7) + ((lid & 16) >> 1);
    const int b_co = (lid & 8);

    const __nv_bfloat16* pAh = g_bf[ahIdx] + (size_t)m0 * GM_K;
    const __nv_bfloat16* pAl = g_bf[alIdx] + (size_t)m0 * GM_K;
    const __nv_bfloat16* pBh = g_bf[bhIdx] + (size_t)n0 * GM_K;
    const __nv_bfloat16* pBl = g_bf[blIdx] + (size_t)n0 * GM_K;

    float acc[4][4][4];
    #pragma unroll
    for (int i = 0; i < 4; i++)
        #pragma unroll
        for (int j = 0; j < 4; j++)
            #pragma unroll
            for (int q = 0; q < 4; q++) acc[i][j][q] = 0.f;

    auto load_stage = [&](int stage, int k0) {
        __nv_bfloat16* s = dyn + stage * GSTAGE;
        #pragma unroll
        for (int i = 0; i < 4; i++) {
            int unit = t + i * 256;
            int r  = unit >> 3;
            int c8 = (unit & 7) * 8;
            size_t g = (size_t)r * GM_K + k0 + c8;
            int so = r * APAD + c8;
            cp16(&s[0 * GTILE + so], pAh + g);
            cp16(&s[1 * GTILE + so], pAl + g);
            cp16(&s[2 * GTILE + so], pBh + g);
            cp16(&s[3 * GTILE + so], pBl + g);
        }
    };

    load_stage(0, 0);
    CP_COMMIT();

    for (int c = 0; c < NCHUNK; c++) {
        if (c + 1 < NCHUNK) {
            load_stage((c + 1) & 1, (c + 1) * BKC);
            CP_COMMIT();
            CP_WAIT(1);
        } else {
            CP_WAIT(0);
        }
        __syncthreads();

        const __nv_bfloat16* Ahs = dyn + (c & 1) * GSTAGE + 0 * GTILE;
        const __nv_bfloat16* Als = dyn + (c & 1) * GSTAGE + 1 * GTILE;
        const __nv_bfloat16* Bhs = dyn + (c & 1) * GSTAGE + 2 * GTILE;
        const __nv_bfloat16* Bls = dyn + (c & 1) * GSTAGE + 3 * GTILE;

        uint32_t ah[2][4][4], al[2][4][4], bh[2][4][2], bl[2][4][2];
        LOAD_FRAGS(ah[0], al[0], bh[0], bl[0], 0);

        #pragma unroll
        for (int ks = 0; ks < 4; ks++) {
            const int cur = ks & 1, nxt = cur ^ 1;
            #pragma unroll
            for (int mf = 0; mf < 4; mf++)
                #pragma unroll
                for (int nf = 0; nf < 4; nf++)
                    mma_bf16(acc[mf][nf], ah[cur][mf], bh[cur][nf]);
            if (ks < 3) {
                const int kk = (ks + 1) * 16;
                LOAD_FRAGS(ah[nxt], al[nxt], bh[nxt], bl[nxt], kk);
            }
            #pragma unroll
            for (int mf = 0; mf < 4; mf++)
                #pragma unroll
                for (int nf = 0; nf < 4; nf++)
                    mma_bf16(acc[mf][nf], ah[cur][mf], bl[cur][nf]);
            #pragma unroll
            for (int mf = 0; mf < 4; mf++)
                #pragma unroll
                for (int nf = 0; nf < 4; nf++)
                    mma_bf16(acc[mf][nf], al[cur][mf], bh[cur][nf]);
        }
        __syncthreads();
    }

    if (hiIdx >= 0) {
        __nv_bfloat16* Ch = g_bf[hiIdx];
        __nv_bfloat16* Cl = g_bf[loIdx];
        #pragma unroll
        for (int mf = 0; mf < 4; mf++) {
            int row = m0 + wm * 64 + mf * 16 + qr;
            #pragma unroll
            for (int nf = 0; nf < 4; nf++) {
                int col = n0 + wn * 32 + nf * 8 + qc;
                #pragma unroll
                for (int half = 0; half < 2; half++) {
                    int r = row + half * 8;
                    float v0 = acc[mf][nf][half * 2 + 0];
                    float v1 = acc[mf][nf][half * 2 + 1];
                    float h0 = __bfloat162float(__float2bfloat16_rn(v0));
                    float h1 = __bfloat162float(__float2bfloat16_rn(v1));
                    *(uint32_t*)&Ch[(size_t)r * GM_N + col] = pack_bf16(h0, h1);
                    *(uint32_t*)&Cl[(size_t)r * GM_N + col] =
                        pack_bf16(v0 - h0, v1 - h1);
                }
            }
        }
    } else {
        #pragma unroll
        for (int mf = 0; mf < 4; mf++) {
            int row = m0 + wm * 64 + mf * 16 + qr;
            #pragma unroll
            for (int nf = 0; nf < 4; nf++) {
                int col = n0 + wn * 32 + nf * 8 + qc;
                float b0 = bias ? bias[col] : 0.f;
                float b1 = bias ? bias[col + 1] : 0.f;
                float2 v0 = make_float2(acc[mf][nf][0] + b0, acc[mf][nf][1] + b1);
                float2 v1 = make_float2(acc[mf][nf][2] + b0, acc[mf][nf][3] + b1);
                *(float2*)(Cext + (size_t)row * GM_N + col) = v0;
                *(float2*)(Cext + (size_t)(row + 8) * GM_N + col) = v1;
            }
        }
    }
}

// ===========================================================================
// Flash attention via mma.sync, split-bf16, two-stage cp.async KV pipeline.
// Block: 128 threads = 4 warps; 64-row q tile.
// __launch_bounds__(128, 3): cap regs at 170 so 3 CTAs fit per SM
// (R15 profile: 177 regs blocked the 3rd CTA; occ stuck at 11.8%,
// tensor 58% because softmax phases can't overlap with only 2 CTAs).
// Smem: 3 x 73.7 KB = 221 KB <= 228 KB carve-out.
// ===========================================================================
#define AKT 64
#define KPAD 72
#define ATILE (AKT * KPAD)
#define ASTAGE (4 * ATILE)
#define ATTN_SMEM_BYTES (2 * ASTAGE * 2)  // 73728 B
#define NKT (NSEQ / AKT)                  // 32

__global__ __launch_bounds__(128, 3)
void attn_mma() {
    extern __shared__ __align__(16) __nv_bfloat16 adyn[];

    const int t   = threadIdx.x;
    const int wid = t >> 5;            // 0..3
    const int lid = t & 31;
    const int gr  = lid >> 2;
    const int qc  = (lid & 3) * 2;
    const int qt  = blockIdx.x;        // 0..31
    const int bh  = blockIdx.y;        // 0..31
    const int b   = bh >> 4;
    const int h   = bh & 15;
    const int n0  = qt * 64;
    const int row0 = n0 + wid * 16;

    const int kb_ro = (lid & 7) + ((lid & 16) >> 1);
    const int kb_co = (lid & 8);
    const int vb_ro = (lid & 7) + (lid & 8);
    const int vb_co = (lid & 16) >> 1;

    const size_t batch_off = (size_t)b * NSEQ * DIM + (size_t)h * HDIM;
    const __nv_bfloat16* Qh = g_qh + batch_off;
    const __nv_bfloat16* Ql = g_ql + batch_off;
    const __nv_bfloat16* Kh = g_kh + batch_off;
    const __nv_bfloat16* Kl = g_kl + batch_off;
    const __nv_bfloat16* Vh = g_vh + batch_off;
    const __nv_bfloat16* Vl = g_vl + batch_off;

    uint32_t qfh[4][4], qfl[4][4];
    {
        const int rA = row0 + gr;
        const int rB = rA + 8;
        #pragma unroll
        for (int kf = 0; kf < 4; kf++) {
            int c = kf * 16 + qc;
            qfh[kf][0] = *(const uint32_t*)&Qh[(size_t)rA * DIM + c];
            qfh[kf][1] = *(const uint32_t*)&Qh[(size_t)rB * DIM + c];
            qfh[kf][2] = *(const uint32_t*)&Qh[(size_t)rA * DIM + c + 8];
            qfh[kf][3] = *(const uint32_t*)&Qh[(size_t)rB * DIM + c + 8];
            qfl[kf][0] = *(const uint32_t*)&Ql[(size_t)rA * DIM + c];
            qfl[kf][1] = *(const uint32_t*)&Ql[(size_t)rB * DIM + c];
            qfl[kf][2] = *(const uint32_t*)&Ql[(size_t)rA * DIM + c + 8];
            qfl[kf][3] = *(const uint32_t*)&Ql[(size_t)rB * DIM + c + 8];
        }
    }

    // KV stage loader: 512 int4 units per array / 128 threads = 4 each
    auto load_kv = [&](int stage, int kv0) {
        __nv_bfloat16* s = adyn + stage * ASTAGE;
        #pragma unroll
        for (int i = 0; i < 4; i++) {
            int unit = t + i * 128;
            int r  = unit >> 3;
            int c8 = (unit & 7) * 8;
            size_t goff = (size_t)(kv0 + r) * DIM + c8;
            int so = r * KPAD + c8;
            cp16(&s[0 * ATILE + so], Kh + goff);
            cp16(&s[1 * ATILE + so], Kl + goff);
            cp16(&s[2 * ATILE + so], Vh + goff);
            cp16(&s[3 * ATILE + so], Vl + goff);
        }
    };

    float om0 = -1e30f, om1 = -1e30f;
    float osum0 = 0.f, osum1 = 0.f;
    float o[8][4];
    #pragma unroll
    for (int nf = 0; nf < 8; nf++)
        #pragma unroll
        for (int q = 0; q < 4; q++) o[nf][q] = 0.f;

    load_kv(0, 0);
    CP_COMMIT();

    for (int kt = 0; kt < NKT; kt++) {
        if (kt + 1 < NKT) {
            load_kv((kt + 1) & 1, (kt + 1) * AKT);
            CP_COMMIT();
            CP_WAIT(1);
        } else {
            CP_WAIT(0);
        }
        __syncthreads();

        const __nv_bfloat16* Khs = adyn + (kt & 1) * ASTAGE + 0 * ATILE;
        const __nv_bfloat16* Kls = adyn + (kt & 1) * ASTAGE + 1 * ATILE;
        const __nv_bfloat16* Vhs = adyn + (kt & 1) * ASTAGE + 2 * ATILE;
        const __nv_bfloat16* Vls = adyn + (kt & 1) * ASTAGE + 3 * ATILE;

        // S = Q K^T (split 3-product): preload K frags, then 3 passes
        float s[8][4];
        #pragma unroll
        for (int nf = 0; nf < 8; nf++)
            #pragma unroll
            for (int q = 0; q < 4; q++) s[nf][q] = 0.f;
        #pragma unroll
        for (int kf = 0; kf < 4; kf++) {
            const int kk = kf * 16;
            uint32_t kbh[4][4], kbl[4][4];
            #pragma unroll
            for (int nfp = 0; nfp < 4; nfp++) {
                int cc = nfp * 16 + kb_ro;
                ldm_x4(kbh[nfp], smem_u32(&Khs[cc * KPAD + kk + kb_co]));
                ldm_x4(kbl[nfp], smem_u32(&Kls[cc * KPAD + kk + kb_co]));
            }
            #pragma unroll
            for (int nfp = 0; nfp < 4; nfp++) {
                mma_bf16(s[2*nfp    ], qfh[kf], kbh[nfp] + 0);
                mma_bf16(s[2*nfp + 1], qfh[kf], kbh[nfp] + 2);
            }
            #pragma unroll
            for (int nfp = 0; nfp < 4; nfp++) {
                mma_bf16(s[2*nfp    ], qfh[kf], kbl[nfp] + 0);
                mma_bf16(s[2*nfp + 1], qfh[kf], kbl[nfp] + 2);
            }
            #pragma unroll
            for (int nfp = 0; nfp < 4; nfp++) {
                mma_bf16(s[2*nfp    ], qfl[kf], kbh[nfp] + 0);
                mma_bf16(s[2*nfp + 1], qfl[kf], kbh[nfp] + 2);
            }
        }

        // Online softmax. Row gr -> c0,c1; row gr+8 -> c2,c3.
        float tmax0 = -1e30f, tmax1 = -1e30f;
        #pragma unroll
        for (int nf = 0; nf < 8; nf++) {
            tmax0 = fmaxf(tmax0, fmaxf(s[nf][0], s[nf][1]));
            tmax1 = fmaxf(tmax1, fmaxf(s[nf][2], s[nf][3]));
        }
        tmax0 = fmaxf(tmax0, __shfl_xor_sync(0xffffffff, tmax0, 1));
        tmax0 = fmaxf(tmax0, __shfl_xor_sync(0xffffffff, tmax0, 2));
        tmax1 = fmaxf(tmax1, __shfl_xor_sync(0xffffffff, tmax1, 1));
        tmax1 = fmaxf(tmax1, __shfl_xor_sync(0xffffffff, tmax1, 2));

        float mn0 = fmaxf(om0, tmax0);
        float mn1 = fmaxf(om1, tmax1);
        float alpha0 = __expf((om0 - mn0) * ATT_SCALE);
        float alpha1 = __expf((om1 - mn1) * ATT_SCALE);
        om0 = mn0; om1 = mn1;

        uint32_t ph0[8], ph1[8], pl0[8], pl1[8];
        float lsum0 = 0.f, lsum1 = 0.f;
        #pragma unroll
        for (int nf = 0; nf < 8; nf++) {
            float p0 = __expf((s[nf][0] - mn0) * ATT_SCALE);
            float p1 = __expf((s[nf][1] - mn0) * ATT_SCALE);
            float p2 = __expf((s[nf][2] - mn1) * ATT_SCALE);
            float p3 = __expf((s[nf][3] - mn1) * ATT_SCALE);
            lsum0 += p0 + p1;
            lsum1 += p2 + p3;
            float h0 = __bfloat162float(__float2bfloat16_rn(p0));
            float h1 = __bfloat162float(__float2bfloat16_rn(p1));
            float h2 = __bfloat162float(__float2bfloat16_rn(p2));
            float h3 = __bfloat162float(__float2bfloat16_rn(p3));
            ph0[nf] = pack_bf16(h0, h1);
            ph1[nf] = pack_bf16(h2, h3);
            pl0[nf] = pack_bf16(p0 - h0, p1 - h1);
            pl1[nf] = pack_bf16(p2 - h2, p3 - h3);
        }
        lsum0 += __shfl_xor_sync(0xffffffff, lsum0, 1);
        lsum0 += __shfl_xor_sync(0xffffffff, lsum0, 2);
        lsum1 += __shfl_xor_sync(0xffffffff, lsum1, 1);
        lsum1 += __shfl_xor_sync(0xffffffff, lsum1, 2);
        osum0 = osum0 * alpha0 + lsum0;
        osum1 = osum1 * alpha1 + lsum1;

        #pragma unroll
        for (int nf = 0; nf < 8; nf++) {
            o[nf][0] *= alpha0; o[nf][1] *= alpha0;
            o[nf][2] *= alpha1; o[nf][3] *= alpha1;
        }

        // O += P V (split 3-product): preload V frags per kf, 3 passes
        #pragma unroll
        for (int kf = 0; kf < 4; kf++) {
            uint32_t pah[4] = {ph0[2*kf], ph1[2*kf], ph0[2*kf+1], ph1[2*kf+1]};
            uint32_t pal[4] = {pl0[2*kf], pl1[2*kf], pl0[2*kf+1], pl1[2*kf+1]};
            const int kk = kf * 16;
            uint32_t vbh[4][4], vbl[4][4];
            #pragma unroll
            for (int nfp = 0; nfp < 4; nfp++) {
                int rr = kk + vb_ro;
                int cc = nfp * 16 + vb_co;
                ldm_x4_t(vbh[nfp], smem_u32(&Vhs[rr * KPAD + cc]));
                ldm_x4_t(vbl[nfp], smem_u32(&Vls[rr * KPAD + cc]));
            }
            #pragma unroll
            for (int nfp = 0; nfp < 4; nfp++) {
                mma_bf16(o[2*nfp    ], pah, vbh[nfp] + 0);
                mma_bf16(o[2*nfp + 1], pah, vbh[nfp] + 2);
            }
            #pragma unroll
            for (int nfp = 0; nfp < 4; nfp++) {
                mma_bf16(o[2*nfp    ], pah, vbl[nfp] + 0);
                mma_bf16(o[2*nfp + 1], pah, vbl[nfp] + 2);
            }
            #pragma unroll
            for (int nfp = 0; nfp < 4; nfp++) {
                mma_bf16(o[2*nfp    ], pal, vbh[nfp] + 0);
                mma_bf16(o[2*nfp + 1], pal, vbh[nfp] + 2);
            }
        }
        __syncthreads();
    }

    // Epilogue: normalize, split, store to g_goh/g_gol
    const float inv0 = 1.0f / osum0;
    const float inv1 = 1.0f / osum1;
    const int rowA = b * NSEQ + row0 + gr;
    #pragma unroll
    for (int nf = 0; nf < 8; nf++) {
        int col = h * HDIM + nf * 8 + qc;
        float v0 = o[nf][0] * inv0;
        float v1 = o[nf][1] * inv0;
        float v2 = o[nf][2] * inv1;
        float v3 = o[nf][3] * inv1;
        float h0 = __bfloat162float(__float2bfloat16_rn(v0));
        float h1 = __bfloat162float(__float2bfloat16_rn(v1));
        float h2 = __bfloat162float(__float2bfloat16_rn(v2));
        float h3 = __bfloat162float(__float2bfloat16_rn(v3));
        *(uint32_t*)&g_goh[(size_t)rowA * DIM + col] = pack_bf16(h0, h1);
        *(uint32_t*)&g_gol[(size_t)rowA * DIM + col] = pack_bf16(v0 - h0, v1 - h1);
        *(uint32_t*)&g_goh[(size_t)(rowA + 8) * DIM + col] = pack_bf16(h2, h3);
        *(uint32_t*)&g_gol[(size_t)(rowA + 8) * DIM + col] = pack_bf16(v2 - h2, v3 - h3);
    }
}

// ===========================================================================
// Launch
// ===========================================================================
extern "C" void kernel_launch(void* const* d_in, const int* in_sizes, int n_in,
                              void* d_out, int out_size) {
    const float* x1 = (const float*)d_in[0];
    const float* x2 = (const float*)d_in[1];
    const float* wq = (const float*)d_in[2];
    const float* wk = (const float*)d_in[3];
    const float* wv = (const float*)d_in[4];
    const float* wo = (const float*)d_in[5];
    const float* bo = (const float*)d_in[6];
    float* out = (float*)d_out;

    const int NX = MROWS * DIM;
    const int NW = DIM * DIM;

    cudaFuncSetAttribute(gemm_mma,
                         cudaFuncAttributeMaxDynamicSharedMemorySize,
                         GEMM_SMEM_BYTES);
    cudaFuncSetAttribute(attn_mma,
                         cudaFuncAttributeMaxDynamicSharedMemorySize,
                         ATTN_SMEM_BYTES);

    split2_kernel<<<dim3(512, 2), 256>>>(x1, x2, NX);
    split4_kernel<<<dim3(256, 4), 256>>>(wq, wk, wv, wo, NW);

    // Fused Q/K/V projections: one launch, 3 z-slices
    gemm_mma<<<dim3(GM_N / 128, GM_M / 128, 3), 256, GEMM_SMEM_BYTES>>>(
        1, 0, 0, 0, 0, nullptr, 0, 0, nullptr);

    attn_mma<<<dim3(NSEQ / 64, B * HEADS), 128, ATTN_SMEM_BYTES>>>();

    gemm_mma<<<dim3(GM_N / 128, GM_M / 128, 1), 256, GEMM_SMEM_BYTES>>>(
        0, BF_GOH, BF_GOL, BF_WOH, BF_WOL, out, -1, -1, bo);
}

// round 17
// speedup vs baseline: 3.3750x; 1.0003x over previous
#include <cuda_runtime.h>
#include <cuda_bf16.h>
#include <cstdint>
#include <math.h>

// Problem shapes (fixed)
#define B 2
#define NSEQ 2048
#define DIM 1024
#define HEADS 16
#define HDIM 64
#define MROWS (B * NSEQ)   // 4096
#define ATT_SCALE 0.125f   // 64^-0.5

#define GM_M 4096
#define GM_N 1024
#define GM_K 1024

// ===========================================================================
// Scratch: bf16 hi/lo split arrays (device globals)
// ===========================================================================
__device__ __nv_bfloat16 g_x1h[MROWS * DIM];
__device__ __nv_bfloat16 g_x1l[MROWS * DIM];
__device__ __nv_bfloat16 g_x2h[MROWS * DIM];
__device__ __nv_bfloat16 g_x2l[MROWS * DIM];
__device__ __nv_bfloat16 g_wqh[DIM * DIM];
__device__ __nv_bfloat16 g_wql[DIM * DIM];
__device__ __nv_bfloat16 g_wkh[DIM * DIM];
__device__ __nv_bfloat16 g_wkl[DIM * DIM];
__device__ __nv_bfloat16 g_wvh[DIM * DIM];
__device__ __nv_bfloat16 g_wvl[DIM * DIM];
__device__ __nv_bfloat16 g_woh[DIM * DIM];
__device__ __nv_bfloat16 g_wol[DIM * DIM];
__device__ __nv_bfloat16 g_qh[MROWS * DIM];
__device__ __nv_bfloat16 g_ql[MROWS * DIM];
__device__ __nv_bfloat16 g_kh[MROWS * DIM];
__device__ __nv_bfloat16 g_kl[MROWS * DIM];
__device__ __nv_bfloat16 g_vh[MROWS * DIM];
__device__ __nv_bfloat16 g_vl[MROWS * DIM];
__device__ __nv_bfloat16 g_goh[MROWS * DIM];
__device__ __nv_bfloat16 g_gol[MROWS * DIM];

#define BF_X1H 0
#define BF_X1L 1
#define BF_X2H 2
#define BF_X2L 3
#define BF_WQH 4
#define BF_WQL 5
#define BF_WKH 6
#define BF_WKL 7
#define BF_WVH 8
#define BF_WVL 9
#define BF_WOH 10
#define BF_WOL 11
#define BF_QH 12
#define BF_QL 13
#define BF_KH 14
#define BF_KL 15
#define BF_VH 16
#define BF_VL 17
#define BF_GOH 18
#define BF_GOL 19
__device__ __nv_bfloat16* const g_bf[20] = {
    g_x1h, g_x1l, g_x2h, g_x2l,
    g_wqh, g_wql, g_wkh, g_wkl, g_wvh, g_wvl, g_woh, g_wol,
    g_qh, g_ql, g_kh, g_kl, g_vh, g_vl, g_goh, g_gol
};

// Fused QKV operand table: {Ah, Al, Bh, Bl, Chi, Clo} per z
__device__ const int c_qkv[3][6] = {
    {BF_X1H, BF_X1L, BF_WQH, BF_WQL, BF_QH, BF_QL},
    {BF_X2H, BF_X2L, BF_WKH, BF_WKL, BF_KH, BF_KL},
    {BF_X2H, BF_X2L, BF_WVH, BF_WVL, BF_VH, BF_VL}
};

// ===========================================================================
// Helpers
// ===========================================================================
__device__ __forceinline__ uint32_t pack_bf16(float x, float y) {
    __nv_bfloat162 v = __floats2bfloat162_rn(x, y);   // .x = low = x
    return *(uint32_t*)&v;
}

__device__ __forceinline__ void mma_bf16(float* c, const uint32_t* a,
                                         const uint32_t* b) {
    asm volatile(
        "mma.sync.aligned.m16n8k16.row.col.f32.bf16.bf16.f32 "
        "{%0,%1,%2,%3}, {%4,%5,%6,%7}, {%8,%9}, {%0,%1,%2,%3};"
        : "+f"(c[0]), "+f"(c[1]), "+f"(c[2]), "+f"(c[3])
        : "r"(a[0]), "r"(a[1]), "r"(a[2]), "r"(a[3]),
          "r"(b[0]), "r"(b[1]));
}

__device__ __forceinline__ void cp16(void* smem_dst, const void* gsrc) {
    uint32_t d = (uint32_t)__cvta_generic_to_shared(smem_dst);
    asm volatile("cp.async.cg.shared.global [%0], [%1], 16;"
                 :: "r"(d), "l"(gsrc));
}
#define CP_COMMIT() asm volatile("cp.async.commit_group;" ::: "memory")
#define CP_WAIT(n)  asm volatile("cp.async.wait_group %0;" :: "n"(n) : "memory")

__device__ __forceinline__ uint32_t smem_u32(const void* p) {
    return (uint32_t)__cvta_generic_to_shared(p);
}
__device__ __forceinline__ void ldm_x4(uint32_t* r, uint32_t addr) {
    asm volatile("ldmatrix.sync.aligned.m8n8.x4.shared.b16 {%0,%1,%2,%3}, [%4];"
                 : "=r"(r[0]), "=r"(r[1]), "=r"(r[2]), "=r"(r[3]) : "r"(addr));
}
__device__ __forceinline__ void ldm_x4_t(uint32_t* r, uint32_t addr) {
    asm volatile("ldmatrix.sync.aligned.m8n8.x4.trans.shared.b16 {%0,%1,%2,%3}, [%4];"
                 : "=r"(r[0]), "=r"(r[1]), "=r"(r[2]), "=r"(r[3]) : "r"(addr));
}

// ===========================================================================
// fp32 -> (bf16 hi, bf16 lo) splits, fused launches.
// ===========================================================================
__global__ void split2_kernel(const float* __restrict__ s0,
                              const float* __restrict__ s1, int n) {
    const float* src = (blockIdx.y == 0) ? s0 : s1;
    __nv_bfloat16* hi = (blockIdx.y == 0) ? g_x1h : g_x2h;
    __nv_bfloat16* lo = (blockIdx.y == 0) ? g_x1l : g_x2l;
    for (int i = blockIdx.x * blockDim.x + threadIdx.x; i < n;
         i += gridDim.x * blockDim.x) {
        float x = src[i];
        __nv_bfloat16 h = __float2bfloat16_rn(x);
        hi[i] = h;
        lo[i] = __float2bfloat16_rn(x - __bfloat162float(h));
    }
}

__global__ void split4_kernel(const float* __restrict__ s0,
                              const float* __restrict__ s1,
                              const float* __restrict__ s2,
                              const float* __restrict__ s3, int n) {
    int w = blockIdx.y;
    const float* src = (w == 0) ? s0 : (w == 1) ? s1 : (w == 2) ? s2 : s3;
    __nv_bfloat16* hi = g_bf[BF_WQH + 2 * w];
    __nv_bfloat16* lo = g_bf[BF_WQL + 2 * w];
    for (int i = blockIdx.x * blockDim.x + threadIdx.x; i < n;
         i += gridDim.x * blockDim.x) {
        float x = src[i];
        __nv_bfloat16 h = __float2bfloat16_rn(x);
        hi[i] = h;
        lo[i] = __float2bfloat16_rn(x - __bfloat162float(h));
    }
}

// ===========================================================================
// Split-bf16 tensor-core GEMM: C = A * Bw^T (+bias), C = Ah*Bh+Ah*Bl+Al*Bh.
// 128-thread CTA, 128x64 output tile (4 warps 2x2, warp tile 64x32) so
// TWO CTAs fit per SM (smem 110.6 KB x2 = 221 KB; regs free at 256/thr):
// cross-CTA overlap hides barriers + pipeline bubbles (R13: 1-CTA config
// stuck at tensor 49.8%). Two-stage cp.async, K chunk 64, ldmatrix.x4
// with cross-ks register double-buffering. Per-element accumulation order
// unchanged -> bit-identical results.
// ===========================================================================
#define BKC 64
#define APAD 72
#define GT_A (128 * APAD)              // A tile elems (per split half)
#define GT_B (64 * APAD)               // B tile elems (per split half)
#define GSTAGE (2 * GT_A + 2 * GT_B)   // elems per stage
#define GEMM_SMEM_BYTES (2 * GSTAGE * 2)  // 110592 B
#define NCHUNK (GM_K / BKC)               // 16

#define LOAD_FRAGS(DST_AH, DST_AL, DST_BH, DST_BL, KK)                        \
    do {                                                                      \
        _Pragma("unroll")                                                     \
        for (int mf = 0; mf < 4; mf++) {                                      \
            int r = wm * 64 + mf * 16 + a_ro;                                 \
            ldm_x4(DST_AH[mf], smem_u32(&Ahs[r * APAD + (KK) + a_co]));       \
            ldm_x4(DST_AL[mf], smem_u32(&Als[r * APAD + (KK) + a_co]));       \
        }                                                                     \
        _Pragma("unroll")                                                     \
        for (int nfp = 0; nfp < 2; nfp++) {                                   \
            int cc = wn * 32 + nfp * 16 + b_ro;                               \
            uint32_t b4h[4], b4l[4];                                          \
            ldm_x4(b4h, smem_u32(&Bhs[cc * APAD + (KK) + b_co]));             \
            ldm_x4(b4l, smem_u32(&Bls[cc * APAD + (KK) + b_co]));             \
            DST_BH[2*nfp][0] = b4h[0]; DST_BH[2*nfp][1] = b4h[1];             \
            DST_BH[2*nfp+1][0] = b4h[2]; DST_BH[2*nfp+1][1] = b4h[3];         \
            DST_BL[2*nfp][0] = b4l[0]; DST_BL[2*nfp][1] = b4l[1];             \
            DST_BL[2*nfp+1][0] = b4l[2]; DST_BL[2*nfp+1][1] = b4l[3];         \
        }                                                                     \
    } while (0)

__global__ __launch_bounds__(128, 2)
void gemm_mma(int fused, int ahIdx, int alIdx, int bhIdx, int blIdx,
              float* __restrict__ Cext, int hiIdx, int loIdx,
              const float* __restrict__ bias) {
    extern __shared__ __align__(16) __nv_bfloat16 dyn[];

    if (fused) {
        const int* tab = c_qkv[blockIdx.z];
        ahIdx = tab[0]; alIdx = tab[1];
        bhIdx = tab[2]; blIdx = tab[3];
        hiIdx = tab[4]; loIdx = tab[5];
    }

    const int t   = threadIdx.x;
    const int wid = t >> 5;            // 0..3
    const int lid = t & 31;
    const int wm  = wid >> 1;          // 0..1
    const int wn  = wid & 1;           // 0..1
    const int n0  = blockIdx.x * 64;
    const int m0  = blockIdx.y * 128;
    const int qr  = lid >> 2;
    const int qc  = (lid & 3) * 2;

    const int a_ro = (lid & 7) + (lid & 8);
    const int a_co = (lid & 16) >> 1;
    const int b_ro = (lid & 7) + ((lid & 16) >> 1);
    const int b_co = (lid & 8);

    const __nv_bfloat16* pAh = g_bf[ahIdx] + (size_t)m0 * GM_K;
    const __nv_bfloat16* pAl = g_bf[alIdx] + (size_t)m0 * GM_K;
    const __nv_bfloat16* pBh = g_bf[bhIdx] + (size_t)n0 * GM_K;
    const __nv_bfloat16* pBl = g_bf[blIdx] + (size_t)n0 * GM_K;

    float acc[4][4][4];
    #pragma unroll
    for (int i = 0; i < 4; i++)
        #pragma unroll
        for (int j = 0; j < 4; j++)
            #pragma unroll
            for (int q = 0; q < 4; q++) acc[i][j][q] = 0.f;

    // stage layout: [Ah(128x72) | Al(128x72) | Bh(64x72) | Bl(64x72)]
    auto load_stage = [&](int stage, int k0) {
        __nv_bfloat16* s = dyn + stage * GSTAGE;
        // A tiles: 128x64 -> 1024 int4 units / 128 thr = 8 each
        #pragma unroll
        for (int i = 0; i < 8; i++) {
            int unit = t + i * 128;
            int r  = unit >> 3;
            int c8 = (unit & 7) * 8;
            size_t g = (size_t)r * GM_K + k0 + c8;
            int so = r * APAD + c8;
            cp16(&s[so], pAh + g);
            cp16(&s[GT_A + so], pAl + g);
        }
        // B tiles: 64x64 -> 512 int4 units / 128 thr = 4 each
        #pragma unroll
        for (int i = 0; i < 4; i++) {
            int unit = t + i * 128;
            int r  = unit >> 3;
            int c8 = (unit & 7) * 8;
            size_t g = (size_t)r * GM_K + k0 + c8;
            int so = r * APAD + c8;
            cp16(&s[2 * GT_A + so], pBh + g);
            cp16(&s[2 * GT_A + GT_B + so], pBl + g);
        }
    };

    load_stage(0, 0);
    CP_COMMIT();

    for (int c = 0; c < NCHUNK; c++) {
        if (c + 1 < NCHUNK) {
            load_stage((c + 1) & 1, (c + 1) * BKC);
            CP_COMMIT();
            CP_WAIT(1);
        } else {
            CP_WAIT(0);
        }
        __syncthreads();

        const __nv_bfloat16* Ahs = dyn + (c & 1) * GSTAGE;
        const __nv_bfloat16* Als = Ahs + GT_A;
        const __nv_bfloat16* Bhs = Ahs + 2 * GT_A;
        const __nv_bfloat16* Bls = Ahs + 2 * GT_A + GT_B;

        uint32_t ah[2][4][4], al[2][4][4], bh[2][4][2], bl[2][4][2];
        LOAD_FRAGS(ah[0], al[0], bh[0], bl[0], 0);

        #pragma unroll
        for (int ks = 0; ks < 4; ks++) {
            const int cur = ks & 1, nxt = cur ^ 1;
            #pragma unroll
            for (int mf = 0; mf < 4; mf++)
                #pragma unroll
                for (int nf = 0; nf < 4; nf++)
                    mma_bf16(acc[mf][nf], ah[cur][mf], bh[cur][nf]);
            if (ks < 3) {
                const int kk = (ks + 1) * 16;
                LOAD_FRAGS(ah[nxt], al[nxt], bh[nxt], bl[nxt], kk);
            }
            #pragma unroll
            for (int mf = 0; mf < 4; mf++)
                #pragma unroll
                for (int nf = 0; nf < 4; nf++)
                    mma_bf16(acc[mf][nf], ah[cur][mf], bl[cur][nf]);
            #pragma unroll
            for (int mf = 0; mf < 4; mf++)
                #pragma unroll
                for (int nf = 0; nf < 4; nf++)
                    mma_bf16(acc[mf][nf], al[cur][mf], bh[cur][nf]);
        }
        __syncthreads();
    }

    if (hiIdx >= 0) {
        __nv_bfloat16* Ch = g_bf[hiIdx];
        __nv_bfloat16* Cl = g_bf[loIdx];
        #pragma unroll
        for (int mf = 0; mf < 4; mf++) {
            int row = m0 + wm * 64 + mf * 16 + qr;
            #pragma unroll
            for (int nf = 0; nf < 4; nf++) {
                int col = n0 + wn * 32 + nf * 8 + qc;
                #pragma unroll
                for (int half = 0; half < 2; half++) {
                    int r = row + half * 8;
                    float v0 = acc[mf][nf][half * 2 + 0];
                    float v1 = acc[mf][nf][half * 2 + 1];
                    float h0 = __bfloat162float(__float2bfloat16_rn(v0));
                    float h1 = __bfloat162float(__float2bfloat16_rn(v1));
                    *(uint32_t*)&Ch[(size_t)r * GM_N + col] = pack_bf16(h0, h1);
                    *(uint32_t*)&Cl[(size_t)r * GM_N + col] =
                        pack_bf16(v0 - h0, v1 - h1);
                }
            }
        }
    } else {
        #pragma unroll
        for (int mf = 0; mf < 4; mf++) {
            int row = m0 + wm * 64 + mf * 16 + qr;
            #pragma unroll
            for (int nf = 0; nf < 4; nf++) {
                int col = n0 + wn * 32 + nf * 8 + qc;
                float b0 = bias ? bias[col] : 0.f;
                float b1 = bias ? bias[col + 1] : 0.f;
                float2 v0 = make_float2(acc[mf][nf][0] + b0, acc[mf][nf][1] + b1);
                float2 v1 = make_float2(acc[mf][nf][2] + b0, acc[mf][nf][3] + b1);
                *(float2*)(Cext + (size_t)row * GM_N + col) = v0;
                *(float2*)(Cext + (size_t)(row + 8) * GM_N + col) = v1;
            }
        }
    }
}

// ===========================================================================
// Flash attention via mma.sync, split-bf16, two-stage cp.async KV pipeline.
// Block: 128 threads = 4 warps; 64-row q tile. __launch_bounds__(128, 3).
// ===========================================================================
#define AKT 64
#define KPAD 72
#define ATILE (AKT * KPAD)
#define ASTAGE (4 * ATILE)
#define ATTN_SMEM_BYTES (2 * ASTAGE * 2)  // 73728 B
#define NKT (NSEQ / AKT)                  // 32

__global__ __launch_bounds__(128, 3)
void attn_mma() {
    extern __shared__ __align__(16) __nv_bfloat16 adyn[];

    const int t   = threadIdx.x;
    const int wid = t >> 5;            // 0..3
    const int lid = t & 31;
    const int gr  = lid >> 2;
    const int qc  = (lid & 3) * 2;
    const int qt  = blockIdx.x;        // 0..31
    const int bh  = blockIdx.y;        // 0..31
    const int b   = bh >> 4;
    const int h   = bh & 15;
    const int n0  = qt * 64;
    const int row0 = n0 + wid * 16;

    const int kb_ro = (lid & 7) + ((lid & 16) >> 1);
    const int kb_co = (lid & 8);
    const int vb_ro = (lid & 7) + (lid & 8);
    const int vb_co = (lid & 16) >> 1;

    const size_t batch_off = (size_t)b * NSEQ * DIM + (size_t)h * HDIM;
    const __nv_bfloat16* Qh = g_qh + batch_off;
    const __nv_bfloat16* Ql = g_ql + batch_off;
    const __nv_bfloat16* Kh = g_kh + batch_off;
    const __nv_bfloat16* Kl = g_kl + batch_off;
    const __nv_bfloat16* Vh = g_vh + batch_off;
    const __nv_bfloat16* Vl = g_vl + batch_off;

    uint32_t qfh[4][4], qfl[4][4];
    {
        const int rA = row0 + gr;
        const int rB = rA + 8;
        #pragma unroll
        for (int kf = 0; kf < 4; kf++) {
            int c = kf * 16 + qc;
            qfh[kf][0] = *(const uint32_t*)&Qh[(size_t)rA * DIM + c];
            qfh[kf][1] = *(const uint32_t*)&Qh[(size_t)rB * DIM + c];
            qfh[kf][2] = *(const uint32_t*)&Qh[(size_t)rA * DIM + c + 8];
            qfh[kf][3] = *(const uint32_t*)&Qh[(size_t)rB * DIM + c + 8];
            qfl[kf][0] = *(const uint32_t*)&Ql[(size_t)rA * DIM + c];
            qfl[kf][1] = *(const uint32_t*)&Ql[(size_t)rB * DIM + c];
            qfl[kf][2] = *(const uint32_t*)&Ql[(size_t)rA * DIM + c + 8];
            qfl[kf][3] = *(const uint32_t*)&Ql[(size_t)rB * DIM + c + 8];
        }
    }

    auto load_kv = [&](int stage, int kv0) {
        __nv_bfloat16* s = adyn + stage * ASTAGE;
        #pragma unroll
        for (int i = 0; i < 4; i++) {
            int unit = t + i * 128;
            int r  = unit >> 3;
            int c8 = (unit & 7) * 8;
            size_t goff = (size_t)(kv0 + r) * DIM + c8;
            int so = r * KPAD + c8;
            cp16(&s[0 * ATILE + so], Kh + goff);
            cp16(&s[1 * ATILE + so], Kl + goff);
            cp16(&s[2 * ATILE + so], Vh + goff);
            cp16(&s[3 * ATILE + so], Vl + goff);
        }
    };

    float om0 = -1e30f, om1 = -1e30f;
    float osum0 = 0.f, osum1 = 0.f;
    float o[8][4];
    #pragma unroll
    for (int nf = 0; nf < 8; nf++)
        #pragma unroll
        for (int q = 0; q < 4; q++) o[nf][q] = 0.f;

    load_kv(0, 0);
    CP_COMMIT();

    for (int kt = 0; kt < NKT; kt++) {
        if (kt + 1 < NKT) {
            load_kv((kt + 1) & 1, (kt + 1) * AKT);
            CP_COMMIT();
            CP_WAIT(1);
        } else {
            CP_WAIT(0);
        }
        __syncthreads();

        const __nv_bfloat16* Khs = adyn + (kt & 1) * ASTAGE + 0 * ATILE;
        const __nv_bfloat16* Kls = adyn + (kt & 1) * ASTAGE + 1 * ATILE;
        const __nv_bfloat16* Vhs = adyn + (kt & 1) * ASTAGE + 2 * ATILE;
        const __nv_bfloat16* Vls = adyn + (kt & 1) * ASTAGE + 3 * ATILE;

        float s[8][4];
        #pragma unroll
        for (int nf = 0; nf < 8; nf++)
            #pragma unroll
            for (int q = 0; q < 4; q++) s[nf][q] = 0.f;
        #pragma unroll
        for (int kf = 0; kf < 4; kf++) {
            const int kk = kf * 16;
            uint32_t kbh[4][4], kbl[4][4];
            #pragma unroll
            for (int nfp = 0; nfp < 4; nfp++) {
                int cc = nfp * 16 + kb_ro;
                ldm_x4(kbh[nfp], smem_u32(&Khs[cc * KPAD + kk + kb_co]));
                ldm_x4(kbl[nfp], smem_u32(&Kls[cc * KPAD + kk + kb_co]));
            }
            #pragma unroll
            for (int nfp = 0; nfp < 4; nfp++) {
                mma_bf16(s[2*nfp    ], qfh[kf], kbh[nfp] + 0);
                mma_bf16(s[2*nfp + 1], qfh[kf], kbh[nfp] + 2);
            }
            #pragma unroll
            for (int nfp = 0; nfp < 4; nfp++) {
                mma_bf16(s[2*nfp    ], qfh[kf], kbl[nfp] + 0);
                mma_bf16(s[2*nfp + 1], qfh[kf], kbl[nfp] + 2);
            }
            #pragma unroll
            for (int nfp = 0; nfp < 4; nfp++) {
                mma_bf16(s[2*nfp    ], qfl[kf], kbh[nfp] + 0);
                mma_bf16(s[2*nfp + 1], qfl[kf], kbh[nfp] + 2);
            }
        }

        float tmax0 = -1e30f, tmax1 = -1e30f;
        #pragma unroll
        for (int nf = 0; nf < 8; nf++) {
            tmax0 = fmaxf(tmax0, fmaxf(s[nf][0], s[nf][1]));
            tmax1 = fmaxf(tmax1, fmaxf(s[nf][2], s[nf][3]));
        }
        tmax0 = fmaxf(tmax0, __shfl_xor_sync(0xffffffff, tmax0, 1));
        tmax0 = fmaxf(tmax0, __shfl_xor_sync(0xffffffff, tmax0, 2));
        tmax1 = fmaxf(tmax1, __shfl_xor_sync(0xffffffff, tmax1, 1));
        tmax1 = fmaxf(tmax1, __shfl_xor_sync(0xffffffff, tmax1, 2));

        float mn0 = fmaxf(om0, tmax0);
        float mn1 = fmaxf(om1, tmax1);
        float alpha0 = __expf((om0 - mn0) * ATT_SCALE);
        float alpha1 = __expf((om1 - mn1) * ATT_SCALE);
        om0 = mn0; om1 = mn1;

        uint32_t ph0[8], ph1[8], pl0[8], pl1[8];
        float lsum0 = 0.f, lsum1 = 0.f;
        #pragma unroll
        for (int nf = 0; nf < 8; nf++) {
            float p0 = __expf((s[nf][0] - mn0) * ATT_SCALE);
            float p1 = __expf((s[nf][1] - mn0) * ATT_SCALE);
            float p2 = __expf((s[nf][2] - mn1) * ATT_SCALE);
            float p3 = __expf((s[nf][3] - mn1) * ATT_SCALE);
            lsum0 += p0 + p1;
            lsum1 += p2 + p3;
            float h0 = __bfloat162float(__float2bfloat16_rn(p0));
            float h1 = __bfloat162float(__float2bfloat16_rn(p1));
            float h2 = __bfloat162float(__float2bfloat16_rn(p2));
            float h3 = __bfloat162float(__float2bfloat16_rn(p3));
            ph0[nf] = pack_bf16(h0, h1);
            ph1[nf] = pack_bf16(h2, h3);
            pl0[nf] = pack_bf16(p0 - h0, p1 - h1);
            pl1[nf] = pack_bf16(p2 - h2, p3 - h3);
        }
        lsum0 += __shfl_xor_sync(0xffffffff, lsum0, 1);
        lsum0 += __shfl_xor_sync(0xffffffff, lsum0, 2);
        lsum1 += __shfl_xor_sync(0xffffffff, lsum1, 1);
        lsum1 += __shfl_xor_sync(0xffffffff, lsum1, 2);
        osum0 = osum0 * alpha0 + lsum0;
        osum1 = osum1 * alpha1 + lsum1;

        #pragma unroll
        for (int nf = 0; nf < 8; nf++) {
            o[nf][0] *= alpha0; o[nf][1] *= alpha0;
            o[nf][2] *= alpha1; o[nf][3] *= alpha1;
        }

        #pragma unroll
        for (int kf = 0; kf < 4; kf++) {
            uint32_t pah[4] = {ph0[2*kf], ph1[2*kf], ph0[2*kf+1], ph1[2*kf+1]};
            uint32_t pal[4] = {pl0[2*kf], pl1[2*kf], pl0[2*kf+1], pl1[2*kf+1]};
            const int kk = kf * 16;
            uint32_t vbh[4][4], vbl[4][4];
            #pragma unroll
            for (int nfp = 0; nfp < 4; nfp++) {
                int rr = kk + vb_ro;
                int cc = nfp * 16 + vb_co;
                ldm_x4_t(vbh[nfp], smem_u32(&Vhs[rr * KPAD + cc]));
                ldm_x4_t(vbl[nfp], smem_u32(&Vls[rr * KPAD + cc]));
            }
            #pragma unroll
            for (int nfp = 0; nfp < 4; nfp++) {
                mma_bf16(o[2*nfp    ], pah, vbh[nfp] + 0);
                mma_bf16(o[2*nfp + 1], pah, vbh[nfp] + 2);
            }
            #pragma unroll
            for (int nfp = 0; nfp < 4; nfp++) {
                mma_bf16(o[2*nfp    ], pah, vbl[nfp] + 0);
                mma_bf16(o[2*nfp + 1], pah, vbl[nfp] + 2);
            }
            #pragma unroll
            for (int nfp = 0; nfp < 4; nfp++) {
                mma_bf16(o[2*nfp    ], pal, vbh[nfp] + 0);
                mma_bf16(o[2*nfp + 1], pal, vbh[nfp] + 2);
            }
        }
        __syncthreads();
    }

    const float inv0 = 1.0f / osum0;
    const float inv1 = 1.0f / osum1;
    const int rowA = b * NSEQ + row0 + gr;
    #pragma unroll
    for (int nf = 0; nf < 8; nf++) {
        int col = h * HDIM + nf * 8 + qc;
        float v0 = o[nf][0] * inv0;
        float v1 = o[nf][1] * inv0;
        float v2 = o[nf][2] * inv1;
        float v3 = o[nf][3] * inv1;
        float h0 = __bfloat162float(__float2bfloat16_rn(v0));
        float h1 = __bfloat162float(__float2bfloat16_rn(v1));
        float h2 = __bfloat162float(__float2bfloat16_rn(v2));
        float h3 = __bfloat162float(__float2bfloat16_rn(v3));
        *(uint32_t*)&g_goh[(size_t)rowA * DIM + col] = pack_bf16(h0, h1);
        *(uint32_t*)&g_gol[(size_t)rowA * DIM + col] = pack_bf16(v0 - h0, v1 - h1);
        *(uint32_t*)&g_goh[(size_t)(rowA + 8) * DIM + col] = pack_bf16(h2, h3);
        *(uint32_t*)&g_gol[(size_t)(rowA + 8) * DIM + col] = pack_bf16(v2 - h2, v3 - h3);
    }
}

// ===========================================================================
// Launch
// ===========================================================================
extern "C" void kernel_launch(void* const* d_in, const int* in_sizes, int n_in,
                              void* d_out, int out_size) {
    const float* x1 = (const float*)d_in[0];
    const float* x2 = (const float*)d_in[1];
    const float* wq = (const float*)d_in[2];
    const float* wk = (const float*)d_in[3];
    const float* wv = (const float*)d_in[4];
    const float* wo = (const float*)d_in[5];
    const float* bo = (const float*)d_in[6];
    float* out = (float*)d_out;

    const int NX = MROWS * DIM;
    const int NW = DIM * DIM;

    cudaFuncSetAttribute(gemm_mma,
                         cudaFuncAttributeMaxDynamicSharedMemorySize,
                         GEMM_SMEM_BYTES);
    cudaFuncSetAttribute(attn_mma,
                         cudaFuncAttributeMaxDynamicSharedMemorySize,
                         ATTN_SMEM_BYTES);

    split2_kernel<<<dim3(512, 2), 256>>>(x1, x2, NX);
    split4_kernel<<<dim3(256, 4), 256>>>(wq, wk, wv, wo, NW);

    // Fused Q/K/V projections: one launch, 3 z-slices
    gemm_mma<<<dim3(GM_N / 64, GM_M / 128, 3), 128, GEMM_SMEM_BYTES>>>(
        1, 0, 0, 0, 0, nullptr, 0, 0, nullptr);

    attn_mma<<<dim3(NSEQ / 64, B * HEADS), 128, ATTN_SMEM_BYTES>>>();

    gemm_mma<<<dim3(GM_N / 64, GM_M / 128, 1), 128, GEMM_SMEM_BYTES>>>(
        0, BF_GOH, BF_GOL, BF_WOH, BF_WOL, out, -1, -1, bo);
}